// round 1
// baseline (speedup 1.0000x reference)
#include <cuda_runtime.h>

#define N_NODES   50000
#define N_EDGES   2400000
#define NUM_GRAPHS 2048
#define HID       128
#define GEMM_BLKS ((N_NODES + 127) / 128)   // 391

// ---------------- scratch (static device memory; no allocs) ----------------
__device__ __align__(16) float g_emb[N_NODES * 256];
__device__ __align__(16) float g_x[N_NODES * HID];
__device__ __align__(16) float g_feats[N_NODES * 512];
__device__ __align__(16) float g_h[N_NODES * HID];
__device__ __align__(16) float g_t[N_NODES * HID];
__device__ __align__(16) float g_gskip[N_NODES * HID];
__device__ float    g_scores[N_NODES * 4];
__device__ unsigned g_smax[NUM_GRAPHS * 4];
__device__ float    g_sden[NUM_GRAPHS * 4];
__device__ float    g_pooled[NUM_GRAPHS * HID];

// order-preserving float <-> uint map (for atomicMax on floats incl. negatives)
__device__ __forceinline__ unsigned fmap(float f) {
    unsigned u = __float_as_uint(f);
    return (u >> 31) ? ~u : (u | 0x80000000u);
}
__device__ __forceinline__ float funmap(unsigned u) {
    return (u >> 31) ? __uint_as_float(u & 0x7fffffffu) : __uint_as_float(~u);
}
__device__ __forceinline__ float silu(float v) { return v / (1.f + __expf(-v)); }

// ---------------- embedding gather: concat 4 tables -> g_emb[N,256] --------
__global__ void gather_embed_kernel(const int* __restrict__ atom, const int* __restrict__ hyd,
                                    const int* __restrict__ deg,  const int* __restrict__ hyb,
                                    const float* __restrict__ ea, const float* __restrict__ eh,
                                    const float* __restrict__ ed, const float* __restrict__ ey) {
    int n = blockIdx.x;
    int t = threadIdx.x;  // 64
    float* dst = g_emb + (size_t)n * 256;
    dst[t]       = ea[atom[n] * 64 + t];
    dst[64 + t]  = eh[hyd[n]  * 64 + t];
    dst[128 + t] = ed[deg[n]  * 64 + t];
    dst[192 + t] = ey[hyb[n]  * 64 + t];
}

// ---------------- generic tiled SGEMM: C = act(A[M,K]@B[K,128] + bias (+res)(+res2))
__global__ __launch_bounds__(256) void sgemm128_kernel(
    const float* __restrict__ A, const float* __restrict__ B,
    const float* __restrict__ bias,
    const float* __restrict__ res, const float* __restrict__ res2,
    float* __restrict__ C, int M, int K, int act) {
    const int N = 128;
    __shared__ float As[8][128];
    __shared__ float Bs[8][128];
    int tid  = threadIdx.x;
    int row0 = blockIdx.x * 128;
    int tx = tid % 16, ty = tid / 16;

    float acc[8][8];
#pragma unroll
    for (int i = 0; i < 8; i++)
#pragma unroll
        for (int j = 0; j < 8; j++) acc[i][j] = 0.f;

    int arow  = tid >> 1;          // 0..127
    int acol4 = (tid & 1) * 4;     // 0 or 4
    int brow  = tid >> 5;          // 0..7
    int bcol4 = (tid & 31) * 4;

    for (int k0 = 0; k0 < K; k0 += 8) {
        float4 av;
        int gr = row0 + arow;
        if (gr < M) av = *(const float4*)(A + (size_t)gr * K + k0 + acol4);
        else        av = make_float4(0.f, 0.f, 0.f, 0.f);
        As[acol4 + 0][arow] = av.x;
        As[acol4 + 1][arow] = av.y;
        As[acol4 + 2][arow] = av.z;
        As[acol4 + 3][arow] = av.w;
        *(float4*)&Bs[brow][bcol4] = *(const float4*)(B + (size_t)(k0 + brow) * N + bcol4);
        __syncthreads();
#pragma unroll
        for (int k = 0; k < 8; k++) {
            float4 a0 = *(const float4*)&As[k][ty * 8];
            float4 a1 = *(const float4*)&As[k][ty * 8 + 4];
            float4 b0 = *(const float4*)&Bs[k][tx * 8];
            float4 b1 = *(const float4*)&Bs[k][tx * 8 + 4];
            float ra[8] = {a0.x, a0.y, a0.z, a0.w, a1.x, a1.y, a1.z, a1.w};
            float rb[8] = {b0.x, b0.y, b0.z, b0.w, b1.x, b1.y, b1.z, b1.w};
#pragma unroll
            for (int i = 0; i < 8; i++)
#pragma unroll
                for (int j = 0; j < 8; j++) acc[i][j] += ra[i] * rb[j];
        }
        __syncthreads();
    }

#pragma unroll
    for (int i = 0; i < 8; i++) {
        int r = row0 + ty * 8 + i;
        if (r >= M) continue;
#pragma unroll
        for (int j = 0; j < 8; j++) {
            int c = tx * 8 + j;
            float v = acc[i][j] + bias[c];
            if (res)  v += res[(size_t)r * 128 + c];
            if (res2) v += res2[(size_t)r * 128 + c];
            if (act)  v = silu(v);
            C[(size_t)r * 128 + c] = v;
        }
    }
}

// ---------------- per-layer feats init: [:,0:128]=x, [:,128:512]=0 ---------
__global__ void init_feats_kernel() {
    int j4 = blockIdx.x * blockDim.x + threadIdx.x;  // over N*128 float4s
    if (j4 >= N_NODES * 128) return;
    int n = j4 >> 7, c4 = j4 & 127;
    float4* f4 = (float4*)g_feats;
    const float4* x4 = (const float4*)g_x;
    f4[j4] = (c4 < 32) ? x4[n * 32 + c4] : make_float4(0.f, 0.f, 0.f, 0.f);
}

// ---------------- edge scatter: feats[t%N, 128+(t/N)*128+c] += x[s%N, c] ---
__global__ void scatter_kernel(const int* __restrict__ tgt, const int* __restrict__ srcv) {
    int w    = (blockIdx.x * blockDim.x + threadIdx.x) >> 5;
    int lane = threadIdx.x & 31;
    if (w >= N_EDGES) return;
    int s  = srcv[w];
    int t  = tgt[w];
    int sn = s % N_NODES;
    int tn = t % N_NODES;
    int hop = t / N_NODES;
    float4 v = *(const float4*)(g_x + (size_t)sn * HID + lane * 4);
    float* dst = g_feats + (size_t)tn * 512 + (hop + 1) * HID + lane * 4;
    atomicAdd(dst + 0, v.x);
    atomicAdd(dst + 1, v.y);
    atomicAdd(dst + 2, v.z);
    atomicAdd(dst + 3, v.w);
}

// ---------------- pooling: init / scores+segmax / exp+segsum / weighted sum
__global__ void init_pool_kernel() {
    int i = blockIdx.x * blockDim.x + threadIdx.x;
    if (i < NUM_GRAPHS * HID) g_pooled[i] = 0.f;
    if (i < NUM_GRAPHS * 4) { g_smax[i] = 0u; g_sden[i] = 0.f; }
}

__global__ void scores_kernel(const int* __restrict__ batch, const float* __restrict__ attn_w,
                              const float* __restrict__ attn_b, const float* __restrict__ temp) {
    int w    = (blockIdx.x * blockDim.x + threadIdx.x) >> 5;
    int lane = threadIdx.x & 31;
    if (w >= N_NODES) return;
    float a[4] = {0.f, 0.f, 0.f, 0.f};
    for (int c = lane; c < HID; c += 32) {
        float xv = g_x[(size_t)w * HID + c];
        a[0] += xv * attn_w[c];
        a[1] += xv * attn_w[128 + c];
        a[2] += xv * attn_w[256 + c];
        a[3] += xv * attn_w[384 + c];
    }
#pragma unroll
    for (int o = 16; o; o >>= 1)
#pragma unroll
        for (int h = 0; h < 4; h++) a[h] += __shfl_down_sync(0xffffffffu, a[h], o);
    if (lane == 0) {
        float invT = 1.f / temp[0];
        int g = batch[w];
#pragma unroll
        for (int h = 0; h < 4; h++) {
            float sc = (a[h] + attn_b[h]) * invT;
            g_scores[w * 4 + h] = sc;
            atomicMax(&g_smax[g * 4 + h], fmap(sc));
        }
    }
}

__global__ void exp_kernel(const int* __restrict__ batch) {
    int i = blockIdx.x * blockDim.x + threadIdx.x;
    if (i >= N_NODES * 4) return;
    int n = i >> 2, h = i & 3;
    int g = batch[n];
    float e = expf(g_scores[i] - funmap(g_smax[g * 4 + h]));
    g_scores[i] = e;
    atomicAdd(&g_sden[g * 4 + h], e);
}

__global__ void pool_kernel(const int* __restrict__ batch) {
    int n = blockIdx.x;
    int c = threadIdx.x;  // 128
    int g = batch[n];
    float wbar = 0.f;
#pragma unroll
    for (int h = 0; h < 4; h++) wbar += g_scores[n * 4 + h] / g_sden[g * 4 + h];
    wbar *= 0.25f;
    atomicAdd(&g_pooled[g * HID + c], g_x[(size_t)n * HID + c] * wbar);
}

// ---------------- readout FFN: [G,128]->silu->silu->dot ---------------------
__global__ void ffn_kernel(const float* __restrict__ w1, const float* __restrict__ b1,
                           const float* __restrict__ w2, const float* __restrict__ b2,
                           const float* __restrict__ w3, const float* __restrict__ b3,
                           float* __restrict__ out) {
    int g = blockIdx.x;
    int t = threadIdx.x;  // 128
    __shared__ float p[128], h1[128], red[128];
    p[t] = g_pooled[g * HID + t];
    __syncthreads();
    float acc = b1[t];
#pragma unroll 8
    for (int k = 0; k < 128; k++) acc += p[k] * w1[k * 128 + t];
    h1[t] = silu(acc);
    __syncthreads();
    float acc2 = b2[t];
#pragma unroll 8
    for (int k = 0; k < 128; k++) acc2 += h1[k] * w2[k * 128 + t];
    acc2 = silu(acc2);
    red[t] = acc2 * w3[t];
    __syncthreads();
    for (int s = 64; s > 0; s >>= 1) {
        if (t < s) red[t] += red[t + s];
        __syncthreads();
    }
    if (t == 0) out[g] = red[0] + b3[0];
}

// ---------------- host launcher ---------------------------------------------
extern "C" void kernel_launch(void* const* d_in, const int* in_sizes, int n_in,
                              void* d_out, int out_size) {
    const int* atom  = (const int*)d_in[0];
    const int* hyd   = (const int*)d_in[1];
    const int* deg   = (const int*)d_in[2];
    const int* hyb   = (const int*)d_in[3];
    const int* tgt   = (const int*)d_in[4];
    const int* srcv  = (const int*)d_in[5];
    const int* batch = (const int*)d_in[6];
    const float* emb_atom = (const float*)d_in[7];
    const float* emb_h    = (const float*)d_in[8];
    const float* emb_deg  = (const float*)d_in[9];
    const float* emb_hyb  = (const float*)d_in[10];
    const float* proj_w   = (const float*)d_in[11];
    const float* proj_b   = (const float*)d_in[12];
    const float* in_w     = (const float*)d_in[13];
    const float* in_b     = (const float*)d_in[14];
    const float* mlp_w1   = (const float*)d_in[15];
    const float* mlp_b1   = (const float*)d_in[16];
    const float* mlp_w2   = (const float*)d_in[17];
    const float* mlp_b2   = (const float*)d_in[18];
    const float* skip_w   = (const float*)d_in[19];
    const float* skip_b   = (const float*)d_in[20];
    const float* attn_w   = (const float*)d_in[21];
    const float* attn_b   = (const float*)d_in[22];
    const float* temp     = (const float*)d_in[23];
    const float* ffn_w1   = (const float*)d_in[24];
    const float* ffn_b1   = (const float*)d_in[25];
    const float* ffn_w2   = (const float*)d_in[26];
    const float* ffn_b2   = (const float*)d_in[27];
    const float* ffn_w3   = (const float*)d_in[28];
    const float* ffn_b3   = (const float*)d_in[29];
    float* out = (float*)d_out;

    float *pemb, *px, *pfeats, *ph, *pt, *pg;
    cudaGetSymbolAddress((void**)&pemb,  g_emb);
    cudaGetSymbolAddress((void**)&px,    g_x);
    cudaGetSymbolAddress((void**)&pfeats,g_feats);
    cudaGetSymbolAddress((void**)&ph,    g_h);
    cudaGetSymbolAddress((void**)&pt,    g_t);
    cudaGetSymbolAddress((void**)&pg,    g_gskip);

    // 1. embedding + projection
    gather_embed_kernel<<<N_NODES, 64>>>(atom, hyd, deg, hyb, emb_atom, emb_h, emb_deg, emb_hyb);
    sgemm128_kernel<<<GEMM_BLKS, 256>>>(pemb, proj_w, proj_b, nullptr, nullptr, px, N_NODES, 256, 1);

    // 2. shell conv layers
    for (int l = 0; l < 3; l++) {
        init_feats_kernel<<<(N_NODES * 128 + 255) / 256, 256>>>();
        scatter_kernel<<<N_EDGES / 8, 256>>>(tgt, srcv);
        sgemm128_kernel<<<GEMM_BLKS, 256>>>(pfeats, in_w + (size_t)l * 512 * 128,
                                            in_b + l * 128, nullptr, nullptr, ph, N_NODES, 512, 1);
        sgemm128_kernel<<<GEMM_BLKS, 256>>>(pfeats, skip_w + (size_t)l * 512 * 128,
                                            skip_b + l * 128, nullptr, nullptr, pg, N_NODES, 512, 0);
        for (int m = 0; m < 2; m++) {
            int idx = l * 2 + m;
            sgemm128_kernel<<<GEMM_BLKS, 256>>>(ph, mlp_w1 + (size_t)idx * 16384,
                                                mlp_b1 + idx * 128, nullptr, nullptr, pt, N_NODES, 128, 1);
            bool last = (m == 1);
            sgemm128_kernel<<<GEMM_BLKS, 256>>>(pt, mlp_w2 + (size_t)idx * 16384,
                                                mlp_b2 + idx * 128, ph, last ? pg : nullptr,
                                                last ? px : ph, N_NODES, 128, 0);
        }
    }

    // 3. attention pooling
    init_pool_kernel<<<(NUM_GRAPHS * HID + 255) / 256, 256>>>();
    scores_kernel<<<(N_NODES * 32 + 255) / 256, 256>>>(batch, attn_w, attn_b, temp);
    exp_kernel<<<(N_NODES * 4 + 255) / 256, 256>>>(batch);
    pool_kernel<<<N_NODES, 128>>>(batch);

    // 4. readout FFN
    ffn_kernel<<<NUM_GRAPHS, 128>>>(ffn_w1, ffn_b1, ffn_w2, ffn_b2, ffn_w3, ffn_b3, out);
}

// round 2
// speedup vs baseline: 1.5976x; 1.5976x over previous
#include <cuda_runtime.h>

#define N_NODES   50000
#define N_EDGES   2400000
#define NUM_GRAPHS 2048
#define HID       128
#define GEMM_BLKS ((N_NODES + 127) / 128)   // 391
#define ASTR 20   // smem row stride (pad) for 16-wide k tiles

// ---------------- scratch (static device memory; no allocs) ----------------
__device__ __align__(16) float g_emb[N_NODES * 256];
__device__ __align__(16) float g_x[N_NODES * HID];
__device__ __align__(16) float g_feats[N_NODES * 512];
__device__ __align__(16) float g_h[N_NODES * HID];
__device__ __align__(16) float g_t[N_NODES * HID];
__device__ __align__(16) float g_gskip[N_NODES * HID];
__device__ float    g_scores[N_NODES * 4];
__device__ unsigned g_smax[NUM_GRAPHS * 4];
__device__ float    g_sden[NUM_GRAPHS * 4];
__device__ float    g_pooled[NUM_GRAPHS * HID];

// order-preserving float <-> uint map (for atomicMax on floats incl. negatives)
__device__ __forceinline__ unsigned fmap(float f) {
    unsigned u = __float_as_uint(f);
    return (u >> 31) ? ~u : (u | 0x80000000u);
}
__device__ __forceinline__ float funmap(unsigned u) {
    return (u >> 31) ? __uint_as_float(u & 0x7fffffffu) : __uint_as_float(~u);
}
__device__ __forceinline__ float silu(float v) { return v / (1.f + __expf(-v)); }

__device__ __forceinline__ unsigned f2tf32(float v) {
    unsigned r;
    asm("cvt.rna.tf32.f32 %0, %1;" : "=r"(r) : "f"(v));
    return r;
}

#define MMA_TF32(cc, aa, bb) \
    asm volatile("mma.sync.aligned.m16n8k8.row.col.f32.tf32.tf32.f32 " \
                 "{%0,%1,%2,%3},{%4,%5,%6,%7},{%8,%9},{%0,%1,%2,%3};" \
                 : "+f"(cc[0]), "+f"(cc[1]), "+f"(cc[2]), "+f"(cc[3]) \
                 : "r"(aa[0]), "r"(aa[1]), "r"(aa[2]), "r"(aa[3]), \
                   "r"(bb[0]), "r"(bb[1]))

// ---------------- embedding gather: concat 4 tables -> g_emb[N,256] --------
__global__ void gather_embed_kernel(const int* __restrict__ atom, const int* __restrict__ hyd,
                                    const int* __restrict__ deg,  const int* __restrict__ hyb,
                                    const float* __restrict__ ea, const float* __restrict__ eh,
                                    const float* __restrict__ ed, const float* __restrict__ ey) {
    int n = blockIdx.x;
    int t = threadIdx.x;  // 64
    float* dst = g_emb + (size_t)n * 256;
    dst[t]       = ea[atom[n] * 64 + t];
    dst[64 + t]  = eh[hyd[n]  * 64 + t];
    dst[128 + t] = ed[deg[n]  * 64 + t];
    dst[192 + t] = ey[hyb[n]  * 64 + t];
}

// ---------------- split-TF32 tensor-core GEMM -------------------------------
// C[M,128] = act(A[M,K] @ B[K,128] + bias (+res)(+res2)), K % 16 == 0
// 3-pass split tf32 (hi*hi + hi*lo + lo*hi) => ~fp32 accuracy on tensor cores.
__global__ __launch_bounds__(256) void mma_gemm_kernel(
    const float* __restrict__ A, const float* __restrict__ B,
    const float* __restrict__ bias,
    const float* __restrict__ res, const float* __restrict__ res2,
    float* __restrict__ C, int M, int K, int act) {
    __shared__ unsigned Ah[128 * ASTR], Al[128 * ASTR];   // [m][k], stride ASTR
    __shared__ unsigned Bh[128 * ASTR], Bl[128 * ASTR];   // [n][k], stride ASTR

    const int tid  = threadIdx.x;
    const int lane = tid & 31, wid = tid >> 5;
    const int wm = (wid >> 2) * 64;    // warp M offset (2 warps in M)
    const int wn = (wid & 3) * 32;     // warp N offset (4 warps in N)
    const int grp = lane >> 2, tg = lane & 3;
    const int row0 = blockIdx.x * 128;

    float c[4][4][4];
#pragma unroll
    for (int i = 0; i < 4; i++)
#pragma unroll
        for (int j = 0; j < 4; j++)
#pragma unroll
            for (int q = 0; q < 4; q++) c[i][j][q] = 0.f;

    const int ar  = tid >> 2;            // A load: row (0..63, +64)
    const int ac4 = (tid & 3) * 4;       // A load: k offset (float4)
    const int bn  = tid & 127;           // B load: n
    const int bk0 = (tid >> 7) * 8;      // B load: k base (0 or 8)

    for (int k0 = 0; k0 < K; k0 += 16) {
        // global loads into registers first (overlap with previous compute)
        float4 av[2];
#pragma unroll
        for (int it = 0; it < 2; it++) {
            int grow = row0 + ar + it * 64;
            av[it] = (grow < M) ? *(const float4*)(A + (size_t)grow * K + k0 + ac4)
                                : make_float4(0.f, 0.f, 0.f, 0.f);
        }
        float bv[8];
#pragma unroll
        for (int kk = 0; kk < 8; kk++)
            bv[kk] = B[(size_t)(k0 + bk0 + kk) * 128 + bn];

        __syncthreads();  // previous iteration's fragment reads done

        // convert to split tf32 and stage in smem
#pragma unroll
        for (int it = 0; it < 2; it++) {
            int r = ar + it * 64;
            float vv[4] = {av[it].x, av[it].y, av[it].z, av[it].w};
#pragma unroll
            for (int j = 0; j < 4; j++) {
                unsigned h = f2tf32(vv[j]);
                Ah[r * ASTR + ac4 + j] = h;
                Al[r * ASTR + ac4 + j] = f2tf32(vv[j] - __uint_as_float(h));
            }
        }
#pragma unroll
        for (int kk = 0; kk < 8; kk++) {
            unsigned h = f2tf32(bv[kk]);
            Bh[bn * ASTR + bk0 + kk] = h;
            Bl[bn * ASTR + bk0 + kk] = f2tf32(bv[kk] - __uint_as_float(h));
        }
        __syncthreads();

#pragma unroll
        for (int s = 0; s < 2; s++) {
            const int ks = s * 8;
            unsigned ah[4][4], al[4][4], bh[4][2], bl[4][2];
#pragma unroll
            for (int mf = 0; mf < 4; mf++) {
                int r = wm + mf * 16 + grp;
                int b0 = r * ASTR + ks + tg;
                int b1 = (r + 8) * ASTR + ks + tg;
                ah[mf][0] = Ah[b0];     ah[mf][1] = Ah[b1];
                ah[mf][2] = Ah[b0 + 4]; ah[mf][3] = Ah[b1 + 4];
                al[mf][0] = Al[b0];     al[mf][1] = Al[b1];
                al[mf][2] = Al[b0 + 4]; al[mf][3] = Al[b1 + 4];
            }
#pragma unroll
            for (int nf = 0; nf < 4; nf++) {
                int n = wn + nf * 8 + grp;
                int b0 = n * ASTR + ks + tg;
                bh[nf][0] = Bh[b0]; bh[nf][1] = Bh[b0 + 4];
                bl[nf][0] = Bl[b0]; bl[nf][1] = Bl[b0 + 4];
            }
#pragma unroll
            for (int mf = 0; mf < 4; mf++)
#pragma unroll
                for (int nf = 0; nf < 4; nf++) {
                    MMA_TF32(c[mf][nf], ah[mf], bh[nf]);
                    MMA_TF32(c[mf][nf], ah[mf], bl[nf]);
                    MMA_TF32(c[mf][nf], al[mf], bh[nf]);
                }
        }
    }

    // epilogue
#pragma unroll
    for (int mf = 0; mf < 4; mf++) {
        int r0 = row0 + wm + mf * 16 + grp;
        int r1 = r0 + 8;
#pragma unroll
        for (int nf = 0; nf < 4; nf++) {
            int col = wn + nf * 8 + 2 * tg;
            float bia0 = bias[col], bia1 = bias[col + 1];
            if (r0 < M) {
                float v0 = c[mf][nf][0] + bia0;
                float v1 = c[mf][nf][1] + bia1;
                if (res)  { v0 += res[(size_t)r0 * 128 + col];  v1 += res[(size_t)r0 * 128 + col + 1]; }
                if (res2) { v0 += res2[(size_t)r0 * 128 + col]; v1 += res2[(size_t)r0 * 128 + col + 1]; }
                if (act)  { v0 = silu(v0); v1 = silu(v1); }
                C[(size_t)r0 * 128 + col]     = v0;
                C[(size_t)r0 * 128 + col + 1] = v1;
            }
            if (r1 < M) {
                float v2 = c[mf][nf][2] + bia0;
                float v3 = c[mf][nf][3] + bia1;
                if (res)  { v2 += res[(size_t)r1 * 128 + col];  v3 += res[(size_t)r1 * 128 + col + 1]; }
                if (res2) { v2 += res2[(size_t)r1 * 128 + col]; v3 += res2[(size_t)r1 * 128 + col + 1]; }
                if (act)  { v2 = silu(v2); v3 = silu(v3); }
                C[(size_t)r1 * 128 + col]     = v2;
                C[(size_t)r1 * 128 + col + 1] = v3;
            }
        }
    }
}

// ---------------- per-layer feats init: [:,0:128]=x, [:,128:512]=0 ---------
__global__ void init_feats_kernel() {
    int j4 = blockIdx.x * blockDim.x + threadIdx.x;  // over N*128 float4s
    if (j4 >= N_NODES * 128) return;
    int n = j4 >> 7, c4 = j4 & 127;
    float4* f4 = (float4*)g_feats;
    const float4* x4 = (const float4*)g_x;
    f4[j4] = (c4 < 32) ? x4[n * 32 + c4] : make_float4(0.f, 0.f, 0.f, 0.f);
}

// ---------------- edge scatter: feats[t%N, 128+(t/N)*128+c] += x[s%N, c] ---
// one warp per edge; each lane reduces one float4 with a single red.v4
__global__ void scatter_kernel(const int* __restrict__ tgt, const int* __restrict__ srcv) {
    int w    = (blockIdx.x * blockDim.x + threadIdx.x) >> 5;
    int lane = threadIdx.x & 31;
    if (w >= N_EDGES) return;
    int s  = srcv[w];
    int t  = tgt[w];
    int sn = s % N_NODES;
    int tn = t % N_NODES;
    int hop = t / N_NODES;
    float4 v = *(const float4*)(g_x + (size_t)sn * HID + lane * 4);
    float* dst = g_feats + (size_t)tn * 512 + (hop + 1) * HID + lane * 4;
    asm volatile("red.global.add.v4.f32 [%0], {%1,%2,%3,%4};"
                 :: "l"(dst), "f"(v.x), "f"(v.y), "f"(v.z), "f"(v.w)
                 : "memory");
}

// ---------------- pooling: init / scores+segmax / exp+segsum / weighted sum
__global__ void init_pool_kernel() {
    int i = blockIdx.x * blockDim.x + threadIdx.x;
    if (i < NUM_GRAPHS * HID) g_pooled[i] = 0.f;
    if (i < NUM_GRAPHS * 4) { g_smax[i] = 0u; g_sden[i] = 0.f; }
}

__global__ void scores_kernel(const int* __restrict__ batch, const float* __restrict__ attn_w,
                              const float* __restrict__ attn_b, const float* __restrict__ temp) {
    int w    = (blockIdx.x * blockDim.x + threadIdx.x) >> 5;
    int lane = threadIdx.x & 31;
    if (w >= N_NODES) return;
    float a[4] = {0.f, 0.f, 0.f, 0.f};
    for (int c = lane; c < HID; c += 32) {
        float xv = g_x[(size_t)w * HID + c];
        a[0] += xv * attn_w[c];
        a[1] += xv * attn_w[128 + c];
        a[2] += xv * attn_w[256 + c];
        a[3] += xv * attn_w[384 + c];
    }
#pragma unroll
    for (int o = 16; o; o >>= 1)
#pragma unroll
        for (int h = 0; h < 4; h++) a[h] += __shfl_down_sync(0xffffffffu, a[h], o);
    if (lane == 0) {
        float invT = 1.f / temp[0];
        int g = batch[w];
#pragma unroll
        for (int h = 0; h < 4; h++) {
            float sc = (a[h] + attn_b[h]) * invT;
            g_scores[w * 4 + h] = sc;
            atomicMax(&g_smax[g * 4 + h], fmap(sc));
        }
    }
}

__global__ void exp_kernel(const int* __restrict__ batch) {
    int i = blockIdx.x * blockDim.x + threadIdx.x;
    if (i >= N_NODES * 4) return;
    int n = i >> 2, h = i & 3;
    int g = batch[n];
    float e = expf(g_scores[i] - funmap(g_smax[g * 4 + h]));
    g_scores[i] = e;
    atomicAdd(&g_sden[g * 4 + h], e);
}

__global__ void pool_kernel(const int* __restrict__ batch) {
    int n = blockIdx.x;
    int c = threadIdx.x;  // 128
    int g = batch[n];
    float wbar = 0.f;
#pragma unroll
    for (int h = 0; h < 4; h++) wbar += g_scores[n * 4 + h] / g_sden[g * 4 + h];
    wbar *= 0.25f;
    atomicAdd(&g_pooled[g * HID + c], g_x[(size_t)n * HID + c] * wbar);
}

// ---------------- readout FFN: [G,128]->silu->silu->dot ---------------------
__global__ void ffn_kernel(const float* __restrict__ w1, const float* __restrict__ b1,
                           const float* __restrict__ w2, const float* __restrict__ b2,
                           const float* __restrict__ w3, const float* __restrict__ b3,
                           float* __restrict__ out) {
    int g = blockIdx.x;
    int t = threadIdx.x;  // 128
    __shared__ float p[128], h1[128], red[128];
    p[t] = g_pooled[g * HID + t];
    __syncthreads();
    float acc = b1[t];
#pragma unroll 8
    for (int k = 0; k < 128; k++) acc += p[k] * w1[k * 128 + t];
    h1[t] = silu(acc);
    __syncthreads();
    float acc2 = b2[t];
#pragma unroll 8
    for (int k = 0; k < 128; k++) acc2 += h1[k] * w2[k * 128 + t];
    acc2 = silu(acc2);
    red[t] = acc2 * w3[t];
    __syncthreads();
    for (int s = 64; s > 0; s >>= 1) {
        if (t < s) red[t] += red[t + s];
        __syncthreads();
    }
    if (t == 0) out[g] = red[0] + b3[0];
}

// ---------------- host launcher ---------------------------------------------
extern "C" void kernel_launch(void* const* d_in, const int* in_sizes, int n_in,
                              void* d_out, int out_size) {
    const int* atom  = (const int*)d_in[0];
    const int* hyd   = (const int*)d_in[1];
    const int* deg   = (const int*)d_in[2];
    const int* hyb   = (const int*)d_in[3];
    const int* tgt   = (const int*)d_in[4];
    const int* srcv  = (const int*)d_in[5];
    const int* batch = (const int*)d_in[6];
    const float* emb_atom = (const float*)d_in[7];
    const float* emb_h    = (const float*)d_in[8];
    const float* emb_deg  = (const float*)d_in[9];
    const float* emb_hyb  = (const float*)d_in[10];
    const float* proj_w   = (const float*)d_in[11];
    const float* proj_b   = (const float*)d_in[12];
    const float* in_w     = (const float*)d_in[13];
    const float* in_b     = (const float*)d_in[14];
    const float* mlp_w1   = (const float*)d_in[15];
    const float* mlp_b1   = (const float*)d_in[16];
    const float* mlp_w2   = (const float*)d_in[17];
    const float* mlp_b2   = (const float*)d_in[18];
    const float* skip_w   = (const float*)d_in[19];
    const float* skip_b   = (const float*)d_in[20];
    const float* attn_w   = (const float*)d_in[21];
    const float* attn_b   = (const float*)d_in[22];
    const float* temp     = (const float*)d_in[23];
    const float* ffn_w1   = (const float*)d_in[24];
    const float* ffn_b1   = (const float*)d_in[25];
    const float* ffn_w2   = (const float*)d_in[26];
    const float* ffn_b2   = (const float*)d_in[27];
    const float* ffn_w3   = (const float*)d_in[28];
    const float* ffn_b3   = (const float*)d_in[29];
    float* out = (float*)d_out;

    float *pemb, *px, *pfeats, *ph, *pt, *pg;
    cudaGetSymbolAddress((void**)&pemb,  g_emb);
    cudaGetSymbolAddress((void**)&px,    g_x);
    cudaGetSymbolAddress((void**)&pfeats,g_feats);
    cudaGetSymbolAddress((void**)&ph,    g_h);
    cudaGetSymbolAddress((void**)&pt,    g_t);
    cudaGetSymbolAddress((void**)&pg,    g_gskip);

    // 1. embedding + projection
    gather_embed_kernel<<<N_NODES, 64>>>(atom, hyd, deg, hyb, emb_atom, emb_h, emb_deg, emb_hyb);
    mma_gemm_kernel<<<GEMM_BLKS, 256>>>(pemb, proj_w, proj_b, nullptr, nullptr, px, N_NODES, 256, 1);

    // 2. shell conv layers
    for (int l = 0; l < 3; l++) {
        init_feats_kernel<<<(N_NODES * 128 + 255) / 256, 256>>>();
        scatter_kernel<<<N_EDGES / 8, 256>>>(tgt, srcv);
        mma_gemm_kernel<<<GEMM_BLKS, 256>>>(pfeats, in_w + (size_t)l * 512 * 128,
                                            in_b + l * 128, nullptr, nullptr, ph, N_NODES, 512, 1);
        mma_gemm_kernel<<<GEMM_BLKS, 256>>>(pfeats, skip_w + (size_t)l * 512 * 128,
                                            skip_b + l * 128, nullptr, nullptr, pg, N_NODES, 512, 0);
        for (int m = 0; m < 2; m++) {
            int idx = l * 2 + m;
            mma_gemm_kernel<<<GEMM_BLKS, 256>>>(ph, mlp_w1 + (size_t)idx * 16384,
                                                mlp_b1 + idx * 128, nullptr, nullptr, pt, N_NODES, 128, 1);
            bool last = (m == 1);
            mma_gemm_kernel<<<GEMM_BLKS, 256>>>(pt, mlp_w2 + (size_t)idx * 16384,
                                                mlp_b2 + idx * 128, ph, last ? pg : nullptr,
                                                last ? px : ph, N_NODES, 128, 0);
        }
    }

    // 3. attention pooling
    init_pool_kernel<<<(NUM_GRAPHS * HID + 255) / 256, 256>>>();
    scores_kernel<<<(N_NODES * 32 + 255) / 256, 256>>>(batch, attn_w, attn_b, temp);
    exp_kernel<<<(N_NODES * 4 + 255) / 256, 256>>>(batch);
    pool_kernel<<<N_NODES, 128>>>(batch);

    // 4. readout FFN
    ffn_kernel<<<NUM_GRAPHS, 128>>>(ffn_w1, ffn_b1, ffn_w2, ffn_b2, ffn_w3, ffn_b3, out);
}

// round 3
// speedup vs baseline: 1.8497x; 1.1578x over previous
#include <cuda_runtime.h>

#define N_NODES   50000
#define N_EDGES   2400000
#define NUM_GRAPHS 2048
#define HID       128
#define GEMM_BLKS ((N_NODES + 127) / 128)   // 391
#define ASTR 20    // smem stride for streamed 16-wide k tiles
#define XSTR 132   // smem stride for resident 128-wide split buffers

// ---------------- scratch (static device memory; no allocs) ----------------
__device__ __align__(16) float g_emb[N_NODES * 256];
__device__ __align__(16) float g_x[N_NODES * HID];
__device__ __align__(16) float g_feats[N_NODES * 512];
__device__ __align__(16) float g_gskip[N_NODES * HID];
__device__ float    g_scores[N_NODES * 4];
__device__ unsigned g_smax[NUM_GRAPHS * 4];
__device__ float    g_sden[NUM_GRAPHS * 4];
__device__ float    g_pooled[NUM_GRAPHS * HID];

__device__ __forceinline__ unsigned fmap(float f) {
    unsigned u = __float_as_uint(f);
    return (u >> 31) ? ~u : (u | 0x80000000u);
}
__device__ __forceinline__ float funmap(unsigned u) {
    return (u >> 31) ? __uint_as_float(u & 0x7fffffffu) : __uint_as_float(~u);
}
__device__ __forceinline__ float silu(float v) { return v / (1.f + __expf(-v)); }

__device__ __forceinline__ unsigned f2tf32(float v) {
    unsigned r;
    asm("cvt.rna.tf32.f32 %0, %1;" : "=r"(r) : "f"(v));
    return r;
}

#define MMA_TF32(cc, aa, bb) \
    asm volatile("mma.sync.aligned.m16n8k8.row.col.f32.tf32.tf32.f32 " \
                 "{%0,%1,%2,%3},{%4,%5,%6,%7},{%8,%9},{%0,%1,%2,%3};" \
                 : "+f"(cc[0]), "+f"(cc[1]), "+f"(cc[2]), "+f"(cc[3]) \
                 : "r"(aa[0]), "r"(aa[1]), "r"(aa[2]), "r"(aa[3]), \
                   "r"(bb[0]), "r"(bb[1]))

// ---------------- embedding gather ------------------------------------------
__global__ void gather_embed_kernel(const int* __restrict__ atom, const int* __restrict__ hyd,
                                    const int* __restrict__ deg,  const int* __restrict__ hyb,
                                    const float* __restrict__ ea, const float* __restrict__ eh,
                                    const float* __restrict__ ed, const float* __restrict__ ey) {
    int n = blockIdx.x;
    int t = threadIdx.x;  // 64
    float* dst = g_emb + (size_t)n * 256;
    dst[t]       = ea[atom[n] * 64 + t];
    dst[64 + t]  = eh[hyd[n]  * 64 + t];
    dst[128 + t] = ed[deg[n]  * 64 + t];
    dst[192 + t] = ey[hyb[n]  * 64 + t];
}

// ---------------- standalone split-TF32 GEMM (proj only) --------------------
__global__ __launch_bounds__(256) void mma_gemm_kernel(
    const float* __restrict__ A, const float* __restrict__ B,
    const float* __restrict__ bias, float* __restrict__ C, int M, int K, int act) {
    __shared__ unsigned Ah[128 * ASTR], Al[128 * ASTR];
    __shared__ unsigned Bh[128 * ASTR], Bl[128 * ASTR];

    const int tid  = threadIdx.x;
    const int lane = tid & 31, wid = tid >> 5;
    const int wm = (wid >> 2) * 64;
    const int wn = (wid & 3) * 32;
    const int grp = lane >> 2, tg = lane & 3;
    const int row0 = blockIdx.x * 128;

    float c[4][4][4];
#pragma unroll
    for (int i = 0; i < 4; i++)
#pragma unroll
        for (int j = 0; j < 4; j++)
#pragma unroll
            for (int q = 0; q < 4; q++) c[i][j][q] = 0.f;

    const int ar  = tid >> 2;
    const int ac4 = (tid & 3) * 4;
    const int bn  = tid & 127;
    const int bk0 = (tid >> 7) * 8;

    float4 av[2]; float bv[8];
    {
        int gr0 = row0 + ar, gr1 = gr0 + 64;
        av[0] = (gr0 < M) ? *(const float4*)(A + (size_t)gr0 * K + ac4) : make_float4(0,0,0,0);
        av[1] = (gr1 < M) ? *(const float4*)(A + (size_t)gr1 * K + ac4) : make_float4(0,0,0,0);
#pragma unroll
        for (int kk = 0; kk < 8; kk++) bv[kk] = B[(size_t)(bk0 + kk) * 128 + bn];
    }

    for (int k0 = 0; k0 < K; k0 += 16) {
        __syncthreads();
#pragma unroll
        for (int it = 0; it < 2; it++) {
            int r = ar + it * 64;
            float vv[4] = {av[it].x, av[it].y, av[it].z, av[it].w};
#pragma unroll
            for (int j = 0; j < 4; j++) {
                unsigned h = f2tf32(vv[j]);
                Ah[r * ASTR + ac4 + j] = h;
                Al[r * ASTR + ac4 + j] = f2tf32(vv[j] - __uint_as_float(h));
            }
        }
#pragma unroll
        for (int kk = 0; kk < 8; kk++) {
            unsigned h = f2tf32(bv[kk]);
            Bh[bn * ASTR + bk0 + kk] = h;
            Bl[bn * ASTR + bk0 + kk] = f2tf32(bv[kk] - __uint_as_float(h));
        }
        __syncthreads();
        if (k0 + 16 < K) {
            int kn = k0 + 16;
            int gr0 = row0 + ar, gr1 = gr0 + 64;
            av[0] = (gr0 < M) ? *(const float4*)(A + (size_t)gr0 * K + kn + ac4) : make_float4(0,0,0,0);
            av[1] = (gr1 < M) ? *(const float4*)(A + (size_t)gr1 * K + kn + ac4) : make_float4(0,0,0,0);
#pragma unroll
            for (int kk = 0; kk < 8; kk++) bv[kk] = B[(size_t)(kn + bk0 + kk) * 128 + bn];
        }
#pragma unroll
        for (int s = 0; s < 2; s++) {
            const int ks = s * 8;
            unsigned bh[4][2], bl[4][2];
#pragma unroll
            for (int nf = 0; nf < 4; nf++) {
                int b0 = (wn + nf * 8 + grp) * ASTR + ks + tg;
                bh[nf][0] = Bh[b0]; bh[nf][1] = Bh[b0 + 4];
                bl[nf][0] = Bl[b0]; bl[nf][1] = Bl[b0 + 4];
            }
#pragma unroll
            for (int mf = 0; mf < 4; mf++) {
                unsigned ah[4], al[4];
                int a0 = (wm + mf * 16 + grp) * ASTR + ks + tg;
                int a1 = a0 + 8 * ASTR;
                ah[0] = Ah[a0]; ah[1] = Ah[a1]; ah[2] = Ah[a0 + 4]; ah[3] = Ah[a1 + 4];
                al[0] = Al[a0]; al[1] = Al[a1]; al[2] = Al[a0 + 4]; al[3] = Al[a1 + 4];
#pragma unroll
                for (int nf = 0; nf < 4; nf++) {
                    MMA_TF32(c[mf][nf], ah, bh[nf]);
                    MMA_TF32(c[mf][nf], ah, bl[nf]);
                    MMA_TF32(c[mf][nf], al, bh[nf]);
                }
            }
        }
    }

#pragma unroll
    for (int mf = 0; mf < 4; mf++) {
        int r0 = row0 + wm + mf * 16 + grp;
        int r1 = r0 + 8;
#pragma unroll
        for (int nf = 0; nf < 4; nf++) {
            int col = wn + nf * 8 + 2 * tg;
            float bia0 = bias[col], bia1 = bias[col + 1];
            if (r0 < M) {
                float v0 = c[mf][nf][0] + bia0, v1 = c[mf][nf][1] + bia1;
                if (act) { v0 = silu(v0); v1 = silu(v1); }
                C[(size_t)r0 * 128 + col] = v0; C[(size_t)r0 * 128 + col + 1] = v1;
            }
            if (r1 < M) {
                float v2 = c[mf][nf][2] + bia0, v3 = c[mf][nf][3] + bia1;
                if (act) { v2 = silu(v2); v3 = silu(v3); }
                C[(size_t)r1 * 128 + col] = v2; C[(size_t)r1 * 128 + col + 1] = v3;
            }
        }
    }
}

// ---------------- mega layer kernel -----------------------------------------
// Phase A: [h | gskip] = feats[128rows, 512] @ [in_w | skip_w]  (h -> smem split, gskip -> global)
// Then 2 MLP blocks entirely in-block: t=silu(h@W1+b1); h=t@W2+b2+h; final += gskip -> g_x
__global__ __launch_bounds__(512, 1) void layer_kernel(
    const float* __restrict__ in_w,   const float* __restrict__ in_b,
    const float* __restrict__ skip_w, const float* __restrict__ skip_b,
    const float* __restrict__ mlp_w1, const float* __restrict__ mlp_b1,
    const float* __restrict__ mlp_w2, const float* __restrict__ mlp_b2,
    int l) {
    extern __shared__ unsigned sm[];
    unsigned* Xh  = sm;                    // 128*XSTR  resident split A
    unsigned* Xl  = Xh  + 128 * XSTR;
    unsigned* Ahs = Xl  + 128 * XSTR;      // 128*ASTR  streamed A chunks
    unsigned* Als = Ahs + 128 * ASTR;
    unsigned* Bhs = Als + 128 * ASTR;      // 256*ASTR  streamed B chunks
    unsigned* Bls = Bhs + 256 * ASTR;

    const int tid  = threadIdx.x;
    const int lane = tid & 31, wid = tid >> 5;
    const int grp  = lane >> 2, tg = lane & 3;
    const int wm   = (wid >> 3) * 64;   // 2 warps in M
    const int wni  = wid & 7;           // 8 warps in N
    const int row0 = blockIdx.x * 128;

    const float* Win = in_w   + (size_t)l * 512 * 128;
    const float* Wsk = skip_w + (size_t)l * 512 * 128;

    // ================= phase A: K=512, N=256 fused =================
    float cA[4][4][4];
#pragma unroll
    for (int i = 0; i < 4; i++)
#pragma unroll
        for (int j = 0; j < 4; j++)
#pragma unroll
            for (int q = 0; q < 4; q++) cA[i][j][q] = 0.f;

    const int ar  = tid >> 2;            // 0..127
    const int ac4 = (tid & 3) * 4;
    const int bn  = tid & 255;           // 0..255
    const int bk0 = (tid >> 8) * 8;      // 0 or 8
    const float* Wmy = (bn < 128) ? Win : Wsk;
    const int    bcol = bn & 127;

    float4 av; float bv[8];
    {
        int gr = row0 + ar;
        av = (gr < N_NODES) ? *(const float4*)(g_feats + (size_t)gr * 512 + ac4)
                            : make_float4(0,0,0,0);
#pragma unroll
        for (int kk = 0; kk < 8; kk++) bv[kk] = Wmy[(size_t)(bk0 + kk) * 128 + bcol];
    }

    const int wnA = wni * 32;
    for (int k0 = 0; k0 < 512; k0 += 16) {
        __syncthreads();
        {
            float vv[4] = {av.x, av.y, av.z, av.w};
#pragma unroll
            for (int j = 0; j < 4; j++) {
                unsigned h = f2tf32(vv[j]);
                Ahs[ar * ASTR + ac4 + j] = h;
                Als[ar * ASTR + ac4 + j] = f2tf32(vv[j] - __uint_as_float(h));
            }
#pragma unroll
            for (int kk = 0; kk < 8; kk++) {
                unsigned h = f2tf32(bv[kk]);
                Bhs[bn * ASTR + bk0 + kk] = h;
                Bls[bn * ASTR + bk0 + kk] = f2tf32(bv[kk] - __uint_as_float(h));
            }
        }
        __syncthreads();
        if (k0 + 16 < 512) {
            int kn = k0 + 16;
            int gr = row0 + ar;
            av = (gr < N_NODES) ? *(const float4*)(g_feats + (size_t)gr * 512 + kn + ac4)
                                : make_float4(0,0,0,0);
#pragma unroll
            for (int kk = 0; kk < 8; kk++) bv[kk] = Wmy[(size_t)(kn + bk0 + kk) * 128 + bcol];
        }
#pragma unroll
        for (int s = 0; s < 2; s++) {
            const int ks = s * 8;
            unsigned bh[4][2], bl[4][2];
#pragma unroll
            for (int nf = 0; nf < 4; nf++) {
                int b0 = (wnA + nf * 8 + grp) * ASTR + ks + tg;
                bh[nf][0] = Bhs[b0]; bh[nf][1] = Bhs[b0 + 4];
                bl[nf][0] = Bls[b0]; bl[nf][1] = Bls[b0 + 4];
            }
#pragma unroll
            for (int mf = 0; mf < 4; mf++) {
                unsigned ah[4], al[4];
                int a0 = (wm + mf * 16 + grp) * ASTR + ks + tg;
                int a1 = a0 + 8 * ASTR;
                ah[0] = Ahs[a0]; ah[1] = Ahs[a1]; ah[2] = Ahs[a0 + 4]; ah[3] = Ahs[a1 + 4];
                al[0] = Als[a0]; al[1] = Als[a1]; al[2] = Als[a0 + 4]; al[3] = Als[a1 + 4];
#pragma unroll
                for (int nf = 0; nf < 4; nf++) {
                    MMA_TF32(cA[mf][nf], ah, bh[nf]);
                    MMA_TF32(cA[mf][nf], ah, bl[nf]);
                    MMA_TF32(cA[mf][nf], al, bh[nf]);
                }
            }
        }
    }
    __syncthreads();  // streamed buffers done; safe to write Xh/Xl

    // phase A epilogue: wni<4 -> h (silu) into smem split; wni>=4 -> gskip to global
    {
        const float* bias = (wni < 4) ? (in_b + l * 128) : (skip_b + l * 128);
#pragma unroll
        for (int mf = 0; mf < 4; mf++) {
            int r0 = wm + mf * 16 + grp;
#pragma unroll
            for (int nf = 0; nf < 4; nf++) {
                int col = (wni & 3) * 32 + nf * 8 + 2 * tg;
                float b0 = bias[col], b1 = bias[col + 1];
                float v0 = cA[mf][nf][0] + b0, v1 = cA[mf][nf][1] + b1;
                float v2 = cA[mf][nf][2] + b0, v3 = cA[mf][nf][3] + b1;
                if (wni < 4) {
                    v0 = silu(v0); v1 = silu(v1); v2 = silu(v2); v3 = silu(v3);
                    unsigned h;
                    h = f2tf32(v0); Xh[r0*XSTR + col]       = h; Xl[r0*XSTR + col]       = f2tf32(v0 - __uint_as_float(h));
                    h = f2tf32(v1); Xh[r0*XSTR + col + 1]   = h; Xl[r0*XSTR + col + 1]   = f2tf32(v1 - __uint_as_float(h));
                    h = f2tf32(v2); Xh[(r0+8)*XSTR + col]   = h; Xl[(r0+8)*XSTR + col]   = f2tf32(v2 - __uint_as_float(h));
                    h = f2tf32(v3); Xh[(r0+8)*XSTR + col+1] = h; Xl[(r0+8)*XSTR + col+1] = f2tf32(v3 - __uint_as_float(h));
                } else {
                    int gr0 = row0 + r0, gr1 = gr0 + 8;
                    if (gr0 < N_NODES) { g_gskip[(size_t)gr0*128 + col] = v0; g_gskip[(size_t)gr0*128 + col+1] = v1; }
                    if (gr1 < N_NODES) { g_gskip[(size_t)gr1*128 + col] = v2; g_gskip[(size_t)gr1*128 + col+1] = v3; }
                }
            }
        }
    }
    __syncthreads();

    // ================= MLP chain: 2 blocks, K=128, N=128 =================
    const int wnM  = wni * 16;
    const int bn2  = tid & 127;
    const int kb2  = (tid >> 7) * 4;     // 0,4,8,12

    for (int m = 0; m < 2; m++) {
        const float* W1 = mlp_w1 + (size_t)(l * 2 + m) * 16384;
        const float* B1 = mlp_b1 + (l * 2 + m) * 128;
        const float* W2 = mlp_w2 + (size_t)(l * 2 + m) * 16384;
        const float* B2 = mlp_b2 + (l * 2 + m) * 128;

        for (int phase = 0; phase < 2; phase++) {
            const float* W = phase ? W2 : W1;
            float cT[4][2][4];
#pragma unroll
            for (int i = 0; i < 4; i++)
#pragma unroll
                for (int j = 0; j < 2; j++)
#pragma unroll
                    for (int q = 0; q < 4; q++) cT[i][j][q] = 0.f;

            float bv2[4];
#pragma unroll
            for (int kk = 0; kk < 4; kk++) bv2[kk] = W[(size_t)(kb2 + kk) * 128 + bn2];

            for (int k0 = 0; k0 < 128; k0 += 16) {
                __syncthreads();
#pragma unroll
                for (int kk = 0; kk < 4; kk++) {
                    unsigned h = f2tf32(bv2[kk]);
                    Bhs[bn2 * ASTR + kb2 + kk] = h;
                    Bls[bn2 * ASTR + kb2 + kk] = f2tf32(bv2[kk] - __uint_as_float(h));
                }
                __syncthreads();
                if (k0 + 16 < 128) {
                    int kn = k0 + 16;
#pragma unroll
                    for (int kk = 0; kk < 4; kk++) bv2[kk] = W[(size_t)(kn + kb2 + kk) * 128 + bn2];
                }
#pragma unroll
                for (int s = 0; s < 2; s++) {
                    const int ks = s * 8;         // within chunk (B), global = k0+ks (A)
                    unsigned bh[2][2], bl[2][2];
#pragma unroll
                    for (int nf = 0; nf < 2; nf++) {
                        int b0 = (wnM + nf * 8 + grp) * ASTR + ks + tg;
                        bh[nf][0] = Bhs[b0]; bh[nf][1] = Bhs[b0 + 4];
                        bl[nf][0] = Bls[b0]; bl[nf][1] = Bls[b0 + 4];
                    }
#pragma unroll
                    for (int mf = 0; mf < 4; mf++) {
                        unsigned ah[4], al[4];
                        int a0 = (wm + mf * 16 + grp) * XSTR + k0 + ks + tg;
                        int a1 = a0 + 8 * XSTR;
                        ah[0] = Xh[a0]; ah[1] = Xh[a1]; ah[2] = Xh[a0 + 4]; ah[3] = Xh[a1 + 4];
                        al[0] = Xl[a0]; al[1] = Xl[a1]; al[2] = Xl[a0 + 4]; al[3] = Xl[a1 + 4];
#pragma unroll
                        for (int nf = 0; nf < 2; nf++) {
                            MMA_TF32(cT[mf][nf], ah, bh[nf]);
                            MMA_TF32(cT[mf][nf], ah, bl[nf]);
                            MMA_TF32(cT[mf][nf], al, bh[nf]);
                        }
                    }
                }
            }

            if (phase == 0) {
                // t = silu(cT + b1); grab residual (current X) then overwrite X with t
                float res[4][2][4];
#pragma unroll
                for (int mf = 0; mf < 4; mf++) {
                    int r0 = wm + mf * 16 + grp;
#pragma unroll
                    for (int nf = 0; nf < 2; nf++) {
                        int col = wnM + nf * 8 + 2 * tg;
                        res[mf][nf][0] = __uint_as_float(Xh[r0*XSTR + col])       + __uint_as_float(Xl[r0*XSTR + col]);
                        res[mf][nf][1] = __uint_as_float(Xh[r0*XSTR + col + 1])   + __uint_as_float(Xl[r0*XSTR + col + 1]);
                        res[mf][nf][2] = __uint_as_float(Xh[(r0+8)*XSTR + col])   + __uint_as_float(Xl[(r0+8)*XSTR + col]);
                        res[mf][nf][3] = __uint_as_float(Xh[(r0+8)*XSTR + col+1]) + __uint_as_float(Xl[(r0+8)*XSTR + col+1]);
                        cT[mf][nf][0] = silu(cT[mf][nf][0] + B1[col]);
                        cT[mf][nf][1] = silu(cT[mf][nf][1] + B1[col + 1]);
                        cT[mf][nf][2] = silu(cT[mf][nf][2] + B1[col]);
                        cT[mf][nf][3] = silu(cT[mf][nf][3] + B1[col + 1]);
                    }
                }
                __syncthreads();
#pragma unroll
                for (int mf = 0; mf < 4; mf++) {
                    int r0 = wm + mf * 16 + grp;
#pragma unroll
                    for (int nf = 0; nf < 2; nf++) {
                        int col = wnM + nf * 8 + 2 * tg;
                        unsigned h;
                        h = f2tf32(cT[mf][nf][0]); Xh[r0*XSTR+col]       = h; Xl[r0*XSTR+col]       = f2tf32(cT[mf][nf][0]-__uint_as_float(h));
                        h = f2tf32(cT[mf][nf][1]); Xh[r0*XSTR+col+1]     = h; Xl[r0*XSTR+col+1]     = f2tf32(cT[mf][nf][1]-__uint_as_float(h));
                        h = f2tf32(cT[mf][nf][2]); Xh[(r0+8)*XSTR+col]   = h; Xl[(r0+8)*XSTR+col]   = f2tf32(cT[mf][nf][2]-__uint_as_float(h));
                        h = f2tf32(cT[mf][nf][3]); Xh[(r0+8)*XSTR+col+1] = h; Xl[(r0+8)*XSTR+col+1] = f2tf32(cT[mf][nf][3]-__uint_as_float(h));
                        // stash residual in cA slot? no: carry in res -> move to persistent regs below
                        cA[mf][nf][0] = res[mf][nf][0]; cA[mf][nf][1] = res[mf][nf][1];
                        cA[mf][nf][2] = res[mf][nf][2]; cA[mf][nf][3] = res[mf][nf][3];
                    }
                }
                __syncthreads();
            } else {
                // out = cT + b2 + residual(cA); last block: += gskip, -> g_x; else -> X split
                if (m == 0) __syncthreads();  // X frag reads done before overwrite
#pragma unroll
                for (int mf = 0; mf < 4; mf++) {
                    int r0 = wm + mf * 16 + grp;
#pragma unroll
                    for (int nf = 0; nf < 2; nf++) {
                        int col = wnM + nf * 8 + 2 * tg;
                        float o0 = cT[mf][nf][0] + B2[col]     + cA[mf][nf][0];
                        float o1 = cT[mf][nf][1] + B2[col + 1] + cA[mf][nf][1];
                        float o2 = cT[mf][nf][2] + B2[col]     + cA[mf][nf][2];
                        float o3 = cT[mf][nf][3] + B2[col + 1] + cA[mf][nf][3];
                        if (m == 1) {
                            int gr0 = row0 + r0, gr1 = gr0 + 8;
                            if (gr0 < N_NODES) {
                                g_x[(size_t)gr0*128 + col]   = o0 + g_gskip[(size_t)gr0*128 + col];
                                g_x[(size_t)gr0*128 + col+1] = o1 + g_gskip[(size_t)gr0*128 + col+1];
                            }
                            if (gr1 < N_NODES) {
                                g_x[(size_t)gr1*128 + col]   = o2 + g_gskip[(size_t)gr1*128 + col];
                                g_x[(size_t)gr1*128 + col+1] = o3 + g_gskip[(size_t)gr1*128 + col+1];
                            }
                        } else {
                            unsigned h;
                            h = f2tf32(o0); Xh[r0*XSTR+col]       = h; Xl[r0*XSTR+col]       = f2tf32(o0-__uint_as_float(h));
                            h = f2tf32(o1); Xh[r0*XSTR+col+1]     = h; Xl[r0*XSTR+col+1]     = f2tf32(o1-__uint_as_float(h));
                            h = f2tf32(o2); Xh[(r0+8)*XSTR+col]   = h; Xl[(r0+8)*XSTR+col]   = f2tf32(o2-__uint_as_float(h));
                            h = f2tf32(o3); Xh[(r0+8)*XSTR+col+1] = h; Xl[(r0+8)*XSTR+col+1] = f2tf32(o3-__uint_as_float(h));
                        }
                    }
                }
                if (m == 0) __syncthreads();
            }
        }
    }
}

// ---------------- per-layer feats init --------------------------------------
__global__ void init_feats_kernel() {
    int j4 = blockIdx.x * blockDim.x + threadIdx.x;
    if (j4 >= N_NODES * 128) return;
    int n = j4 >> 7, c4 = j4 & 127;
    float4* f4 = (float4*)g_feats;
    const float4* x4 = (const float4*)g_x;
    f4[j4] = (c4 < 32) ? x4[n * 32 + c4] : make_float4(0.f, 0.f, 0.f, 0.f);
}

// ---------------- edge scatter ----------------------------------------------
__global__ void scatter_kernel(const int* __restrict__ tgt, const int* __restrict__ srcv) {
    int w    = (blockIdx.x * blockDim.x + threadIdx.x) >> 5;
    int lane = threadIdx.x & 31;
    if (w >= N_EDGES) return;
    int s  = srcv[w];
    int t  = tgt[w];
    int sn = s % N_NODES;
    int tn = t % N_NODES;
    int hop = t / N_NODES;
    float4 v = *(const float4*)(g_x + (size_t)sn * HID + lane * 4);
    float* dst = g_feats + (size_t)tn * 512 + (hop + 1) * HID + lane * 4;
    asm volatile("red.global.add.v4.f32 [%0], {%1,%2,%3,%4};"
                 :: "l"(dst), "f"(v.x), "f"(v.y), "f"(v.z), "f"(v.w)
                 : "memory");
}

// ---------------- pooling ----------------------------------------------------
__global__ void init_pool_kernel() {
    int i = blockIdx.x * blockDim.x + threadIdx.x;
    if (i < NUM_GRAPHS * HID) g_pooled[i] = 0.f;
    if (i < NUM_GRAPHS * 4) { g_smax[i] = 0u; g_sden[i] = 0.f; }
}

__global__ void scores_kernel(const int* __restrict__ batch, const float* __restrict__ attn_w,
                              const float* __restrict__ attn_b, const float* __restrict__ temp) {
    int w    = (blockIdx.x * blockDim.x + threadIdx.x) >> 5;
    int lane = threadIdx.x & 31;
    if (w >= N_NODES) return;
    float a[4] = {0.f, 0.f, 0.f, 0.f};
    for (int c = lane; c < HID; c += 32) {
        float xv = g_x[(size_t)w * HID + c];
        a[0] += xv * attn_w[c];
        a[1] += xv * attn_w[128 + c];
        a[2] += xv * attn_w[256 + c];
        a[3] += xv * attn_w[384 + c];
    }
#pragma unroll
    for (int o = 16; o; o >>= 1)
#pragma unroll
        for (int h = 0; h < 4; h++) a[h] += __shfl_down_sync(0xffffffffu, a[h], o);
    if (lane == 0) {
        float invT = 1.f / temp[0];
        int g = batch[w];
#pragma unroll
        for (int h = 0; h < 4; h++) {
            float sc = (a[h] + attn_b[h]) * invT;
            g_scores[w * 4 + h] = sc;
            atomicMax(&g_smax[g * 4 + h], fmap(sc));
        }
    }
}

__global__ void exp_kernel(const int* __restrict__ batch) {
    int i = blockIdx.x * blockDim.x + threadIdx.x;
    if (i >= N_NODES * 4) return;
    int n = i >> 2, h = i & 3;
    int g = batch[n];
    float e = expf(g_scores[i] - funmap(g_smax[g * 4 + h]));
    g_scores[i] = e;
    atomicAdd(&g_sden[g * 4 + h], e);
}

__global__ void pool_kernel(const int* __restrict__ batch) {
    int n = blockIdx.x;
    int c = threadIdx.x;
    int g = batch[n];
    float wbar = 0.f;
#pragma unroll
    for (int h = 0; h < 4; h++) wbar += g_scores[n * 4 + h] / g_sden[g * 4 + h];
    wbar *= 0.25f;
    atomicAdd(&g_pooled[g * HID + c], g_x[(size_t)n * HID + c] * wbar);
}

// ---------------- readout FFN -----------------------------------------------
__global__ void ffn_kernel(const float* __restrict__ w1, const float* __restrict__ b1,
                           const float* __restrict__ w2, const float* __restrict__ b2,
                           const float* __restrict__ w3, const float* __restrict__ b3,
                           float* __restrict__ out) {
    int g = blockIdx.x;
    int t = threadIdx.x;
    __shared__ float p[128], h1[128], red[128];
    p[t] = g_pooled[g * HID + t];
    __syncthreads();
    float acc = b1[t];
#pragma unroll 8
    for (int k = 0; k < 128; k++) acc += p[k] * w1[k * 128 + t];
    h1[t] = silu(acc);
    __syncthreads();
    float acc2 = b2[t];
#pragma unroll 8
    for (int k = 0; k < 128; k++) acc2 += h1[k] * w2[k * 128 + t];
    acc2 = silu(acc2);
    red[t] = acc2 * w3[t];
    __syncthreads();
    for (int s = 64; s > 0; s >>= 1) {
        if (t < s) red[t] += red[t + s];
        __syncthreads();
    }
    if (t == 0) out[g] = red[0] + b3[0];
}

// ---------------- host launcher ---------------------------------------------
extern "C" void kernel_launch(void* const* d_in, const int* in_sizes, int n_in,
                              void* d_out, int out_size) {
    const int* atom  = (const int*)d_in[0];
    const int* hyd   = (const int*)d_in[1];
    const int* deg   = (const int*)d_in[2];
    const int* hyb   = (const int*)d_in[3];
    const int* tgt   = (const int*)d_in[4];
    const int* srcv  = (const int*)d_in[5];
    const int* batch = (const int*)d_in[6];
    const float* emb_atom = (const float*)d_in[7];
    const float* emb_h    = (const float*)d_in[8];
    const float* emb_deg  = (const float*)d_in[9];
    const float* emb_hyb  = (const float*)d_in[10];
    const float* proj_w   = (const float*)d_in[11];
    const float* proj_b   = (const float*)d_in[12];
    const float* in_w     = (const float*)d_in[13];
    const float* in_b     = (const float*)d_in[14];
    const float* mlp_w1   = (const float*)d_in[15];
    const float* mlp_b1   = (const float*)d_in[16];
    const float* mlp_w2   = (const float*)d_in[17];
    const float* mlp_b2   = (const float*)d_in[18];
    const float* skip_w   = (const float*)d_in[19];
    const float* skip_b   = (const float*)d_in[20];
    const float* attn_w   = (const float*)d_in[21];
    const float* attn_b   = (const float*)d_in[22];
    const float* temp     = (const float*)d_in[23];
    const float* ffn_w1   = (const float*)d_in[24];
    const float* ffn_b1   = (const float*)d_in[25];
    const float* ffn_w2   = (const float*)d_in[26];
    const float* ffn_b2   = (const float*)d_in[27];
    const float* ffn_w3   = (const float*)d_in[28];
    const float* ffn_b3   = (const float*)d_in[29];
    float* out = (float*)d_out;

    float *pemb, *px;
    cudaGetSymbolAddress((void**)&pemb, g_emb);
    cudaGetSymbolAddress((void**)&px,   g_x);

    const int LAYER_SMEM = (2 * 128 * XSTR + 2 * 128 * ASTR + 2 * 256 * ASTR) * 4;  // 196608
    cudaFuncSetAttribute(layer_kernel, cudaFuncAttributeMaxDynamicSharedMemorySize, LAYER_SMEM);

    // 1. embedding + projection
    gather_embed_kernel<<<N_NODES, 64>>>(atom, hyd, deg, hyb, emb_atom, emb_h, emb_deg, emb_hyb);
    mma_gemm_kernel<<<GEMM_BLKS, 256>>>(pemb, proj_w, proj_b, px, N_NODES, 256, 1);

    // 2. shell conv layers (one mega kernel per layer)
    for (int l = 0; l < 3; l++) {
        init_feats_kernel<<<(N_NODES * 128 + 255) / 256, 256>>>();
        scatter_kernel<<<N_EDGES / 8, 256>>>(tgt, srcv);
        layer_kernel<<<GEMM_BLKS, 512, LAYER_SMEM>>>(in_w, in_b, skip_w, skip_b,
                                                     mlp_w1, mlp_b1, mlp_w2, mlp_b2, l);
    }

    // 3. attention pooling
    init_pool_kernel<<<(NUM_GRAPHS * HID + 255) / 256, 256>>>();
    scores_kernel<<<(N_NODES * 32 + 255) / 256, 256>>>(batch, attn_w, attn_b, temp);
    exp_kernel<<<(N_NODES * 4 + 255) / 256, 256>>>(batch);
    pool_kernel<<<N_NODES, 128>>>(batch);

    // 4. readout FFN
    ffn_kernel<<<NUM_GRAPHS, 128>>>(ffn_w1, ffn_b1, ffn_w2, ffn_b2, ffn_w3, ffn_b3, out);
}

// round 4
// speedup vs baseline: 2.4500x; 1.3245x over previous
#include <cuda_runtime.h>

#define N_NODES   50000
#define N_EDGES   2400000
#define NUM_GRAPHS 2048
#define NSLOT     (3 * N_NODES)          // 150000 hop-slots
#define NCHUNK    ((NSLOT + 1023) / 1024) // 147
#define HID       128
#define GEMM_BLKS ((N_NODES + 127) / 128)   // 391
#define ASTR 20    // smem stride for streamed 16-wide k tiles
#define XSTR 132   // smem stride for resident 128-wide split buffers

// ---------------- scratch (static device memory; no allocs) ----------------
__device__ __align__(16) float g_x[N_NODES * HID];
__device__ __align__(16) float g_hops[(size_t)N_NODES * 384];  // 3 hops x 128
__device__ __align__(16) float g_gskip[N_NODES * HID];
__device__ int g_cnt[NSLOT];
__device__ int g_csum[NCHUNK];
__device__ int g_coff[NCHUNK];
__device__ int g_rowptr[NSLOT + 1];
__device__ int g_cursor[NSLOT];
__device__ int g_esrc[N_EDGES];
__device__ float    g_scores[N_NODES * 4];
__device__ unsigned g_smax[NUM_GRAPHS * 4];
__device__ float    g_sden[NUM_GRAPHS * 4];
__device__ float    g_pooled[NUM_GRAPHS * HID];

__device__ __forceinline__ unsigned fmap(float f) {
    unsigned u = __float_as_uint(f);
    return (u >> 31) ? ~u : (u | 0x80000000u);
}
__device__ __forceinline__ float funmap(unsigned u) {
    return (u >> 31) ? __uint_as_float(u & 0x7fffffffu) : __uint_as_float(~u);
}
__device__ __forceinline__ float silu(float v) { return v / (1.f + __expf(-v)); }

__device__ __forceinline__ unsigned f2tf32(float v) {
    unsigned r;
    asm("cvt.rna.tf32.f32 %0, %1;" : "=r"(r) : "f"(v));
    return r;
}

#define MMA_TF32(cc, aa, bb) \
    asm volatile("mma.sync.aligned.m16n8k8.row.col.f32.tf32.tf32.f32 " \
                 "{%0,%1,%2,%3},{%4,%5,%6,%7},{%8,%9},{%0,%1,%2,%3};" \
                 : "+f"(cc[0]), "+f"(cc[1]), "+f"(cc[2]), "+f"(cc[3]) \
                 : "r"(aa[0]), "r"(aa[1]), "r"(aa[2]), "r"(aa[3]), \
                   "r"(bb[0]), "r"(bb[1]))

// ================= CSR build =================
__global__ void zero_cnt_kernel() {
    int i = blockIdx.x * blockDim.x + threadIdx.x;
    if (i < NSLOT) g_cnt[i] = 0;
}
__global__ void count_kernel(const int* __restrict__ tgt) {
    int e = blockIdx.x * blockDim.x + threadIdx.x;
    if (e < N_EDGES) atomicAdd(&g_cnt[tgt[e]], 1);
}
__global__ void chunk_sum_kernel() {
    __shared__ int red[256];
    int b = blockIdx.x, t = threadIdx.x;
    int s = 0;
#pragma unroll
    for (int j = 0; j < 4; j++) {
        int i = b * 1024 + j * 256 + t;
        if (i < NSLOT) s += g_cnt[i];
    }
    red[t] = s; __syncthreads();
    for (int o = 128; o > 0; o >>= 1) {
        if (t < o) red[t] += red[t + o];
        __syncthreads();
    }
    if (t == 0) g_csum[b] = red[0];
}
__global__ void scan_chunks_kernel() {
    if (threadIdx.x == 0) {
        int run = 0;
        for (int b = 0; b < NCHUNK; b++) { g_coff[b] = run; run += g_csum[b]; }
        g_rowptr[NSLOT] = run;
    }
}
__global__ void scan_within_kernel() {
    __shared__ int buf[2][1024];
    int b = blockIdx.x, t = threadIdx.x;
    int i = b * 1024 + t;
    int v = (i < NSLOT) ? g_cnt[i] : 0;
    buf[0][t] = v;
    __syncthreads();
    int cur = 0;
#pragma unroll
    for (int off = 1; off < 1024; off <<= 1) {
        int nv = buf[cur][t] + ((t >= off) ? buf[cur][t - off] : 0);
        buf[cur ^ 1][t] = nv;
        cur ^= 1;
        __syncthreads();
    }
    if (i < NSLOT) {
        int excl = buf[cur][t] - v;
        int rp = g_coff[b] + excl;
        g_rowptr[i] = rp;
        g_cursor[i] = rp;
    }
}
__global__ void fill_kernel(const int* __restrict__ tgt, const int* __restrict__ srcv) {
    int e = blockIdx.x * blockDim.x + threadIdx.x;
    if (e >= N_EDGES) return;
    int t = tgt[e];
    int pos = atomicAdd(&g_cursor[t], 1);
    g_esrc[pos] = srcv[e] % N_NODES;
}

// ================= hop gather: one warp per slot, no atomics =================
__global__ __launch_bounds__(256) void gather_hops_kernel() {
    int slot = (blockIdx.x * blockDim.x + threadIdx.x) >> 5;
    int lane = threadIdx.x & 31;
    if (slot >= NSLOT) return;
    int beg = g_rowptr[slot], end = g_rowptr[slot + 1];
    float4 acc0 = make_float4(0.f, 0.f, 0.f, 0.f);
    float4 acc1 = make_float4(0.f, 0.f, 0.f, 0.f);
    int e = beg;
    for (; e + 1 < end; e += 2) {
        int s0 = g_esrc[e], s1 = g_esrc[e + 1];
        float4 v0 = *(const float4*)(g_x + (size_t)s0 * HID + lane * 4);
        float4 v1 = *(const float4*)(g_x + (size_t)s1 * HID + lane * 4);
        acc0.x += v0.x; acc0.y += v0.y; acc0.z += v0.z; acc0.w += v0.w;
        acc1.x += v1.x; acc1.y += v1.y; acc1.z += v1.z; acc1.w += v1.w;
    }
    if (e < end) {
        int s0 = g_esrc[e];
        float4 v0 = *(const float4*)(g_x + (size_t)s0 * HID + lane * 4);
        acc0.x += v0.x; acc0.y += v0.y; acc0.z += v0.z; acc0.w += v0.w;
    }
    acc0.x += acc1.x; acc0.y += acc1.y; acc0.z += acc1.z; acc0.w += acc1.w;
    int node = slot % N_NODES, hop = slot / N_NODES;
    *(float4*)(g_hops + (size_t)node * 384 + hop * HID + lane * 4) = acc0;
}

// ================= fused embed+proj GEMM =================
// x = silu(concat(emb tables)[N,256] @ proj_w[256,128] + b)
__global__ __launch_bounds__(256) void proj_kernel(
    const int* __restrict__ atom, const int* __restrict__ hyd,
    const int* __restrict__ deg,  const int* __restrict__ hyb,
    const float* __restrict__ ea, const float* __restrict__ eh,
    const float* __restrict__ ed, const float* __restrict__ ey,
    const float* __restrict__ B, const float* __restrict__ bias) {
    __shared__ unsigned Ah[128 * ASTR], Al[128 * ASTR];
    __shared__ unsigned Bh[128 * ASTR], Bl[128 * ASTR];
    __shared__ int sidx[128][4];

    const int tid  = threadIdx.x;
    const int lane = tid & 31, wid = tid >> 5;
    const int wm = (wid >> 2) * 64;
    const int wn = (wid & 3) * 32;
    const int grp = lane >> 2, tg = lane & 3;
    const int row0 = blockIdx.x * 128;

    if (tid < 128) {
        int gr = row0 + tid;
        int g2 = (gr < N_NODES) ? gr : 0;
        sidx[tid][0] = atom[g2];
        sidx[tid][1] = hyd[g2];
        sidx[tid][2] = deg[g2];
        sidx[tid][3] = hyb[g2];
    }
    __syncthreads();
    const float* tabs[4] = {ea, eh, ed, ey};

    float c[4][4][4];
#pragma unroll
    for (int i = 0; i < 4; i++)
#pragma unroll
        for (int j = 0; j < 4; j++)
#pragma unroll
            for (int q = 0; q < 4; q++) c[i][j][q] = 0.f;

    const int ar  = tid >> 2;        // 0..63
    const int ac4 = (tid & 3) * 4;
    const int bn  = tid & 127;
    const int bk0 = (tid >> 7) * 8;

    for (int k0 = 0; k0 < 256; k0 += 16) {
        float4 av[2]; float bv[8];
        int kt = (k0 + ac4) >> 6, kw = (k0 + ac4) & 63;
#pragma unroll
        for (int it = 0; it < 2; it++) {
            int r = ar + it * 64;
            av[it] = *(const float4*)(tabs[kt] + (size_t)sidx[r][kt] * 64 + kw);
        }
#pragma unroll
        for (int kk = 0; kk < 8; kk++) bv[kk] = B[(size_t)(k0 + bk0 + kk) * 128 + bn];

        __syncthreads();
#pragma unroll
        for (int it = 0; it < 2; it++) {
            int r = ar + it * 64;
            float vv[4] = {av[it].x, av[it].y, av[it].z, av[it].w};
#pragma unroll
            for (int j = 0; j < 4; j++) {
                unsigned h = f2tf32(vv[j]);
                Ah[r * ASTR + ac4 + j] = h;
                Al[r * ASTR + ac4 + j] = f2tf32(vv[j] - __uint_as_float(h));
            }
        }
#pragma unroll
        for (int kk = 0; kk < 8; kk++) {
            unsigned h = f2tf32(bv[kk]);
            Bh[bn * ASTR + bk0 + kk] = h;
            Bl[bn * ASTR + bk0 + kk] = f2tf32(bv[kk] - __uint_as_float(h));
        }
        __syncthreads();
#pragma unroll
        for (int s = 0; s < 2; s++) {
            const int ks = s * 8;
            unsigned bh[4][2], bl[4][2];
#pragma unroll
            for (int nf = 0; nf < 4; nf++) {
                int b0 = (wn + nf * 8 + grp) * ASTR + ks + tg;
                bh[nf][0] = Bh[b0]; bh[nf][1] = Bh[b0 + 4];
                bl[nf][0] = Bl[b0]; bl[nf][1] = Bl[b0 + 4];
            }
#pragma unroll
            for (int mf = 0; mf < 4; mf++) {
                unsigned ah[4], al[4];
                int a0 = (wm + mf * 16 + grp) * ASTR + ks + tg;
                int a1 = a0 + 8 * ASTR;
                ah[0] = Ah[a0]; ah[1] = Ah[a1]; ah[2] = Ah[a0 + 4]; ah[3] = Ah[a1 + 4];
                al[0] = Al[a0]; al[1] = Al[a1]; al[2] = Al[a0 + 4]; al[3] = Al[a1 + 4];
#pragma unroll
                for (int nf = 0; nf < 4; nf++) {
                    MMA_TF32(c[mf][nf], ah, bh[nf]);
                    MMA_TF32(c[mf][nf], ah, bl[nf]);
                    MMA_TF32(c[mf][nf], al, bh[nf]);
                }
            }
        }
    }

#pragma unroll
    for (int mf = 0; mf < 4; mf++) {
        int r0 = row0 + wm + mf * 16 + grp;
        int r1 = r0 + 8;
#pragma unroll
        for (int nf = 0; nf < 4; nf++) {
            int col = wn + nf * 8 + 2 * tg;
            float bia0 = bias[col], bia1 = bias[col + 1];
            if (r0 < N_NODES) {
                g_x[(size_t)r0 * 128 + col]     = silu(c[mf][nf][0] + bia0);
                g_x[(size_t)r0 * 128 + col + 1] = silu(c[mf][nf][1] + bia1);
            }
            if (r1 < N_NODES) {
                g_x[(size_t)r1 * 128 + col]     = silu(c[mf][nf][2] + bia0);
                g_x[(size_t)r1 * 128 + col + 1] = silu(c[mf][nf][3] + bia1);
            }
        }
    }
}

// ================= mega layer kernel =================
// feats row = [x row (g_x) | hop rows (g_hops)]
__device__ __forceinline__ const float* feat_ptr(int gr, int k) {
    return (k < 128) ? (g_x + (size_t)gr * 128 + k)
                     : (g_hops + (size_t)gr * 384 + (k - 128));
}

__global__ __launch_bounds__(512, 1) void layer_kernel(
    const float* __restrict__ in_w,   const float* __restrict__ in_b,
    const float* __restrict__ skip_w, const float* __restrict__ skip_b,
    const float* __restrict__ mlp_w1, const float* __restrict__ mlp_b1,
    const float* __restrict__ mlp_w2, const float* __restrict__ mlp_b2,
    int l) {
    extern __shared__ unsigned sm[];
    unsigned* Xh  = sm;
    unsigned* Xl  = Xh  + 128 * XSTR;
    unsigned* Ahs = Xl  + 128 * XSTR;
    unsigned* Als = Ahs + 128 * ASTR;
    unsigned* Bhs = Als + 128 * ASTR;
    unsigned* Bls = Bhs + 256 * ASTR;

    const int tid  = threadIdx.x;
    const int lane = tid & 31, wid = tid >> 5;
    const int grp  = lane >> 2, tg = lane & 3;
    const int wm   = (wid >> 3) * 64;
    const int wni  = wid & 7;
    const int row0 = blockIdx.x * 128;

    const float* Win = in_w   + (size_t)l * 512 * 128;
    const float* Wsk = skip_w + (size_t)l * 512 * 128;

    float cA[4][4][4];
#pragma unroll
    for (int i = 0; i < 4; i++)
#pragma unroll
        for (int j = 0; j < 4; j++)
#pragma unroll
            for (int q = 0; q < 4; q++) cA[i][j][q] = 0.f;

    const int ar  = tid >> 2;
    const int ac4 = (tid & 3) * 4;
    const int bn  = tid & 255;
    const int bk0 = (tid >> 8) * 8;
    const float* Wmy = (bn < 128) ? Win : Wsk;
    const int    bcol = bn & 127;

    float4 av; float bv[8];
    {
        int gr = row0 + ar;
        av = (gr < N_NODES) ? *(const float4*)feat_ptr(gr, ac4) : make_float4(0,0,0,0);
#pragma unroll
        for (int kk = 0; kk < 8; kk++) bv[kk] = Wmy[(size_t)(bk0 + kk) * 128 + bcol];
    }

    const int wnA = wni * 32;
    for (int k0 = 0; k0 < 512; k0 += 16) {
        __syncthreads();
        {
            float vv[4] = {av.x, av.y, av.z, av.w};
#pragma unroll
            for (int j = 0; j < 4; j++) {
                unsigned h = f2tf32(vv[j]);
                Ahs[ar * ASTR + ac4 + j] = h;
                Als[ar * ASTR + ac4 + j] = f2tf32(vv[j] - __uint_as_float(h));
            }
#pragma unroll
            for (int kk = 0; kk < 8; kk++) {
                unsigned h = f2tf32(bv[kk]);
                Bhs[bn * ASTR + bk0 + kk] = h;
                Bls[bn * ASTR + bk0 + kk] = f2tf32(bv[kk] - __uint_as_float(h));
            }
        }
        __syncthreads();
        if (k0 + 16 < 512) {
            int kn = k0 + 16;
            int gr = row0 + ar;
            av = (gr < N_NODES) ? *(const float4*)feat_ptr(gr, kn + ac4) : make_float4(0,0,0,0);
#pragma unroll
            for (int kk = 0; kk < 8; kk++) bv[kk] = Wmy[(size_t)(kn + bk0 + kk) * 128 + bcol];
        }
#pragma unroll
        for (int s = 0; s < 2; s++) {
            const int ks = s * 8;
            unsigned bh[4][2], bl[4][2];
#pragma unroll
            for (int nf = 0; nf < 4; nf++) {
                int b0 = (wnA + nf * 8 + grp) * ASTR + ks + tg;
                bh[nf][0] = Bhs[b0]; bh[nf][1] = Bhs[b0 + 4];
                bl[nf][0] = Bls[b0]; bl[nf][1] = Bls[b0 + 4];
            }
#pragma unroll
            for (int mf = 0; mf < 4; mf++) {
                unsigned ah[4], al[4];
                int a0 = (wm + mf * 16 + grp) * ASTR + ks + tg;
                int a1 = a0 + 8 * ASTR;
                ah[0] = Ahs[a0]; ah[1] = Ahs[a1]; ah[2] = Ahs[a0 + 4]; ah[3] = Ahs[a1 + 4];
                al[0] = Als[a0]; al[1] = Als[a1]; al[2] = Als[a0 + 4]; al[3] = Als[a1 + 4];
#pragma unroll
                for (int nf = 0; nf < 4; nf++) {
                    MMA_TF32(cA[mf][nf], ah, bh[nf]);
                    MMA_TF32(cA[mf][nf], ah, bl[nf]);
                    MMA_TF32(cA[mf][nf], al, bh[nf]);
                }
            }
        }
    }
    __syncthreads();

    {
        const float* bias = (wni < 4) ? (in_b + l * 128) : (skip_b + l * 128);
#pragma unroll
        for (int mf = 0; mf < 4; mf++) {
            int r0 = wm + mf * 16 + grp;
#pragma unroll
            for (int nf = 0; nf < 4; nf++) {
                int col = (wni & 3) * 32 + nf * 8 + 2 * tg;
                float b0 = bias[col], b1 = bias[col + 1];
                float v0 = cA[mf][nf][0] + b0, v1 = cA[mf][nf][1] + b1;
                float v2 = cA[mf][nf][2] + b0, v3 = cA[mf][nf][3] + b1;
                if (wni < 4) {
                    v0 = silu(v0); v1 = silu(v1); v2 = silu(v2); v3 = silu(v3);
                    unsigned h;
                    h = f2tf32(v0); Xh[r0*XSTR + col]       = h; Xl[r0*XSTR + col]       = f2tf32(v0 - __uint_as_float(h));
                    h = f2tf32(v1); Xh[r0*XSTR + col + 1]   = h; Xl[r0*XSTR + col + 1]   = f2tf32(v1 - __uint_as_float(h));
                    h = f2tf32(v2); Xh[(r0+8)*XSTR + col]   = h; Xl[(r0+8)*XSTR + col]   = f2tf32(v2 - __uint_as_float(h));
                    h = f2tf32(v3); Xh[(r0+8)*XSTR + col+1] = h; Xl[(r0+8)*XSTR + col+1] = f2tf32(v3 - __uint_as_float(h));
                } else {
                    int gr0 = row0 + r0, gr1 = gr0 + 8;
                    if (gr0 < N_NODES) { g_gskip[(size_t)gr0*128 + col] = v0; g_gskip[(size_t)gr0*128 + col+1] = v1; }
                    if (gr1 < N_NODES) { g_gskip[(size_t)gr1*128 + col] = v2; g_gskip[(size_t)gr1*128 + col+1] = v3; }
                }
            }
        }
    }
    __syncthreads();

    const int wnM  = wni * 16;
    const int bn2  = tid & 127;
    const int kb2  = (tid >> 7) * 4;

    for (int m = 0; m < 2; m++) {
        const float* B1 = mlp_b1 + (l * 2 + m) * 128;
        const float* B2 = mlp_b2 + (l * 2 + m) * 128;

        for (int phase = 0; phase < 2; phase++) {
            const float* W = (phase ? mlp_w2 : mlp_w1) + (size_t)(l * 2 + m) * 16384;
            float cT[4][2][4];
#pragma unroll
            for (int i = 0; i < 4; i++)
#pragma unroll
                for (int j = 0; j < 2; j++)
#pragma unroll
                    for (int q = 0; q < 4; q++) cT[i][j][q] = 0.f;

            float bv2[4];
#pragma unroll
            for (int kk = 0; kk < 4; kk++) bv2[kk] = W[(size_t)(kb2 + kk) * 128 + bn2];

            for (int k0 = 0; k0 < 128; k0 += 16) {
                __syncthreads();
#pragma unroll
                for (int kk = 0; kk < 4; kk++) {
                    unsigned h = f2tf32(bv2[kk]);
                    Bhs[bn2 * ASTR + kb2 + kk] = h;
                    Bls[bn2 * ASTR + kb2 + kk] = f2tf32(bv2[kk] - __uint_as_float(h));
                }
                __syncthreads();
                if (k0 + 16 < 128) {
                    int kn = k0 + 16;
#pragma unroll
                    for (int kk = 0; kk < 4; kk++) bv2[kk] = W[(size_t)(kn + kb2 + kk) * 128 + bn2];
                }
#pragma unroll
                for (int s = 0; s < 2; s++) {
                    const int ks = s * 8;
                    unsigned bh[2][2], bl[2][2];
#pragma unroll
                    for (int nf = 0; nf < 2; nf++) {
                        int b0 = (wnM + nf * 8 + grp) * ASTR + ks + tg;
                        bh[nf][0] = Bhs[b0]; bh[nf][1] = Bhs[b0 + 4];
                        bl[nf][0] = Bls[b0]; bl[nf][1] = Bls[b0 + 4];
                    }
#pragma unroll
                    for (int mf = 0; mf < 4; mf++) {
                        unsigned ah[4], al[4];
                        int a0 = (wm + mf * 16 + grp) * XSTR + k0 + ks + tg;
                        int a1 = a0 + 8 * XSTR;
                        ah[0] = Xh[a0]; ah[1] = Xh[a1]; ah[2] = Xh[a0 + 4]; ah[3] = Xh[a1 + 4];
                        al[0] = Xl[a0]; al[1] = Xl[a1]; al[2] = Xl[a0 + 4]; al[3] = Xl[a1 + 4];
#pragma unroll
                        for (int nf = 0; nf < 2; nf++) {
                            MMA_TF32(cT[mf][nf], ah, bh[nf]);
                            MMA_TF32(cT[mf][nf], ah, bl[nf]);
                            MMA_TF32(cT[mf][nf], al, bh[nf]);
                        }
                    }
                }
            }

            if (phase == 0) {
                float res[4][2][4];
#pragma unroll
                for (int mf = 0; mf < 4; mf++) {
                    int r0 = wm + mf * 16 + grp;
#pragma unroll
                    for (int nf = 0; nf < 2; nf++) {
                        int col = wnM + nf * 8 + 2 * tg;
                        res[mf][nf][0] = __uint_as_float(Xh[r0*XSTR + col])       + __uint_as_float(Xl[r0*XSTR + col]);
                        res[mf][nf][1] = __uint_as_float(Xh[r0*XSTR + col + 1])   + __uint_as_float(Xl[r0*XSTR + col + 1]);
                        res[mf][nf][2] = __uint_as_float(Xh[(r0+8)*XSTR + col])   + __uint_as_float(Xl[(r0+8)*XSTR + col]);
                        res[mf][nf][3] = __uint_as_float(Xh[(r0+8)*XSTR + col+1]) + __uint_as_float(Xl[(r0+8)*XSTR + col+1]);
                        cT[mf][nf][0] = silu(cT[mf][nf][0] + B1[col]);
                        cT[mf][nf][1] = silu(cT[mf][nf][1] + B1[col + 1]);
                        cT[mf][nf][2] = silu(cT[mf][nf][2] + B1[col]);
                        cT[mf][nf][3] = silu(cT[mf][nf][3] + B1[col + 1]);
                    }
                }
                __syncthreads();
#pragma unroll
                for (int mf = 0; mf < 4; mf++) {
                    int r0 = wm + mf * 16 + grp;
#pragma unroll
                    for (int nf = 0; nf < 2; nf++) {
                        int col = wnM + nf * 8 + 2 * tg;
                        unsigned h;
                        h = f2tf32(cT[mf][nf][0]); Xh[r0*XSTR+col]       = h; Xl[r0*XSTR+col]       = f2tf32(cT[mf][nf][0]-__uint_as_float(h));
                        h = f2tf32(cT[mf][nf][1]); Xh[r0*XSTR+col+1]     = h; Xl[r0*XSTR+col+1]     = f2tf32(cT[mf][nf][1]-__uint_as_float(h));
                        h = f2tf32(cT[mf][nf][2]); Xh[(r0+8)*XSTR+col]   = h; Xl[(r0+8)*XSTR+col]   = f2tf32(cT[mf][nf][2]-__uint_as_float(h));
                        h = f2tf32(cT[mf][nf][3]); Xh[(r0+8)*XSTR+col+1] = h; Xl[(r0+8)*XSTR+col+1] = f2tf32(cT[mf][nf][3]-__uint_as_float(h));
                        cA[mf][nf][0] = res[mf][nf][0]; cA[mf][nf][1] = res[mf][nf][1];
                        cA[mf][nf][2] = res[mf][nf][2]; cA[mf][nf][3] = res[mf][nf][3];
                    }
                }
                __syncthreads();
            } else {
                if (m == 0) __syncthreads();
#pragma unroll
                for (int mf = 0; mf < 4; mf++) {
                    int r0 = wm + mf * 16 + grp;
#pragma unroll
                    for (int nf = 0; nf < 2; nf++) {
                        int col = wnM + nf * 8 + 2 * tg;
                        float o0 = cT[mf][nf][0] + B2[col]     + cA[mf][nf][0];
                        float o1 = cT[mf][nf][1] + B2[col + 1] + cA[mf][nf][1];
                        float o2 = cT[mf][nf][2] + B2[col]     + cA[mf][nf][2];
                        float o3 = cT[mf][nf][3] + B2[col + 1] + cA[mf][nf][3];
                        if (m == 1) {
                            int gr0 = row0 + r0, gr1 = gr0 + 8;
                            if (gr0 < N_NODES) {
                                g_x[(size_t)gr0*128 + col]   = o0 + g_gskip[(size_t)gr0*128 + col];
                                g_x[(size_t)gr0*128 + col+1] = o1 + g_gskip[(size_t)gr0*128 + col+1];
                            }
                            if (gr1 < N_NODES) {
                                g_x[(size_t)gr1*128 + col]   = o2 + g_gskip[(size_t)gr1*128 + col];
                                g_x[(size_t)gr1*128 + col+1] = o3 + g_gskip[(size_t)gr1*128 + col+1];
                            }
                        } else {
                            unsigned h;
                            h = f2tf32(o0); Xh[r0*XSTR+col]       = h; Xl[r0*XSTR+col]       = f2tf32(o0-__uint_as_float(h));
                            h = f2tf32(o1); Xh[r0*XSTR+col+1]     = h; Xl[r0*XSTR+col+1]     = f2tf32(o1-__uint_as_float(h));
                            h = f2tf32(o2); Xh[(r0+8)*XSTR+col]   = h; Xl[(r0+8)*XSTR+col]   = f2tf32(o2-__uint_as_float(h));
                            h = f2tf32(o3); Xh[(r0+8)*XSTR+col+1] = h; Xl[(r0+8)*XSTR+col+1] = f2tf32(o3-__uint_as_float(h));
                        }
                    }
                }
                if (m == 0) __syncthreads();
            }
        }
    }
}

// ---------------- pooling ----------------------------------------------------
__global__ void init_pool_kernel() {
    int i = blockIdx.x * blockDim.x + threadIdx.x;
    if (i < NUM_GRAPHS * HID) g_pooled[i] = 0.f;
    if (i < NUM_GRAPHS * 4) { g_smax[i] = 0u; g_sden[i] = 0.f; }
}

__global__ void scores_kernel(const int* __restrict__ batch, const float* __restrict__ attn_w,
                              const float* __restrict__ attn_b, const float* __restrict__ temp) {
    int w    = (blockIdx.x * blockDim.x + threadIdx.x) >> 5;
    int lane = threadIdx.x & 31;
    if (w >= N_NODES) return;
    float a[4] = {0.f, 0.f, 0.f, 0.f};
    for (int c = lane; c < HID; c += 32) {
        float xv = g_x[(size_t)w * HID + c];
        a[0] += xv * attn_w[c];
        a[1] += xv * attn_w[128 + c];
        a[2] += xv * attn_w[256 + c];
        a[3] += xv * attn_w[384 + c];
    }
#pragma unroll
    for (int o = 16; o; o >>= 1)
#pragma unroll
        for (int h = 0; h < 4; h++) a[h] += __shfl_down_sync(0xffffffffu, a[h], o);
    if (lane == 0) {
        float invT = 1.f / temp[0];
        int g = batch[w];
#pragma unroll
        for (int h = 0; h < 4; h++) {
            float sc = (a[h] + attn_b[h]) * invT;
            g_scores[w * 4 + h] = sc;
            atomicMax(&g_smax[g * 4 + h], fmap(sc));
        }
    }
}

__global__ void exp_kernel(const int* __restrict__ batch) {
    int i = blockIdx.x * blockDim.x + threadIdx.x;
    if (i >= N_NODES * 4) return;
    int n = i >> 2, h = i & 3;
    int g = batch[n];
    float e = expf(g_scores[i] - funmap(g_smax[g * 4 + h]));
    g_scores[i] = e;
    atomicAdd(&g_sden[g * 4 + h], e);
}

__global__ void pool_kernel(const int* __restrict__ batch) {
    int n = blockIdx.x;
    int c = threadIdx.x;
    int g = batch[n];
    float wbar = 0.f;
#pragma unroll
    for (int h = 0; h < 4; h++) wbar += g_scores[n * 4 + h] / g_sden[g * 4 + h];
    wbar *= 0.25f;
    atomicAdd(&g_pooled[g * HID + c], g_x[(size_t)n * HID + c] * wbar);
}

// ---------------- readout FFN -----------------------------------------------
__global__ void ffn_kernel(const float* __restrict__ w1, const float* __restrict__ b1,
                           const float* __restrict__ w2, const float* __restrict__ b2,
                           const float* __restrict__ w3, const float* __restrict__ b3,
                           float* __restrict__ out) {
    int g = blockIdx.x;
    int t = threadIdx.x;
    __shared__ float p[128], h1[128], red[128];
    p[t] = g_pooled[g * HID + t];
    __syncthreads();
    float acc = b1[t];
#pragma unroll 8
    for (int k = 0; k < 128; k++) acc += p[k] * w1[k * 128 + t];
    h1[t] = silu(acc);
    __syncthreads();
    float acc2 = b2[t];
#pragma unroll 8
    for (int k = 0; k < 128; k++) acc2 += h1[k] * w2[k * 128 + t];
    acc2 = silu(acc2);
    red[t] = acc2 * w3[t];
    __syncthreads();
    for (int s = 64; s > 0; s >>= 1) {
        if (t < s) red[t] += red[t + s];
        __syncthreads();
    }
    if (t == 0) out[g] = red[0] + b3[0];
}

// ---------------- host launcher ---------------------------------------------
extern "C" void kernel_launch(void* const* d_in, const int* in_sizes, int n_in,
                              void* d_out, int out_size) {
    const int* atom  = (const int*)d_in[0];
    const int* hyd   = (const int*)d_in[1];
    const int* deg   = (const int*)d_in[2];
    const int* hyb   = (const int*)d_in[3];
    const int* tgt   = (const int*)d_in[4];
    const int* srcv  = (const int*)d_in[5];
    const int* batch = (const int*)d_in[6];
    const float* emb_atom = (const float*)d_in[7];
    const float* emb_h    = (const float*)d_in[8];
    const float* emb_deg  = (const float*)d_in[9];
    const float* emb_hyb  = (const float*)d_in[10];
    const float* proj_w   = (const float*)d_in[11];
    const float* proj_b   = (const float*)d_in[12];
    const float* in_w     = (const float*)d_in[13];
    const float* in_b     = (const float*)d_in[14];
    const float* mlp_w1   = (const float*)d_in[15];
    const float* mlp_b1   = (const float*)d_in[16];
    const float* mlp_w2   = (const float*)d_in[17];
    const float* mlp_b2   = (const float*)d_in[18];
    const float* skip_w   = (const float*)d_in[19];
    const float* skip_b   = (const float*)d_in[20];
    const float* attn_w   = (const float*)d_in[21];
    const float* attn_b   = (const float*)d_in[22];
    const float* temp     = (const float*)d_in[23];
    const float* ffn_w1   = (const float*)d_in[24];
    const float* ffn_b1   = (const float*)d_in[25];
    const float* ffn_w2   = (const float*)d_in[26];
    const float* ffn_b2   = (const float*)d_in[27];
    const float* ffn_w3   = (const float*)d_in[28];
    const float* ffn_b3   = (const float*)d_in[29];
    float* out = (float*)d_out;

    const int LAYER_SMEM = (2 * 128 * XSTR + 2 * 128 * ASTR + 2 * 256 * ASTR) * 4;  // 196608
    cudaFuncSetAttribute(layer_kernel, cudaFuncAttributeMaxDynamicSharedMemorySize, LAYER_SMEM);

    // 0. CSR build (once per launch; reused by all 3 layers)
    zero_cnt_kernel<<<(NSLOT + 255) / 256, 256>>>();
    count_kernel<<<(N_EDGES + 255) / 256, 256>>>(tgt);
    chunk_sum_kernel<<<NCHUNK, 256>>>();
    scan_chunks_kernel<<<1, 32>>>();
    scan_within_kernel<<<NCHUNK, 1024>>>();
    fill_kernel<<<(N_EDGES + 255) / 256, 256>>>(tgt, srcv);

    // 1. fused embedding + projection
    proj_kernel<<<GEMM_BLKS, 256>>>(atom, hyd, deg, hyb, emb_atom, emb_h, emb_deg, emb_hyb,
                                    proj_w, proj_b);

    // 2. shell conv layers
    for (int l = 0; l < 3; l++) {
        gather_hops_kernel<<<(NSLOT * 32 + 255) / 256, 256>>>();
        layer_kernel<<<GEMM_BLKS, 512, LAYER_SMEM>>>(in_w, in_b, skip_w, skip_b,
                                                     mlp_w1, mlp_b1, mlp_w2, mlp_b2, l);
    }

    // 3. attention pooling
    init_pool_kernel<<<(NUM_GRAPHS * HID + 255) / 256, 256>>>();
    scores_kernel<<<(N_NODES * 32 + 255) / 256, 256>>>(batch, attn_w, attn_b, temp);
    exp_kernel<<<(N_NODES * 4 + 255) / 256, 256>>>(batch);
    pool_kernel<<<N_NODES, 128>>>(batch);

    // 4. readout FFN
    ffn_kernel<<<NUM_GRAPHS, 128>>>(ffn_w1, ffn_b1, ffn_w2, ffn_b2, ffn_w3, ffn_b3, out);
}

// round 5
// speedup vs baseline: 3.2351x; 1.3205x over previous
#include <cuda_runtime.h>

#define N_NODES   50000
#define N_EDGES   2400000
#define NUM_GRAPHS 2048
#define NSLOT     (3 * N_NODES)          // 150000 hop-slots
#define NCHUNK    ((NSLOT + 1023) / 1024) // 147
#define HID       128
#define GEMM_BLKS ((N_NODES + 127) / 128)   // 391
#define ASTR 20    // smem stride for streamed 16-wide k tiles
#define XSTR 132   // smem stride for resident 128-wide split buffers

// ---------------- scratch (static device memory; no allocs) ----------------
__device__ __align__(16) float g_x[N_NODES * HID];
__device__ __align__(16) float g_hops[(size_t)N_NODES * 384];  // 3 hops x 128
__device__ __align__(16) float g_gskip[N_NODES * HID];
__device__ int g_cnt[NSLOT];
__device__ int g_csum[NCHUNK];
__device__ int g_coff[NCHUNK];
__device__ int g_rowptr[NSLOT + 1];
__device__ int g_cursor[NSLOT];
__device__ int g_esrc[N_EDGES];

__device__ __forceinline__ float silu(float v) { return v / (1.f + __expf(-v)); }

__device__ __forceinline__ unsigned f2tf32(float v) {
    unsigned r;
    asm("cvt.rna.tf32.f32 %0, %1;" : "=r"(r) : "f"(v));
    return r;
}

#define MMA_TF32(cc, aa, bb) \
    asm volatile("mma.sync.aligned.m16n8k8.row.col.f32.tf32.tf32.f32 " \
                 "{%0,%1,%2,%3},{%4,%5,%6,%7},{%8,%9},{%0,%1,%2,%3};" \
                 : "+f"(cc[0]), "+f"(cc[1]), "+f"(cc[2]), "+f"(cc[3]) \
                 : "r"(aa[0]), "r"(aa[1]), "r"(aa[2]), "r"(aa[3]), \
                   "r"(bb[0]), "r"(bb[1]))

// ================= CSR build =================
__global__ void zero_cnt_kernel() {
    int i = blockIdx.x * blockDim.x + threadIdx.x;
    if (i < NSLOT) g_cnt[i] = 0;
}
__global__ void count_kernel(const int* __restrict__ tgt) {
    int e = blockIdx.x * blockDim.x + threadIdx.x;
    if (e < N_EDGES) atomicAdd(&g_cnt[tgt[e]], 1);
}
__global__ void chunk_sum_kernel() {
    __shared__ int red[256];
    int b = blockIdx.x, t = threadIdx.x;
    int s = 0;
#pragma unroll
    for (int j = 0; j < 4; j++) {
        int i = b * 1024 + j * 256 + t;
        if (i < NSLOT) s += g_cnt[i];
    }
    red[t] = s; __syncthreads();
    for (int o = 128; o > 0; o >>= 1) {
        if (t < o) red[t] += red[t + o];
        __syncthreads();
    }
    if (t == 0) g_csum[b] = red[0];
}
__global__ void scan_chunks_kernel() {
    __shared__ int buf[2][256];
    int t = threadIdx.x;
    int v = (t < NCHUNK) ? g_csum[t] : 0;
    buf[0][t] = v;
    __syncthreads();
    int cur = 0;
#pragma unroll
    for (int off = 1; off < 256; off <<= 1) {
        int nv = buf[cur][t] + ((t >= off) ? buf[cur][t - off] : 0);
        buf[cur ^ 1][t] = nv;
        cur ^= 1;
        __syncthreads();
    }
    if (t < NCHUNK) g_coff[t] = buf[cur][t] - v;
    if (t == NCHUNK - 1) g_rowptr[NSLOT] = buf[cur][t];
}
__global__ void scan_within_kernel() {
    __shared__ int buf[2][1024];
    int b = blockIdx.x, t = threadIdx.x;
    int i = b * 1024 + t;
    int v = (i < NSLOT) ? g_cnt[i] : 0;
    buf[0][t] = v;
    __syncthreads();
    int cur = 0;
#pragma unroll
    for (int off = 1; off < 1024; off <<= 1) {
        int nv = buf[cur][t] + ((t >= off) ? buf[cur][t - off] : 0);
        buf[cur ^ 1][t] = nv;
        cur ^= 1;
        __syncthreads();
    }
    if (i < NSLOT) {
        int excl = buf[cur][t] - v;
        int rp = g_coff[b] + excl;
        g_rowptr[i] = rp;
        g_cursor[i] = rp;
    }
}
__global__ void fill_kernel(const int* __restrict__ tgt, const int* __restrict__ srcv) {
    int e = blockIdx.x * blockDim.x + threadIdx.x;
    if (e >= N_EDGES) return;
    int t = tgt[e];
    int pos = atomicAdd(&g_cursor[t], 1);
    g_esrc[pos] = srcv[e] % N_NODES;
}

// ================= hop gather: one warp per slot, no atomics =================
__global__ __launch_bounds__(256) void gather_hops_kernel() {
    int slot = (blockIdx.x * blockDim.x + threadIdx.x) >> 5;
    int lane = threadIdx.x & 31;
    if (slot >= NSLOT) return;
    int beg = g_rowptr[slot], end = g_rowptr[slot + 1];
    float4 a0 = make_float4(0.f,0.f,0.f,0.f), a1 = a0, a2 = a0, a3 = a0;
    int e = beg;
    for (; e + 3 < end; e += 4) {
        int s0 = g_esrc[e], s1 = g_esrc[e+1], s2 = g_esrc[e+2], s3 = g_esrc[e+3];
        float4 v0 = *(const float4*)(g_x + (size_t)s0 * HID + lane * 4);
        float4 v1 = *(const float4*)(g_x + (size_t)s1 * HID + lane * 4);
        float4 v2 = *(const float4*)(g_x + (size_t)s2 * HID + lane * 4);
        float4 v3 = *(const float4*)(g_x + (size_t)s3 * HID + lane * 4);
        a0.x+=v0.x; a0.y+=v0.y; a0.z+=v0.z; a0.w+=v0.w;
        a1.x+=v1.x; a1.y+=v1.y; a1.z+=v1.z; a1.w+=v1.w;
        a2.x+=v2.x; a2.y+=v2.y; a2.z+=v2.z; a2.w+=v2.w;
        a3.x+=v3.x; a3.y+=v3.y; a3.z+=v3.z; a3.w+=v3.w;
    }
    for (; e < end; e++) {
        int s0 = g_esrc[e];
        float4 v0 = *(const float4*)(g_x + (size_t)s0 * HID + lane * 4);
        a0.x+=v0.x; a0.y+=v0.y; a0.z+=v0.z; a0.w+=v0.w;
    }
    a0.x += a1.x + a2.x + a3.x;
    a0.y += a1.y + a2.y + a3.y;
    a0.z += a1.z + a2.z + a3.z;
    a0.w += a1.w + a2.w + a3.w;
    int node = slot % N_NODES, hop = slot / N_NODES;
    *(float4*)(g_hops + (size_t)node * 384 + hop * HID + lane * 4) = a0;
}

// ================= fused embed+proj GEMM (A split, B tf32-hi) =================
__global__ __launch_bounds__(256) void proj_kernel(
    const int* __restrict__ atom, const int* __restrict__ hyd,
    const int* __restrict__ deg,  const int* __restrict__ hyb,
    const float* __restrict__ ea, const float* __restrict__ eh,
    const float* __restrict__ ed, const float* __restrict__ ey,
    const float* __restrict__ B, const float* __restrict__ bias) {
    __shared__ unsigned Ah[128 * ASTR], Al[128 * ASTR];
    __shared__ unsigned Bh[128 * ASTR];
    __shared__ int sidx[128][4];

    const int tid  = threadIdx.x;
    const int lane = tid & 31, wid = tid >> 5;
    const int wm = (wid >> 2) * 64;
    const int wn = (wid & 3) * 32;
    const int grp = lane >> 2, tg = lane & 3;
    const int row0 = blockIdx.x * 128;

    if (tid < 128) {
        int gr = row0 + tid;
        int g2 = (gr < N_NODES) ? gr : 0;
        sidx[tid][0] = atom[g2];
        sidx[tid][1] = hyd[g2];
        sidx[tid][2] = deg[g2];
        sidx[tid][3] = hyb[g2];
    }
    __syncthreads();
    const float* tabs[4] = {ea, eh, ed, ey};

    float c[4][4][4];
#pragma unroll
    for (int i = 0; i < 4; i++)
#pragma unroll
        for (int j = 0; j < 4; j++)
#pragma unroll
            for (int q = 0; q < 4; q++) c[i][j][q] = 0.f;

    const int ar  = tid >> 2;
    const int ac4 = (tid & 3) * 4;
    const int bn  = tid & 127;
    const int bk0 = (tid >> 7) * 8;

    for (int k0 = 0; k0 < 256; k0 += 16) {
        float4 av[2]; float bv[8];
        int kt = (k0 + ac4) >> 6, kw = (k0 + ac4) & 63;
#pragma unroll
        for (int it = 0; it < 2; it++) {
            int r = ar + it * 64;
            av[it] = *(const float4*)(tabs[kt] + (size_t)sidx[r][kt] * 64 + kw);
        }
#pragma unroll
        for (int kk = 0; kk < 8; kk++) bv[kk] = B[(size_t)(k0 + bk0 + kk) * 128 + bn];

        __syncthreads();
#pragma unroll
        for (int it = 0; it < 2; it++) {
            int r = ar + it * 64;
            float vv[4] = {av[it].x, av[it].y, av[it].z, av[it].w};
#pragma unroll
            for (int j = 0; j < 4; j++) {
                unsigned h = f2tf32(vv[j]);
                Ah[r * ASTR + ac4 + j] = h;
                Al[r * ASTR + ac4 + j] = f2tf32(vv[j] - __uint_as_float(h));
            }
        }
#pragma unroll
        for (int kk = 0; kk < 8; kk++) Bh[bn * ASTR + bk0 + kk] = f2tf32(bv[kk]);
        __syncthreads();
#pragma unroll
        for (int s = 0; s < 2; s++) {
            const int ks = s * 8;
            unsigned bh[4][2];
#pragma unroll
            for (int nf = 0; nf < 4; nf++) {
                int b0 = (wn + nf * 8 + grp) * ASTR + ks + tg;
                bh[nf][0] = Bh[b0]; bh[nf][1] = Bh[b0 + 4];
            }
#pragma unroll
            for (int mf = 0; mf < 4; mf++) {
                unsigned ah[4], al[4];
                int a0 = (wm + mf * 16 + grp) * ASTR + ks + tg;
                int a1 = a0 + 8 * ASTR;
                ah[0] = Ah[a0]; ah[1] = Ah[a1]; ah[2] = Ah[a0 + 4]; ah[3] = Ah[a1 + 4];
                al[0] = Al[a0]; al[1] = Al[a1]; al[2] = Al[a0 + 4]; al[3] = Al[a1 + 4];
#pragma unroll
                for (int nf = 0; nf < 4; nf++) {
                    MMA_TF32(c[mf][nf], ah, bh[nf]);
                    MMA_TF32(c[mf][nf], al, bh[nf]);
                }
            }
        }
    }

#pragma unroll
    for (int mf = 0; mf < 4; mf++) {
        int r0 = row0 + wm + mf * 16 + grp;
        int r1 = r0 + 8;
#pragma unroll
        for (int nf = 0; nf < 4; nf++) {
            int col = wn + nf * 8 + 2 * tg;
            float bia0 = bias[col], bia1 = bias[col + 1];
            if (r0 < N_NODES) {
                g_x[(size_t)r0 * 128 + col]     = silu(c[mf][nf][0] + bia0);
                g_x[(size_t)r0 * 128 + col + 1] = silu(c[mf][nf][1] + bia1);
            }
            if (r1 < N_NODES) {
                g_x[(size_t)r1 * 128 + col]     = silu(c[mf][nf][2] + bia0);
                g_x[(size_t)r1 * 128 + col + 1] = silu(c[mf][nf][3] + bia1);
            }
        }
    }
}

// ================= mega layer kernel =================
__device__ __forceinline__ const float* feat_ptr(int gr, int k) {
    return (k < 128) ? (g_x + (size_t)gr * 128 + k)
                     : (g_hops + (size_t)gr * 384 + (k - 128));
}

__global__ __launch_bounds__(512, 1) void layer_kernel(
    const float* __restrict__ in_w,   const float* __restrict__ in_b,
    const float* __restrict__ skip_w, const float* __restrict__ skip_b,
    const float* __restrict__ mlp_w1, const float* __restrict__ mlp_b1,
    const float* __restrict__ mlp_w2, const float* __restrict__ mlp_b2,
    int l) {
    extern __shared__ unsigned sm[];
    unsigned* Xh  = sm;
    unsigned* Xl  = Xh  + 128 * XSTR;
    unsigned* Ahs = Xl  + 128 * XSTR;
    unsigned* Als = Ahs + 128 * ASTR;
    unsigned* Bhs = Als + 128 * ASTR;   // 256*ASTR

    const int tid  = threadIdx.x;
    const int lane = tid & 31, wid = tid >> 5;
    const int grp  = lane >> 2, tg = lane & 3;
    const int wm   = (wid >> 3) * 64;
    const int wni  = wid & 7;
    const int row0 = blockIdx.x * 128;

    const float* Win = in_w   + (size_t)l * 512 * 128;
    const float* Wsk = skip_w + (size_t)l * 512 * 128;

    float cA[4][4][4];
#pragma unroll
    for (int i = 0; i < 4; i++)
#pragma unroll
        for (int j = 0; j < 4; j++)
#pragma unroll
            for (int q = 0; q < 4; q++) cA[i][j][q] = 0.f;

    const int ar  = tid >> 2;
    const int ac4 = (tid & 3) * 4;
    const int bn  = tid & 255;
    const int bk0 = (tid >> 8) * 8;
    const float* Wmy = (bn < 128) ? Win : Wsk;
    const int    bcol = bn & 127;

    float4 av; float bv[8];
    {
        int gr = row0 + ar;
        av = (gr < N_NODES) ? *(const float4*)feat_ptr(gr, ac4) : make_float4(0,0,0,0);
#pragma unroll
        for (int kk = 0; kk < 8; kk++) bv[kk] = Wmy[(size_t)(bk0 + kk) * 128 + bcol];
    }

    const int wnA = wni * 32;
    for (int k0 = 0; k0 < 512; k0 += 16) {
        __syncthreads();
        {
            float vv[4] = {av.x, av.y, av.z, av.w};
#pragma unroll
            for (int j = 0; j < 4; j++) {
                unsigned h = f2tf32(vv[j]);
                Ahs[ar * ASTR + ac4 + j] = h;
                Als[ar * ASTR + ac4 + j] = f2tf32(vv[j] - __uint_as_float(h));
            }
#pragma unroll
            for (int kk = 0; kk < 8; kk++) Bhs[bn * ASTR + bk0 + kk] = f2tf32(bv[kk]);
        }
        __syncthreads();
        if (k0 + 16 < 512) {
            int kn = k0 + 16;
            int gr = row0 + ar;
            av = (gr < N_NODES) ? *(const float4*)feat_ptr(gr, kn + ac4) : make_float4(0,0,0,0);
#pragma unroll
            for (int kk = 0; kk < 8; kk++) bv[kk] = Wmy[(size_t)(kn + bk0 + kk) * 128 + bcol];
        }
#pragma unroll
        for (int s = 0; s < 2; s++) {
            const int ks = s * 8;
            unsigned bh[4][2];
#pragma unroll
            for (int nf = 0; nf < 4; nf++) {
                int b0 = (wnA + nf * 8 + grp) * ASTR + ks + tg;
                bh[nf][0] = Bhs[b0]; bh[nf][1] = Bhs[b0 + 4];
            }
#pragma unroll
            for (int mf = 0; mf < 4; mf++) {
                unsigned ah[4], al[4];
                int a0 = (wm + mf * 16 + grp) * ASTR + ks + tg;
                int a1 = a0 + 8 * ASTR;
                ah[0] = Ahs[a0]; ah[1] = Ahs[a1]; ah[2] = Ahs[a0 + 4]; ah[3] = Ahs[a1 + 4];
                al[0] = Als[a0]; al[1] = Als[a1]; al[2] = Als[a0 + 4]; al[3] = Als[a1 + 4];
#pragma unroll
                for (int nf = 0; nf < 4; nf++) {
                    MMA_TF32(cA[mf][nf], ah, bh[nf]);
                    MMA_TF32(cA[mf][nf], al, bh[nf]);
                }
            }
        }
    }
    __syncthreads();

    {
        const float* bias = (wni < 4) ? (in_b + l * 128) : (skip_b + l * 128);
#pragma unroll
        for (int mf = 0; mf < 4; mf++) {
            int r0 = wm + mf * 16 + grp;
#pragma unroll
            for (int nf = 0; nf < 4; nf++) {
                int col = (wni & 3) * 32 + nf * 8 + 2 * tg;
                float b0 = bias[col], b1 = bias[col + 1];
                float v0 = cA[mf][nf][0] + b0, v1 = cA[mf][nf][1] + b1;
                float v2 = cA[mf][nf][2] + b0, v3 = cA[mf][nf][3] + b1;
                if (wni < 4) {
                    v0 = silu(v0); v1 = silu(v1); v2 = silu(v2); v3 = silu(v3);
                    unsigned h;
                    h = f2tf32(v0); Xh[r0*XSTR + col]       = h; Xl[r0*XSTR + col]       = f2tf32(v0 - __uint_as_float(h));
                    h = f2tf32(v1); Xh[r0*XSTR + col + 1]   = h; Xl[r0*XSTR + col + 1]   = f2tf32(v1 - __uint_as_float(h));
                    h = f2tf32(v2); Xh[(r0+8)*XSTR + col]   = h; Xl[(r0+8)*XSTR + col]   = f2tf32(v2 - __uint_as_float(h));
                    h = f2tf32(v3); Xh[(r0+8)*XSTR + col+1] = h; Xl[(r0+8)*XSTR + col+1] = f2tf32(v3 - __uint_as_float(h));
                } else {
                    int gr0 = row0 + r0, gr1 = gr0 + 8;
                    if (gr0 < N_NODES) { g_gskip[(size_t)gr0*128 + col] = v0; g_gskip[(size_t)gr0*128 + col+1] = v1; }
                    if (gr1 < N_NODES) { g_gskip[(size_t)gr1*128 + col] = v2; g_gskip[(size_t)gr1*128 + col+1] = v3; }
                }
            }
        }
    }
    __syncthreads();

    const int wnM  = wni * 16;
    const int bn2  = tid & 127;
    const int kb2  = (tid >> 7) * 4;

    for (int m = 0; m < 2; m++) {
        const float* B1 = mlp_b1 + (l * 2 + m) * 128;
        const float* B2 = mlp_b2 + (l * 2 + m) * 128;

        for (int phase = 0; phase < 2; phase++) {
            const float* W = (phase ? mlp_w2 : mlp_w1) + (size_t)(l * 2 + m) * 16384;
            float cT[4][2][4];
#pragma unroll
            for (int i = 0; i < 4; i++)
#pragma unroll
                for (int j = 0; j < 2; j++)
#pragma unroll
                    for (int q = 0; q < 4; q++) cT[i][j][q] = 0.f;

            float bv2[4];
#pragma unroll
            for (int kk = 0; kk < 4; kk++) bv2[kk] = W[(size_t)(kb2 + kk) * 128 + bn2];

            for (int k0 = 0; k0 < 128; k0 += 16) {
                __syncthreads();
#pragma unroll
                for (int kk = 0; kk < 4; kk++) Bhs[bn2 * ASTR + kb2 + kk] = f2tf32(bv2[kk]);
                __syncthreads();
                if (k0 + 16 < 128) {
                    int kn = k0 + 16;
#pragma unroll
                    for (int kk = 0; kk < 4; kk++) bv2[kk] = W[(size_t)(kn + kb2 + kk) * 128 + bn2];
                }
#pragma unroll
                for (int s = 0; s < 2; s++) {
                    const int ks = s * 8;
                    unsigned bh[2][2];
#pragma unroll
                    for (int nf = 0; nf < 2; nf++) {
                        int b0 = (wnM + nf * 8 + grp) * ASTR + ks + tg;
                        bh[nf][0] = Bhs[b0]; bh[nf][1] = Bhs[b0 + 4];
                    }
#pragma unroll
                    for (int mf = 0; mf < 4; mf++) {
                        unsigned ah[4], al[4];
                        int a0 = (wm + mf * 16 + grp) * XSTR + k0 + ks + tg;
                        int a1 = a0 + 8 * XSTR;
                        ah[0] = Xh[a0]; ah[1] = Xh[a1]; ah[2] = Xh[a0 + 4]; ah[3] = Xh[a1 + 4];
                        al[0] = Xl[a0]; al[1] = Xl[a1]; al[2] = Xl[a0 + 4]; al[3] = Xl[a1 + 4];
#pragma unroll
                        for (int nf = 0; nf < 2; nf++) {
                            MMA_TF32(cT[mf][nf], ah, bh[nf]);
                            MMA_TF32(cT[mf][nf], al, bh[nf]);
                        }
                    }
                }
            }

            if (phase == 0) {
                float res[4][2][4];
#pragma unroll
                for (int mf = 0; mf < 4; mf++) {
                    int r0 = wm + mf * 16 + grp;
#pragma unroll
                    for (int nf = 0; nf < 2; nf++) {
                        int col = wnM + nf * 8 + 2 * tg;
                        res[mf][nf][0] = __uint_as_float(Xh[r0*XSTR + col])       + __uint_as_float(Xl[r0*XSTR + col]);
                        res[mf][nf][1] = __uint_as_float(Xh[r0*XSTR + col + 1])   + __uint_as_float(Xl[r0*XSTR + col + 1]);
                        res[mf][nf][2] = __uint_as_float(Xh[(r0+8)*XSTR + col])   + __uint_as_float(Xl[(r0+8)*XSTR + col]);
                        res[mf][nf][3] = __uint_as_float(Xh[(r0+8)*XSTR + col+1]) + __uint_as_float(Xl[(r0+8)*XSTR + col+1]);
                        cT[mf][nf][0] = silu(cT[mf][nf][0] + B1[col]);
                        cT[mf][nf][1] = silu(cT[mf][nf][1] + B1[col + 1]);
                        cT[mf][nf][2] = silu(cT[mf][nf][2] + B1[col]);
                        cT[mf][nf][3] = silu(cT[mf][nf][3] + B1[col + 1]);
                    }
                }
                __syncthreads();
#pragma unroll
                for (int mf = 0; mf < 4; mf++) {
                    int r0 = wm + mf * 16 + grp;
#pragma unroll
                    for (int nf = 0; nf < 2; nf++) {
                        int col = wnM + nf * 8 + 2 * tg;
                        unsigned h;
                        h = f2tf32(cT[mf][nf][0]); Xh[r0*XSTR+col]       = h; Xl[r0*XSTR+col]       = f2tf32(cT[mf][nf][0]-__uint_as_float(h));
                        h = f2tf32(cT[mf][nf][1]); Xh[r0*XSTR+col+1]     = h; Xl[r0*XSTR+col+1]     = f2tf32(cT[mf][nf][1]-__uint_as_float(h));
                        h = f2tf32(cT[mf][nf][2]); Xh[(r0+8)*XSTR+col]   = h; Xl[(r0+8)*XSTR+col]   = f2tf32(cT[mf][nf][2]-__uint_as_float(h));
                        h = f2tf32(cT[mf][nf][3]); Xh[(r0+8)*XSTR+col+1] = h; Xl[(r0+8)*XSTR+col+1] = f2tf32(cT[mf][nf][3]-__uint_as_float(h));
                        cA[mf][nf][0] = res[mf][nf][0]; cA[mf][nf][1] = res[mf][nf][1];
                        cA[mf][nf][2] = res[mf][nf][2]; cA[mf][nf][3] = res[mf][nf][3];
                    }
                }
                __syncthreads();
            } else {
                if (m == 0) __syncthreads();
#pragma unroll
                for (int mf = 0; mf < 4; mf++) {
                    int r0 = wm + mf * 16 + grp;
#pragma unroll
                    for (int nf = 0; nf < 2; nf++) {
                        int col = wnM + nf * 8 + 2 * tg;
                        float o0 = cT[mf][nf][0] + B2[col]     + cA[mf][nf][0];
                        float o1 = cT[mf][nf][1] + B2[col + 1] + cA[mf][nf][1];
                        float o2 = cT[mf][nf][2] + B2[col]     + cA[mf][nf][2];
                        float o3 = cT[mf][nf][3] + B2[col + 1] + cA[mf][nf][3];
                        if (m == 1) {
                            int gr0 = row0 + r0, gr1 = gr0 + 8;
                            if (gr0 < N_NODES) {
                                g_x[(size_t)gr0*128 + col]   = o0 + g_gskip[(size_t)gr0*128 + col];
                                g_x[(size_t)gr0*128 + col+1] = o1 + g_gskip[(size_t)gr0*128 + col+1];
                            }
                            if (gr1 < N_NODES) {
                                g_x[(size_t)gr1*128 + col]   = o2 + g_gskip[(size_t)gr1*128 + col];
                                g_x[(size_t)gr1*128 + col+1] = o3 + g_gskip[(size_t)gr1*128 + col+1];
                            }
                        } else {
                            unsigned h;
                            h = f2tf32(o0); Xh[r0*XSTR+col]       = h; Xl[r0*XSTR+col]       = f2tf32(o0-__uint_as_float(h));
                            h = f2tf32(o1); Xh[r0*XSTR+col+1]     = h; Xl[r0*XSTR+col+1]     = f2tf32(o1-__uint_as_float(h));
                            h = f2tf32(o2); Xh[(r0+8)*XSTR+col]   = h; Xl[(r0+8)*XSTR+col]   = f2tf32(o2-__uint_as_float(h));
                            h = f2tf32(o3); Xh[(r0+8)*XSTR+col+1] = h; Xl[(r0+8)*XSTR+col+1] = f2tf32(o3-__uint_as_float(h));
                        }
                    }
                }
                if (m == 0) __syncthreads();
            }
        }
    }
}

// ================= fused pooling + FFN: one block per graph =================
// batch_indices is sorted -> binary search node range; online softmax per head.
__global__ __launch_bounds__(128) void pool_ffn_kernel(
    const int* __restrict__ batch,
    const float* __restrict__ attn_w, const float* __restrict__ attn_b,
    const float* __restrict__ temp,
    const float* __restrict__ w1, const float* __restrict__ b1,
    const float* __restrict__ w2, const float* __restrict__ b2,
    const float* __restrict__ w3, const float* __restrict__ b3,
    float* __restrict__ out) {
    const int g = blockIdx.x, t = threadIdx.x;
    const int lane = t & 31, wrp = t >> 5;
    __shared__ int sbeg, send;
    __shared__ float aw[512];
    __shared__ float P[4][128];
    __shared__ float ex[128][4];
    __shared__ float m[4], s[4], rs[4];
    __shared__ float wred[4][4];
    __shared__ float p[128], h1[128], red[128];

    if (t == 0) {
        int lo = 0, hi = N_NODES;
        while (lo < hi) { int mid = (lo + hi) >> 1; if (batch[mid] < g) lo = mid + 1; else hi = mid; }
        sbeg = lo;
        hi = N_NODES;
        while (lo < hi) { int mid = (lo + hi) >> 1; if (batch[mid] < g + 1) lo = mid + 1; else hi = mid; }
        send = lo;
    }
    aw[t] = attn_w[t]; aw[128 + t] = attn_w[128 + t];
    aw[256 + t] = attn_w[256 + t]; aw[384 + t] = attn_w[384 + t];
    if (t < 4) { m[t] = -1e30f; s[t] = 0.f; }
    P[0][t] = 0.f; P[1][t] = 0.f; P[2][t] = 0.f; P[3][t] = 0.f;
    __syncthreads();
    const int beg = sbeg, end = send;
    const float invT = 1.f / temp[0];

    for (int c0 = beg; c0 < end; c0 += 128) {
        int idx = c0 + t;
        bool active = idx < end;
        float sc[4] = {-1e30f, -1e30f, -1e30f, -1e30f};
        if (active) {
            const float* xr = g_x + (size_t)idx * HID;
            float a0 = 0.f, a1 = 0.f, a2 = 0.f, a3 = 0.f;
#pragma unroll 8
            for (int k = 0; k < 128; k += 4) {
                float4 xv = *(const float4*)(xr + k);
                a0 += xv.x*aw[k]     + xv.y*aw[k+1]     + xv.z*aw[k+2]     + xv.w*aw[k+3];
                a1 += xv.x*aw[128+k] + xv.y*aw[128+k+1] + xv.z*aw[128+k+2] + xv.w*aw[128+k+3];
                a2 += xv.x*aw[256+k] + xv.y*aw[256+k+1] + xv.z*aw[256+k+2] + xv.w*aw[256+k+3];
                a3 += xv.x*aw[384+k] + xv.y*aw[384+k+1] + xv.z*aw[384+k+2] + xv.w*aw[384+k+3];
            }
            sc[0] = (a0 + attn_b[0]) * invT;
            sc[1] = (a1 + attn_b[1]) * invT;
            sc[2] = (a2 + attn_b[2]) * invT;
            sc[3] = (a3 + attn_b[3]) * invT;
        }
        // per-head block max
        float mx[4] = {sc[0], sc[1], sc[2], sc[3]};
#pragma unroll
        for (int o = 16; o; o >>= 1)
#pragma unroll
            for (int h = 0; h < 4; h++) mx[h] = fmaxf(mx[h], __shfl_xor_sync(0xffffffffu, mx[h], o));
        if (lane == 0)
#pragma unroll
            for (int h = 0; h < 4; h++) wred[wrp][h] = mx[h];
        __syncthreads();
        if (t < 4) {
            float cm = fmaxf(fmaxf(wred[0][t], wred[1][t]), fmaxf(wred[2][t], wred[3][t]));
            float nm = fmaxf(m[t], cm);
            rs[t] = __expf(m[t] - nm);
            m[t] = nm;
            s[t] *= rs[t];
        }
        __syncthreads();
        float e[4];
#pragma unroll
        for (int h = 0; h < 4; h++) {
            e[h] = active ? __expf(sc[h] - m[h]) : 0.f;
            ex[t][h] = e[h];
        }
        float sm2[4] = {e[0], e[1], e[2], e[3]};
#pragma unroll
        for (int o = 16; o; o >>= 1)
#pragma unroll
            for (int h = 0; h < 4; h++) sm2[h] += __shfl_xor_sync(0xffffffffu, sm2[h], o);
        if (lane == 0)
#pragma unroll
            for (int h = 0; h < 4; h++) wred[wrp][h] = sm2[h];
        __syncthreads();
        if (t < 4) s[t] += wred[0][t] + wred[1][t] + wred[2][t] + wred[3][t];

        // pooled accumulation: thread t = dim t
        int cnt = min(128, end - c0);
        float p0 = P[0][t] * rs[0], p1 = P[1][t] * rs[1];
        float p2 = P[2][t] * rs[2], p3 = P[3][t] * rs[3];
        for (int n = 0; n < cnt; n++) {
            float xv = g_x[(size_t)(c0 + n) * HID + t];
            p0 += ex[n][0] * xv;
            p1 += ex[n][1] * xv;
            p2 += ex[n][2] * xv;
            p3 += ex[n][3] * xv;
        }
        P[0][t] = p0; P[1][t] = p1; P[2][t] = p2; P[3][t] = p3;
        __syncthreads();
    }

    // head mean
    float pooled = 0.f;
#pragma unroll
    for (int h = 0; h < 4; h++) if (s[h] > 0.f) pooled += P[h][t] / s[h];
    p[t] = pooled * 0.25f;
    __syncthreads();

    // FFN
    float acc = b1[t];
#pragma unroll 8
    for (int k = 0; k < 128; k++) acc += p[k] * w1[k * 128 + t];
    h1[t] = silu(acc);
    __syncthreads();
    float acc2 = b2[t];
#pragma unroll 8
    for (int k = 0; k < 128; k++) acc2 += h1[k] * w2[k * 128 + t];
    acc2 = silu(acc2);
    red[t] = acc2 * w3[t];
    __syncthreads();
    for (int o = 64; o > 0; o >>= 1) {
        if (t < o) red[t] += red[t + o];
        __syncthreads();
    }
    if (t == 0) out[g] = red[0] + b3[0];
}

// ---------------- host launcher ---------------------------------------------
extern "C" void kernel_launch(void* const* d_in, const int* in_sizes, int n_in,
                              void* d_out, int out_size) {
    const int* atom  = (const int*)d_in[0];
    const int* hyd   = (const int*)d_in[1];
    const int* deg   = (const int*)d_in[2];
    const int* hyb   = (const int*)d_in[3];
    const int* tgt   = (const int*)d_in[4];
    const int* srcv  = (const int*)d_in[5];
    const int* batch = (const int*)d_in[6];
    const float* emb_atom = (const float*)d_in[7];
    const float* emb_h    = (const float*)d_in[8];
    const float* emb_deg  = (const float*)d_in[9];
    const float* emb_hyb  = (const float*)d_in[10];
    const float* proj_w   = (const float*)d_in[11];
    const float* proj_b   = (const float*)d_in[12];
    const float* in_w     = (const float*)d_in[13];
    const float* in_b     = (const float*)d_in[14];
    const float* mlp_w1   = (const float*)d_in[15];
    const float* mlp_b1   = (const float*)d_in[16];
    const float* mlp_w2   = (const float*)d_in[17];
    const float* mlp_b2   = (const float*)d_in[18];
    const float* skip_w   = (const float*)d_in[19];
    const float* skip_b   = (const float*)d_in[20];
    const float* attn_w   = (const float*)d_in[21];
    const float* attn_b   = (const float*)d_in[22];
    const float* temp     = (const float*)d_in[23];
    const float* ffn_w1   = (const float*)d_in[24];
    const float* ffn_b1   = (const float*)d_in[25];
    const float* ffn_w2   = (const float*)d_in[26];
    const float* ffn_b2   = (const float*)d_in[27];
    const float* ffn_w3   = (const float*)d_in[28];
    const float* ffn_b3   = (const float*)d_in[29];
    float* out = (float*)d_out;

    const int LAYER_SMEM = (2 * 128 * XSTR + 2 * 128 * ASTR + 256 * ASTR) * 4;  // 176128
    cudaFuncSetAttribute(layer_kernel, cudaFuncAttributeMaxDynamicSharedMemorySize, LAYER_SMEM);

    // 0. CSR build (once; reused by all 3 layers)
    zero_cnt_kernel<<<(NSLOT + 255) / 256, 256>>>();
    count_kernel<<<(N_EDGES + 255) / 256, 256>>>(tgt);
    chunk_sum_kernel<<<NCHUNK, 256>>>();
    scan_chunks_kernel<<<1, 256>>>();
    scan_within_kernel<<<NCHUNK, 1024>>>();
    fill_kernel<<<(N_EDGES + 255) / 256, 256>>>(tgt, srcv);

    // 1. fused embedding + projection
    proj_kernel<<<GEMM_BLKS, 256>>>(atom, hyd, deg, hyb, emb_atom, emb_h, emb_deg, emb_hyb,
                                    proj_w, proj_b);

    // 2. shell conv layers
    for (int l = 0; l < 3; l++) {
        gather_hops_kernel<<<(NSLOT * 32 + 255) / 256, 256>>>();
        layer_kernel<<<GEMM_BLKS, 512, LAYER_SMEM>>>(in_w, in_b, skip_w, skip_b,
                                                     mlp_w1, mlp_b1, mlp_w2, mlp_b2, l);
    }

    // 3. fused attention pooling + FFN readout
    pool_ffn_kernel<<<NUM_GRAPHS, 128>>>(batch, attn_w, attn_b, temp,
                                         ffn_w1, ffn_b1, ffn_w2, ffn_b2, ffn_w3, ffn_b3, out);
}

// round 6
// speedup vs baseline: 4.2328x; 1.3084x over previous
#include <cuda_runtime.h>

#define N_NODES   50000
#define N_EDGES   2400000
#define NUM_GRAPHS 2048
#define NSLOT     (3 * N_NODES)          // 150000 hop-slots
#define NCHUNK    ((NSLOT + 1023) / 1024) // 147
#define HID       128
#define GEMM_BLKS ((N_NODES + 127) / 128)   // 391
#define ASTR 20    // smem stride for streamed 16-wide k tiles
#define XSTR 132   // smem stride for resident 128-wide buffers

// ---------------- scratch (static device memory; no allocs) ----------------
__device__ __align__(16) float g_x[N_NODES * HID];
__device__ __align__(16) float g_hops[(size_t)N_NODES * 384];  // 3 hops x 128
__device__ __align__(16) float g_gskip[N_NODES * HID];
__device__ int g_cnt[NSLOT];
__device__ int g_csum[NCHUNK];
__device__ int g_coff[NCHUNK];
__device__ int g_rowptr[NSLOT + 1];
__device__ int g_cursor[NSLOT];
__device__ int g_esrc[N_EDGES];

__device__ __forceinline__ float silu(float v) { return v / (1.f + __expf(-v)); }

__device__ __forceinline__ unsigned f2tf32(float v) {
    unsigned r;
    asm("cvt.rna.tf32.f32 %0, %1;" : "=r"(r) : "f"(v));
    return r;
}

#define MMA_TF32(cc, aa, bb) \
    asm volatile("mma.sync.aligned.m16n8k8.row.col.f32.tf32.tf32.f32 " \
                 "{%0,%1,%2,%3},{%4,%5,%6,%7},{%8,%9},{%0,%1,%2,%3};" \
                 : "+f"(cc[0]), "+f"(cc[1]), "+f"(cc[2]), "+f"(cc[3]) \
                 : "r"(aa[0]), "r"(aa[1]), "r"(aa[2]), "r"(aa[3]), \
                   "r"(bb[0]), "r"(bb[1]))

// ================= CSR build =================
__global__ void zero_cnt_kernel() {
    int i = blockIdx.x * blockDim.x + threadIdx.x;
    if (i < NSLOT) g_cnt[i] = 0;
}
__global__ void count_kernel(const int* __restrict__ tgt) {
    int e = blockIdx.x * blockDim.x + threadIdx.x;
    if (e < N_EDGES) atomicAdd(&g_cnt[tgt[e]], 1);
}
__global__ void chunk_sum_kernel() {
    __shared__ int red[256];
    int b = blockIdx.x, t = threadIdx.x;
    int s = 0;
#pragma unroll
    for (int j = 0; j < 4; j++) {
        int i = b * 1024 + j * 256 + t;
        if (i < NSLOT) s += g_cnt[i];
    }
    red[t] = s; __syncthreads();
    for (int o = 128; o > 0; o >>= 1) {
        if (t < o) red[t] += red[t + o];
        __syncthreads();
    }
    if (t == 0) g_csum[b] = red[0];
}
__global__ void scan_chunks_kernel() {
    __shared__ int buf[2][256];
    int t = threadIdx.x;
    int v = (t < NCHUNK) ? g_csum[t] : 0;
    buf[0][t] = v;
    __syncthreads();
    int cur = 0;
#pragma unroll
    for (int off = 1; off < 256; off <<= 1) {
        int nv = buf[cur][t] + ((t >= off) ? buf[cur][t - off] : 0);
        buf[cur ^ 1][t] = nv;
        cur ^= 1;
        __syncthreads();
    }
    if (t < NCHUNK) g_coff[t] = buf[cur][t] - v;
    if (t == NCHUNK - 1) g_rowptr[NSLOT] = buf[cur][t];
}
__global__ void scan_within_kernel() {
    __shared__ int buf[2][1024];
    int b = blockIdx.x, t = threadIdx.x;
    int i = b * 1024 + t;
    int v = (i < NSLOT) ? g_cnt[i] : 0;
    buf[0][t] = v;
    __syncthreads();
    int cur = 0;
#pragma unroll
    for (int off = 1; off < 1024; off <<= 1) {
        int nv = buf[cur][t] + ((t >= off) ? buf[cur][t - off] : 0);
        buf[cur ^ 1][t] = nv;
        cur ^= 1;
        __syncthreads();
    }
    if (i < NSLOT) {
        int excl = buf[cur][t] - v;
        int rp = g_coff[b] + excl;
        g_rowptr[i] = rp;
        g_cursor[i] = rp;
    }
}
__global__ void fill_kernel(const int* __restrict__ tgt, const int* __restrict__ srcv) {
    int e = blockIdx.x * blockDim.x + threadIdx.x;
    if (e >= N_EDGES) return;
    int t = tgt[e];
    int pos = atomicAdd(&g_cursor[t], 1);
    g_esrc[pos] = srcv[e] % N_NODES;
}

// ================= hop gather: one warp per slot, no atomics =================
__global__ __launch_bounds__(256) void gather_hops_kernel() {
    int slot = (blockIdx.x * blockDim.x + threadIdx.x) >> 5;
    int lane = threadIdx.x & 31;
    if (slot >= NSLOT) return;
    int beg = g_rowptr[slot], end = g_rowptr[slot + 1];
    float4 a0 = make_float4(0.f,0.f,0.f,0.f), a1 = a0, a2 = a0, a3 = a0;
    int e = beg;
    for (; e + 3 < end; e += 4) {
        int s0 = g_esrc[e], s1 = g_esrc[e+1], s2 = g_esrc[e+2], s3 = g_esrc[e+3];
        float4 v0 = *(const float4*)(g_x + (size_t)s0 * HID + lane * 4);
        float4 v1 = *(const float4*)(g_x + (size_t)s1 * HID + lane * 4);
        float4 v2 = *(const float4*)(g_x + (size_t)s2 * HID + lane * 4);
        float4 v3 = *(const float4*)(g_x + (size_t)s3 * HID + lane * 4);
        a0.x+=v0.x; a0.y+=v0.y; a0.z+=v0.z; a0.w+=v0.w;
        a1.x+=v1.x; a1.y+=v1.y; a1.z+=v1.z; a1.w+=v1.w;
        a2.x+=v2.x; a2.y+=v2.y; a2.z+=v2.z; a2.w+=v2.w;
        a3.x+=v3.x; a3.y+=v3.y; a3.z+=v3.z; a3.w+=v3.w;
    }
    for (; e < end; e++) {
        int s0 = g_esrc[e];
        float4 v0 = *(const float4*)(g_x + (size_t)s0 * HID + lane * 4);
        a0.x+=v0.x; a0.y+=v0.y; a0.z+=v0.z; a0.w+=v0.w;
    }
    a0.x += a1.x + a2.x + a3.x;
    a0.y += a1.y + a2.y + a3.y;
    a0.z += a1.z + a2.z + a3.z;
    a0.w += a1.w + a2.w + a3.w;
    int node = slot % N_NODES, hop = slot / N_NODES;
    *(float4*)(g_hops + (size_t)node * 384 + hop * HID + lane * 4) = a0;
}

// ================= fused embed+proj GEMM (single-pass tf32) =================
__global__ __launch_bounds__(256) void proj_kernel(
    const int* __restrict__ atom, const int* __restrict__ hyd,
    const int* __restrict__ deg,  const int* __restrict__ hyb,
    const float* __restrict__ ea, const float* __restrict__ eh,
    const float* __restrict__ ed, const float* __restrict__ ey,
    const float* __restrict__ B, const float* __restrict__ bias) {
    __shared__ unsigned Ah[128 * ASTR];
    __shared__ unsigned Bh[128 * ASTR];
    __shared__ int sidx[128][4];

    const int tid  = threadIdx.x;
    const int lane = tid & 31, wid = tid >> 5;
    const int wm = (wid >> 2) * 64;
    const int wn = (wid & 3) * 32;
    const int grp = lane >> 2, tg = lane & 3;
    const int row0 = blockIdx.x * 128;

    if (tid < 128) {
        int gr = row0 + tid;
        int g2 = (gr < N_NODES) ? gr : 0;
        sidx[tid][0] = atom[g2];
        sidx[tid][1] = hyd[g2];
        sidx[tid][2] = deg[g2];
        sidx[tid][3] = hyb[g2];
    }
    __syncthreads();
    const float* tabs[4] = {ea, eh, ed, ey};

    float c[4][4][4];
#pragma unroll
    for (int i = 0; i < 4; i++)
#pragma unroll
        for (int j = 0; j < 4; j++)
#pragma unroll
            for (int q = 0; q < 4; q++) c[i][j][q] = 0.f;

    const int ar  = tid >> 2;
    const int ac4 = (tid & 3) * 4;
    const int bn  = tid & 127;
    const int bk0 = (tid >> 7) * 8;

    for (int k0 = 0; k0 < 256; k0 += 16) {
        float4 av[2]; float bv[8];
        int kt = (k0 + ac4) >> 6, kw = (k0 + ac4) & 63;
#pragma unroll
        for (int it = 0; it < 2; it++) {
            int r = ar + it * 64;
            av[it] = *(const float4*)(tabs[kt] + (size_t)sidx[r][kt] * 64 + kw);
        }
#pragma unroll
        for (int kk = 0; kk < 8; kk++) bv[kk] = B[(size_t)(k0 + bk0 + kk) * 128 + bn];

        __syncthreads();
#pragma unroll
        for (int it = 0; it < 2; it++) {
            int r = ar + it * 64;
            float vv[4] = {av[it].x, av[it].y, av[it].z, av[it].w};
#pragma unroll
            for (int j = 0; j < 4; j++) Ah[r * ASTR + ac4 + j] = f2tf32(vv[j]);
        }
#pragma unroll
        for (int kk = 0; kk < 8; kk++) Bh[bn * ASTR + bk0 + kk] = f2tf32(bv[kk]);
        __syncthreads();
#pragma unroll
        for (int s = 0; s < 2; s++) {
            const int ks = s * 8;
            unsigned bh[4][2];
#pragma unroll
            for (int nf = 0; nf < 4; nf++) {
                int b0 = (wn + nf * 8 + grp) * ASTR + ks + tg;
                bh[nf][0] = Bh[b0]; bh[nf][1] = Bh[b0 + 4];
            }
#pragma unroll
            for (int mf = 0; mf < 4; mf++) {
                unsigned ah[4];
                int a0 = (wm + mf * 16 + grp) * ASTR + ks + tg;
                int a1 = a0 + 8 * ASTR;
                ah[0] = Ah[a0]; ah[1] = Ah[a1]; ah[2] = Ah[a0 + 4]; ah[3] = Ah[a1 + 4];
#pragma unroll
                for (int nf = 0; nf < 4; nf++) MMA_TF32(c[mf][nf], ah, bh[nf]);
            }
        }
    }

#pragma unroll
    for (int mf = 0; mf < 4; mf++) {
        int r0 = row0 + wm + mf * 16 + grp;
        int r1 = r0 + 8;
#pragma unroll
        for (int nf = 0; nf < 4; nf++) {
            int col = wn + nf * 8 + 2 * tg;
            float bia0 = bias[col], bia1 = bias[col + 1];
            if (r0 < N_NODES) {
                g_x[(size_t)r0 * 128 + col]     = silu(c[mf][nf][0] + bia0);
                g_x[(size_t)r0 * 128 + col + 1] = silu(c[mf][nf][1] + bia1);
            }
            if (r1 < N_NODES) {
                g_x[(size_t)r1 * 128 + col]     = silu(c[mf][nf][2] + bia0);
                g_x[(size_t)r1 * 128 + col + 1] = silu(c[mf][nf][3] + bia1);
            }
        }
    }
}

// ================= mega layer kernel (single-pass tf32, fp32 state) =========
__device__ __forceinline__ const float* feat_ptr(int gr, int k) {
    return (k < 128) ? (g_x + (size_t)gr * 128 + k)
                     : (g_hops + (size_t)gr * 384 + (k - 128));
}

__global__ __launch_bounds__(512, 1) void layer_kernel(
    const float* __restrict__ in_w,   const float* __restrict__ in_b,
    const float* __restrict__ skip_w, const float* __restrict__ skip_b,
    const float* __restrict__ mlp_w1, const float* __restrict__ mlp_b1,
    const float* __restrict__ mlp_w2, const float* __restrict__ mlp_b2,
    int l) {
    extern __shared__ unsigned sm[];
    float*    Xf  = (float*)sm;            // 128*XSTR fp32 state (residuals)
    unsigned* Xh  = sm  + 128 * XSTR;      // 128*XSTR tf32 mirror (MMA A-operand)
    unsigned* Ahs = Xh  + 128 * XSTR;      // 128*ASTR streamed A chunks
    unsigned* Bhs = Ahs + 128 * ASTR;      // 256*ASTR streamed B chunks

    const int tid  = threadIdx.x;
    const int lane = tid & 31, wid = tid >> 5;
    const int grp  = lane >> 2, tg = lane & 3;
    const int wm   = (wid >> 3) * 64;
    const int wni  = wid & 7;
    const int row0 = blockIdx.x * 128;

    const float* Win = in_w   + (size_t)l * 512 * 128;
    const float* Wsk = skip_w + (size_t)l * 512 * 128;

    float cA[4][4][4];
#pragma unroll
    for (int i = 0; i < 4; i++)
#pragma unroll
        for (int j = 0; j < 4; j++)
#pragma unroll
            for (int q = 0; q < 4; q++) cA[i][j][q] = 0.f;

    const int ar  = tid >> 2;
    const int ac4 = (tid & 3) * 4;
    const int bn  = tid & 255;
    const int bk0 = (tid >> 8) * 8;
    const float* Wmy = (bn < 128) ? Win : Wsk;
    const int    bcol = bn & 127;

    float4 av; float bv[8];
    {
        int gr = row0 + ar;
        av = (gr < N_NODES) ? *(const float4*)feat_ptr(gr, ac4) : make_float4(0,0,0,0);
#pragma unroll
        for (int kk = 0; kk < 8; kk++) bv[kk] = Wmy[(size_t)(bk0 + kk) * 128 + bcol];
    }

    const int wnA = wni * 32;
    for (int k0 = 0; k0 < 512; k0 += 16) {
        __syncthreads();
        {
            float vv[4] = {av.x, av.y, av.z, av.w};
#pragma unroll
            for (int j = 0; j < 4; j++) Ahs[ar * ASTR + ac4 + j] = f2tf32(vv[j]);
#pragma unroll
            for (int kk = 0; kk < 8; kk++) Bhs[bn * ASTR + bk0 + kk] = f2tf32(bv[kk]);
        }
        __syncthreads();
        if (k0 + 16 < 512) {
            int kn = k0 + 16;
            int gr = row0 + ar;
            av = (gr < N_NODES) ? *(const float4*)feat_ptr(gr, kn + ac4) : make_float4(0,0,0,0);
#pragma unroll
            for (int kk = 0; kk < 8; kk++) bv[kk] = Wmy[(size_t)(kn + bk0 + kk) * 128 + bcol];
        }
#pragma unroll
        for (int s = 0; s < 2; s++) {
            const int ks = s * 8;
            unsigned bh[4][2];
#pragma unroll
            for (int nf = 0; nf < 4; nf++) {
                int b0 = (wnA + nf * 8 + grp) * ASTR + ks + tg;
                bh[nf][0] = Bhs[b0]; bh[nf][1] = Bhs[b0 + 4];
            }
#pragma unroll
            for (int mf = 0; mf < 4; mf++) {
                unsigned ah[4];
                int a0 = (wm + mf * 16 + grp) * ASTR + ks + tg;
                int a1 = a0 + 8 * ASTR;
                ah[0] = Ahs[a0]; ah[1] = Ahs[a1]; ah[2] = Ahs[a0 + 4]; ah[3] = Ahs[a1 + 4];
#pragma unroll
                for (int nf = 0; nf < 4; nf++) MMA_TF32(cA[mf][nf], ah, bh[nf]);
            }
        }
    }
    __syncthreads();

    // phase A epilogue: wni<4 -> h (silu) into Xf/Xh; wni>=4 -> gskip to global
    {
        const float* bias = (wni < 4) ? (in_b + l * 128) : (skip_b + l * 128);
#pragma unroll
        for (int mf = 0; mf < 4; mf++) {
            int r0 = wm + mf * 16 + grp;
#pragma unroll
            for (int nf = 0; nf < 4; nf++) {
                int col = (wni & 3) * 32 + nf * 8 + 2 * tg;
                float b0 = bias[col], b1 = bias[col + 1];
                float v0 = cA[mf][nf][0] + b0, v1 = cA[mf][nf][1] + b1;
                float v2 = cA[mf][nf][2] + b0, v3 = cA[mf][nf][3] + b1;
                if (wni < 4) {
                    v0 = silu(v0); v1 = silu(v1); v2 = silu(v2); v3 = silu(v3);
                    Xf[r0*XSTR + col]       = v0; Xh[r0*XSTR + col]       = f2tf32(v0);
                    Xf[r0*XSTR + col + 1]   = v1; Xh[r0*XSTR + col + 1]   = f2tf32(v1);
                    Xf[(r0+8)*XSTR + col]   = v2; Xh[(r0+8)*XSTR + col]   = f2tf32(v2);
                    Xf[(r0+8)*XSTR + col+1] = v3; Xh[(r0+8)*XSTR + col+1] = f2tf32(v3);
                } else {
                    int gr0 = row0 + r0, gr1 = gr0 + 8;
                    if (gr0 < N_NODES) { g_gskip[(size_t)gr0*128 + col] = v0; g_gskip[(size_t)gr0*128 + col+1] = v1; }
                    if (gr1 < N_NODES) { g_gskip[(size_t)gr1*128 + col] = v2; g_gskip[(size_t)gr1*128 + col+1] = v3; }
                }
            }
        }
    }
    __syncthreads();

    const int wnM  = wni * 16;
    const int bn2  = tid & 127;
    const int kb2  = (tid >> 7) * 4;

    for (int m = 0; m < 2; m++) {
        const float* B1 = mlp_b1 + (l * 2 + m) * 128;
        const float* B2 = mlp_b2 + (l * 2 + m) * 128;

        for (int phase = 0; phase < 2; phase++) {
            const float* W = (phase ? mlp_w2 : mlp_w1) + (size_t)(l * 2 + m) * 16384;
            float cT[4][2][4];
#pragma unroll
            for (int i = 0; i < 4; i++)
#pragma unroll
                for (int j = 0; j < 2; j++)
#pragma unroll
                    for (int q = 0; q < 4; q++) cT[i][j][q] = 0.f;

            float bv2[4];
#pragma unroll
            for (int kk = 0; kk < 4; kk++) bv2[kk] = W[(size_t)(kb2 + kk) * 128 + bn2];

            for (int k0 = 0; k0 < 128; k0 += 16) {
                __syncthreads();
#pragma unroll
                for (int kk = 0; kk < 4; kk++) Bhs[bn2 * ASTR + kb2 + kk] = f2tf32(bv2[kk]);
                __syncthreads();
                if (k0 + 16 < 128) {
                    int kn = k0 + 16;
#pragma unroll
                    for (int kk = 0; kk < 4; kk++) bv2[kk] = W[(size_t)(kn + kb2 + kk) * 128 + bn2];
                }
#pragma unroll
                for (int s = 0; s < 2; s++) {
                    const int ks = s * 8;
                    unsigned bh[2][2];
#pragma unroll
                    for (int nf = 0; nf < 2; nf++) {
                        int b0 = (wnM + nf * 8 + grp) * ASTR + ks + tg;
                        bh[nf][0] = Bhs[b0]; bh[nf][1] = Bhs[b0 + 4];
                    }
#pragma unroll
                    for (int mf = 0; mf < 4; mf++) {
                        unsigned ah[4];
                        int a0 = (wm + mf * 16 + grp) * XSTR + k0 + ks + tg;
                        int a1 = a0 + 8 * XSTR;
                        ah[0] = Xh[a0]; ah[1] = Xh[a1]; ah[2] = Xh[a0 + 4]; ah[3] = Xh[a1 + 4];
#pragma unroll
                        for (int nf = 0; nf < 2; nf++) MMA_TF32(cT[mf][nf], ah, bh[nf]);
                    }
                }
            }

            if (phase == 0) {
                // t = silu(cT + b1); grab residual (fp32 state) then overwrite X with t
                float res[4][2][4];
#pragma unroll
                for (int mf = 0; mf < 4; mf++) {
                    int r0 = wm + mf * 16 + grp;
#pragma unroll
                    for (int nf = 0; nf < 2; nf++) {
                        int col = wnM + nf * 8 + 2 * tg;
                        res[mf][nf][0] = Xf[r0*XSTR + col];
                        res[mf][nf][1] = Xf[r0*XSTR + col + 1];
                        res[mf][nf][2] = Xf[(r0+8)*XSTR + col];
                        res[mf][nf][3] = Xf[(r0+8)*XSTR + col + 1];
                        cT[mf][nf][0] = silu(cT[mf][nf][0] + B1[col]);
                        cT[mf][nf][1] = silu(cT[mf][nf][1] + B1[col + 1]);
                        cT[mf][nf][2] = silu(cT[mf][nf][2] + B1[col]);
                        cT[mf][nf][3] = silu(cT[mf][nf][3] + B1[col + 1]);
                    }
                }
                __syncthreads();
#pragma unroll
                for (int mf = 0; mf < 4; mf++) {
                    int r0 = wm + mf * 16 + grp;
#pragma unroll
                    for (int nf = 0; nf < 2; nf++) {
                        int col = wnM + nf * 8 + 2 * tg;
                        Xf[r0*XSTR+col]       = cT[mf][nf][0]; Xh[r0*XSTR+col]       = f2tf32(cT[mf][nf][0]);
                        Xf[r0*XSTR+col+1]     = cT[mf][nf][1]; Xh[r0*XSTR+col+1]     = f2tf32(cT[mf][nf][1]);
                        Xf[(r0+8)*XSTR+col]   = cT[mf][nf][2]; Xh[(r0+8)*XSTR+col]   = f2tf32(cT[mf][nf][2]);
                        Xf[(r0+8)*XSTR+col+1] = cT[mf][nf][3]; Xh[(r0+8)*XSTR+col+1] = f2tf32(cT[mf][nf][3]);
                        cA[mf][nf][0] = res[mf][nf][0]; cA[mf][nf][1] = res[mf][nf][1];
                        cA[mf][nf][2] = res[mf][nf][2]; cA[mf][nf][3] = res[mf][nf][3];
                    }
                }
                __syncthreads();
            } else {
                if (m == 0) __syncthreads();
#pragma unroll
                for (int mf = 0; mf < 4; mf++) {
                    int r0 = wm + mf * 16 + grp;
#pragma unroll
                    for (int nf = 0; nf < 2; nf++) {
                        int col = wnM + nf * 8 + 2 * tg;
                        float o0 = cT[mf][nf][0] + B2[col]     + cA[mf][nf][0];
                        float o1 = cT[mf][nf][1] + B2[col + 1] + cA[mf][nf][1];
                        float o2 = cT[mf][nf][2] + B2[col]     + cA[mf][nf][2];
                        float o3 = cT[mf][nf][3] + B2[col + 1] + cA[mf][nf][3];
                        if (m == 1) {
                            int gr0 = row0 + r0, gr1 = gr0 + 8;
                            if (gr0 < N_NODES) {
                                g_x[(size_t)gr0*128 + col]   = o0 + g_gskip[(size_t)gr0*128 + col];
                                g_x[(size_t)gr0*128 + col+1] = o1 + g_gskip[(size_t)gr0*128 + col+1];
                            }
                            if (gr1 < N_NODES) {
                                g_x[(size_t)gr1*128 + col]   = o2 + g_gskip[(size_t)gr1*128 + col];
                                g_x[(size_t)gr1*128 + col+1] = o3 + g_gskip[(size_t)gr1*128 + col+1];
                            }
                        } else {
                            Xf[r0*XSTR+col]       = o0; Xh[r0*XSTR+col]       = f2tf32(o0);
                            Xf[r0*XSTR+col+1]     = o1; Xh[r0*XSTR+col+1]     = f2tf32(o1);
                            Xf[(r0+8)*XSTR+col]   = o2; Xh[(r0+8)*XSTR+col]   = f2tf32(o2);
                            Xf[(r0+8)*XSTR+col+1] = o3; Xh[(r0+8)*XSTR+col+1] = f2tf32(o3);
                        }
                    }
                }
                if (m == 0) __syncthreads();
            }
        }
    }
}

// ================= fused pooling + FFN: one block per graph =================
__global__ __launch_bounds__(128) void pool_ffn_kernel(
    const int* __restrict__ batch,
    const float* __restrict__ attn_w, const float* __restrict__ attn_b,
    const float* __restrict__ temp,
    const float* __restrict__ w1, const float* __restrict__ b1,
    const float* __restrict__ w2, const float* __restrict__ b2,
    const float* __restrict__ w3, const float* __restrict__ b3,
    float* __restrict__ out) {
    const int g = blockIdx.x, t = threadIdx.x;
    const int lane = t & 31, wrp = t >> 5;
    __shared__ int sbeg, send;
    __shared__ float aw[512];
    __shared__ float P[4][128];
    __shared__ float ex[128][4];
    __shared__ float m[4], s[4], rs[4];
    __shared__ float wred[4][4];
    __shared__ float p[128], h1[128], red[128];

    if (t == 0) {
        int lo = 0, hi = N_NODES;
        while (lo < hi) { int mid = (lo + hi) >> 1; if (batch[mid] < g) lo = mid + 1; else hi = mid; }
        sbeg = lo;
        hi = N_NODES;
        while (lo < hi) { int mid = (lo + hi) >> 1; if (batch[mid] < g + 1) lo = mid + 1; else hi = mid; }
        send = lo;
    }
    aw[t] = attn_w[t]; aw[128 + t] = attn_w[128 + t];
    aw[256 + t] = attn_w[256 + t]; aw[384 + t] = attn_w[384 + t];
    if (t < 4) { m[t] = -1e30f; s[t] = 0.f; }
    P[0][t] = 0.f; P[1][t] = 0.f; P[2][t] = 0.f; P[3][t] = 0.f;
    __syncthreads();
    const int beg = sbeg, end = send;
    const float invT = 1.f / temp[0];

    for (int c0 = beg; c0 < end; c0 += 128) {
        int idx = c0 + t;
        bool active = idx < end;
        float sc[4] = {-1e30f, -1e30f, -1e30f, -1e30f};
        if (active) {
            const float* xr = g_x + (size_t)idx * HID;
            float a0 = 0.f, a1 = 0.f, a2 = 0.f, a3 = 0.f;
#pragma unroll 8
            for (int k = 0; k < 128; k += 4) {
                float4 xv = *(const float4*)(xr + k);
                a0 += xv.x*aw[k]     + xv.y*aw[k+1]     + xv.z*aw[k+2]     + xv.w*aw[k+3];
                a1 += xv.x*aw[128+k] + xv.y*aw[128+k+1] + xv.z*aw[128+k+2] + xv.w*aw[128+k+3];
                a2 += xv.x*aw[256+k] + xv.y*aw[256+k+1] + xv.z*aw[256+k+2] + xv.w*aw[256+k+3];
                a3 += xv.x*aw[384+k] + xv.y*aw[384+k+1] + xv.z*aw[384+k+2] + xv.w*aw[384+k+3];
            }
            sc[0] = (a0 + attn_b[0]) * invT;
            sc[1] = (a1 + attn_b[1]) * invT;
            sc[2] = (a2 + attn_b[2]) * invT;
            sc[3] = (a3 + attn_b[3]) * invT;
        }
        float mx[4] = {sc[0], sc[1], sc[2], sc[3]};
#pragma unroll
        for (int o = 16; o; o >>= 1)
#pragma unroll
            for (int h = 0; h < 4; h++) mx[h] = fmaxf(mx[h], __shfl_xor_sync(0xffffffffu, mx[h], o));
        if (lane == 0)
#pragma unroll
            for (int h = 0; h < 4; h++) wred[wrp][h] = mx[h];
        __syncthreads();
        if (t < 4) {
            float cm = fmaxf(fmaxf(wred[0][t], wred[1][t]), fmaxf(wred[2][t], wred[3][t]));
            float nm = fmaxf(m[t], cm);
            rs[t] = __expf(m[t] - nm);
            m[t] = nm;
            s[t] *= rs[t];
        }
        __syncthreads();
        float e[4];
#pragma unroll
        for (int h = 0; h < 4; h++) {
            e[h] = active ? __expf(sc[h] - m[h]) : 0.f;
            ex[t][h] = e[h];
        }
        float sm2[4] = {e[0], e[1], e[2], e[3]};
#pragma unroll
        for (int o = 16; o; o >>= 1)
#pragma unroll
            for (int h = 0; h < 4; h++) sm2[h] += __shfl_xor_sync(0xffffffffu, sm2[h], o);
        if (lane == 0)
#pragma unroll
            for (int h = 0; h < 4; h++) wred[wrp][h] = sm2[h];
        __syncthreads();
        if (t < 4) s[t] += wred[0][t] + wred[1][t] + wred[2][t] + wred[3][t];

        int cnt = min(128, end - c0);
        float p0 = P[0][t] * rs[0], p1 = P[1][t] * rs[1];
        float p2 = P[2][t] * rs[2], p3 = P[3][t] * rs[3];
        for (int n = 0; n < cnt; n++) {
            float xv = g_x[(size_t)(c0 + n) * HID + t];
            p0 += ex[n][0] * xv;
            p1 += ex[n][1] * xv;
            p2 += ex[n][2] * xv;
            p3 += ex[n][3] * xv;
        }
        P[0][t] = p0; P[1][t] = p1; P[2][t] = p2; P[3][t] = p3;
        __syncthreads();
    }

    float pooled = 0.f;
#pragma unroll
    for (int h = 0; h < 4; h++) if (s[h] > 0.f) pooled += P[h][t] / s[h];
    p[t] = pooled * 0.25f;
    __syncthreads();

    float acc = b1[t];
#pragma unroll 8
    for (int k = 0; k < 128; k++) acc += p[k] * w1[k * 128 + t];
    h1[t] = silu(acc);
    __syncthreads();
    float acc2 = b2[t];
#pragma unroll 8
    for (int k = 0; k < 128; k++) acc2 += h1[k] * w2[k * 128 + t];
    acc2 = silu(acc2);
    red[t] = acc2 * w3[t];
    __syncthreads();
    for (int o = 64; o > 0; o >>= 1) {
        if (t < o) red[t] += red[t + o];
        __syncthreads();
    }
    if (t == 0) out[g] = red[0] + b3[0];
}

// ---------------- host launcher ---------------------------------------------
extern "C" void kernel_launch(void* const* d_in, const int* in_sizes, int n_in,
                              void* d_out, int out_size) {
    const int* atom  = (const int*)d_in[0];
    const int* hyd   = (const int*)d_in[1];
    const int* deg   = (const int*)d_in[2];
    const int* hyb   = (const int*)d_in[3];
    const int* tgt   = (const int*)d_in[4];
    const int* srcv  = (const int*)d_in[5];
    const int* batch = (const int*)d_in[6];
    const float* emb_atom = (const float*)d_in[7];
    const float* emb_h    = (const float*)d_in[8];
    const float* emb_deg  = (const float*)d_in[9];
    const float* emb_hyb  = (const float*)d_in[10];
    const float* proj_w   = (const float*)d_in[11];
    const float* proj_b   = (const float*)d_in[12];
    const float* in_w     = (const float*)d_in[13];
    const float* in_b     = (const float*)d_in[14];
    const float* mlp_w1   = (const float*)d_in[15];
    const float* mlp_b1   = (const float*)d_in[16];
    const float* mlp_w2   = (const float*)d_in[17];
    const float* mlp_b2   = (const float*)d_in[18];
    const float* skip_w   = (const float*)d_in[19];
    const float* skip_b   = (const float*)d_in[20];
    const float* attn_w   = (const float*)d_in[21];
    const float* attn_b   = (const float*)d_in[22];
    const float* temp     = (const float*)d_in[23];
    const float* ffn_w1   = (const float*)d_in[24];
    const float* ffn_b1   = (const float*)d_in[25];
    const float* ffn_w2   = (const float*)d_in[26];
    const float* ffn_b2   = (const float*)d_in[27];
    const float* ffn_w3   = (const float*)d_in[28];
    const float* ffn_b3   = (const float*)d_in[29];
    float* out = (float*)d_out;

    const int LAYER_SMEM = (2 * 128 * XSTR + 128 * ASTR + 256 * ASTR) * 4;  // 165888
    cudaFuncSetAttribute(layer_kernel, cudaFuncAttributeMaxDynamicSharedMemorySize, LAYER_SMEM);

    // 0. CSR build (once; reused by all 3 layers)
    zero_cnt_kernel<<<(NSLOT + 255) / 256, 256>>>();
    count_kernel<<<(N_EDGES + 255) / 256, 256>>>(tgt);
    chunk_sum_kernel<<<NCHUNK, 256>>>();
    scan_chunks_kernel<<<1, 256>>>();
    scan_within_kernel<<<NCHUNK, 1024>>>();
    fill_kernel<<<(N_EDGES + 255) / 256, 256>>>(tgt, srcv);

    // 1. fused embedding + projection
    proj_kernel<<<GEMM_BLKS, 256>>>(atom, hyd, deg, hyb, emb_atom, emb_h, emb_deg, emb_hyb,
                                    proj_w, proj_b);

    // 2. shell conv layers
    for (int l = 0; l < 3; l++) {
        gather_hops_kernel<<<(NSLOT * 32 + 255) / 256, 256>>>();
        layer_kernel<<<GEMM_BLKS, 512, LAYER_SMEM>>>(in_w, in_b, skip_w, skip_b,
                                                     mlp_w1, mlp_b1, mlp_w2, mlp_b2, l);
    }

    // 3. fused attention pooling + FFN readout
    pool_ffn_kernel<<<NUM_GRAPHS, 128>>>(batch, attn_w, attn_b, temp,
                                         ffn_w1, ffn_b1, ffn_w2, ffn_b2, ffn_w3, ffn_b3, out);
}

// round 7
// speedup vs baseline: 4.3348x; 1.0241x over previous
#include <cuda_runtime.h>
#include <cuda_fp16.h>

#define N_NODES   50000
#define N_EDGES   2400000
#define NUM_GRAPHS 2048
#define NSLOT     (3 * N_NODES)          // 150000 hop-slots
#define NCHUNK    ((NSLOT + 1023) / 1024) // 147
#define HID       128
#define GEMM_BLKS ((N_NODES + 127) / 128)   // 391
#define ASTR 20    // smem stride for streamed 16-wide k tiles
#define XSTR 132   // smem stride for resident 128-wide buffers

// ---------------- scratch (static device memory; no allocs) ----------------
__device__ __align__(16) float  g_x[N_NODES * HID];
__device__ __align__(16) __half g_xh[N_NODES * HID];           // fp16 mirror for gather
__device__ __align__(16) float  g_hops[(size_t)N_NODES * 384]; // 3 hops x 128
__device__ __align__(16) float  g_gskip[N_NODES * HID];
__device__ int g_cnt[NSLOT];
__device__ int g_csum[NCHUNK];
__device__ int g_coff[NCHUNK];
__device__ int g_rowptr[NSLOT + 1];
__device__ int g_cursor[NSLOT];
__device__ int g_esrc[N_EDGES];

__device__ __forceinline__ float silu(float v) { return v / (1.f + __expf(-v)); }

__device__ __forceinline__ unsigned f2tf32(float v) {
    unsigned r;
    asm("cvt.rna.tf32.f32 %0, %1;" : "=r"(r) : "f"(v));
    return r;
}

#define MMA_TF32(cc, aa, bb) \
    asm volatile("mma.sync.aligned.m16n8k8.row.col.f32.tf32.tf32.f32 " \
                 "{%0,%1,%2,%3},{%4,%5,%6,%7},{%8,%9},{%0,%1,%2,%3};" \
                 : "+f"(cc[0]), "+f"(cc[1]), "+f"(cc[2]), "+f"(cc[3]) \
                 : "r"(aa[0]), "r"(aa[1]), "r"(aa[2]), "r"(aa[3]), \
                   "r"(bb[0]), "r"(bb[1]))

// ================= CSR build =================
__global__ void zero_cnt_kernel() {
    int i = blockIdx.x * blockDim.x + threadIdx.x;
    if (i < NSLOT) g_cnt[i] = 0;
}
__global__ void count_kernel(const int* __restrict__ tgt) {
    int e = blockIdx.x * blockDim.x + threadIdx.x;
    if (e < N_EDGES) atomicAdd(&g_cnt[tgt[e]], 1);
}
__global__ void chunk_sum_kernel() {
    __shared__ int red[256];
    int b = blockIdx.x, t = threadIdx.x;
    int s = 0;
#pragma unroll
    for (int j = 0; j < 4; j++) {
        int i = b * 1024 + j * 256 + t;
        if (i < NSLOT) s += g_cnt[i];
    }
    red[t] = s; __syncthreads();
    for (int o = 128; o > 0; o >>= 1) {
        if (t < o) red[t] += red[t + o];
        __syncthreads();
    }
    if (t == 0) g_csum[b] = red[0];
}
__global__ void scan_chunks_kernel() {
    __shared__ int buf[2][256];
    int t = threadIdx.x;
    int v = (t < NCHUNK) ? g_csum[t] : 0;
    buf[0][t] = v;
    __syncthreads();
    int cur = 0;
#pragma unroll
    for (int off = 1; off < 256; off <<= 1) {
        int nv = buf[cur][t] + ((t >= off) ? buf[cur][t - off] : 0);
        buf[cur ^ 1][t] = nv;
        cur ^= 1;
        __syncthreads();
    }
    if (t < NCHUNK) g_coff[t] = buf[cur][t] - v;
    if (t == NCHUNK - 1) g_rowptr[NSLOT] = buf[cur][t];
}
__global__ void scan_within_kernel() {
    __shared__ int buf[2][1024];
    int b = blockIdx.x, t = threadIdx.x;
    int i = b * 1024 + t;
    int v = (i < NSLOT) ? g_cnt[i] : 0;
    buf[0][t] = v;
    __syncthreads();
    int cur = 0;
#pragma unroll
    for (int off = 1; off < 1024; off <<= 1) {
        int nv = buf[cur][t] + ((t >= off) ? buf[cur][t - off] : 0);
        buf[cur ^ 1][t] = nv;
        cur ^= 1;
        __syncthreads();
    }
    if (i < NSLOT) {
        int excl = buf[cur][t] - v;
        int rp = g_coff[b] + excl;
        g_rowptr[i] = rp;
        g_cursor[i] = rp;
    }
}
__global__ void fill_kernel(const int* __restrict__ tgt, const int* __restrict__ srcv) {
    int e = blockIdx.x * blockDim.x + threadIdx.x;
    if (e >= N_EDGES) return;
    int t = tgt[e];
    int pos = atomicAdd(&g_cursor[t], 1);
    g_esrc[pos] = srcv[e] % N_NODES;
}

// ================= hop gather: one warp per slot, fp16 rows, fp32 accum ====
__global__ __launch_bounds__(256) void gather_hops_kernel() {
    int slot = (blockIdx.x * blockDim.x + threadIdx.x) >> 5;
    int lane = threadIdx.x & 31;
    if (slot >= NSLOT) return;
    int beg = g_rowptr[slot], end = g_rowptr[slot + 1];
    float4 a0 = make_float4(0.f,0.f,0.f,0.f), a1 = a0, a2 = a0, a3 = a0;
    const uint2* xh = (const uint2*)g_xh;   // 32 uint2 per 128-half row
    int e = beg;
    for (; e + 3 < end; e += 4) {
        int s0 = g_esrc[e], s1 = g_esrc[e+1], s2 = g_esrc[e+2], s3 = g_esrc[e+3];
        uint2 u0 = xh[(size_t)s0 * 32 + lane];
        uint2 u1 = xh[(size_t)s1 * 32 + lane];
        uint2 u2 = xh[(size_t)s2 * 32 + lane];
        uint2 u3 = xh[(size_t)s3 * 32 + lane];
        float2 f;
        f = __half22float2(*(__half2*)&u0.x); a0.x += f.x; a0.y += f.y;
        f = __half22float2(*(__half2*)&u0.y); a0.z += f.x; a0.w += f.y;
        f = __half22float2(*(__half2*)&u1.x); a1.x += f.x; a1.y += f.y;
        f = __half22float2(*(__half2*)&u1.y); a1.z += f.x; a1.w += f.y;
        f = __half22float2(*(__half2*)&u2.x); a2.x += f.x; a2.y += f.y;
        f = __half22float2(*(__half2*)&u2.y); a2.z += f.x; a2.w += f.y;
        f = __half22float2(*(__half2*)&u3.x); a3.x += f.x; a3.y += f.y;
        f = __half22float2(*(__half2*)&u3.y); a3.z += f.x; a3.w += f.y;
    }
    for (; e < end; e++) {
        int s0 = g_esrc[e];
        uint2 u0 = xh[(size_t)s0 * 32 + lane];
        float2 f;
        f = __half22float2(*(__half2*)&u0.x); a0.x += f.x; a0.y += f.y;
        f = __half22float2(*(__half2*)&u0.y); a0.z += f.x; a0.w += f.y;
    }
    a0.x += a1.x + a2.x + a3.x;
    a0.y += a1.y + a2.y + a3.y;
    a0.z += a1.z + a2.z + a3.z;
    a0.w += a1.w + a2.w + a3.w;
    int node = slot % N_NODES, hop = slot / N_NODES;
    *(float4*)(g_hops + (size_t)node * 384 + hop * HID + lane * 4) = a0;
}

// ================= fused embed+proj GEMM (single-pass tf32) =================
__global__ __launch_bounds__(256) void proj_kernel(
    const int* __restrict__ atom, const int* __restrict__ hyd,
    const int* __restrict__ deg,  const int* __restrict__ hyb,
    const float* __restrict__ ea, const float* __restrict__ eh,
    const float* __restrict__ ed, const float* __restrict__ ey,
    const float* __restrict__ B, const float* __restrict__ bias) {
    __shared__ unsigned Ah[128 * ASTR];
    __shared__ unsigned Bh[128 * ASTR];
    __shared__ int sidx[128][4];

    const int tid  = threadIdx.x;
    const int lane = tid & 31, wid = tid >> 5;
    const int wm = (wid >> 2) * 64;
    const int wn = (wid & 3) * 32;
    const int grp = lane >> 2, tg = lane & 3;
    const int row0 = blockIdx.x * 128;

    if (tid < 128) {
        int gr = row0 + tid;
        int g2 = (gr < N_NODES) ? gr : 0;
        sidx[tid][0] = atom[g2];
        sidx[tid][1] = hyd[g2];
        sidx[tid][2] = deg[g2];
        sidx[tid][3] = hyb[g2];
    }
    __syncthreads();
    const float* tabs[4] = {ea, eh, ed, ey};

    float c[4][4][4];
#pragma unroll
    for (int i = 0; i < 4; i++)
#pragma unroll
        for (int j = 0; j < 4; j++)
#pragma unroll
            for (int q = 0; q < 4; q++) c[i][j][q] = 0.f;

    const int ar  = tid >> 2;
    const int ac4 = (tid & 3) * 4;
    const int bn  = tid & 127;
    const int bk0 = (tid >> 7) * 8;

    for (int k0 = 0; k0 < 256; k0 += 16) {
        float4 av[2]; float bv[8];
        int kt = (k0 + ac4) >> 6, kw = (k0 + ac4) & 63;
#pragma unroll
        for (int it = 0; it < 2; it++) {
            int r = ar + it * 64;
            av[it] = *(const float4*)(tabs[kt] + (size_t)sidx[r][kt] * 64 + kw);
        }
#pragma unroll
        for (int kk = 0; kk < 8; kk++) bv[kk] = B[(size_t)(k0 + bk0 + kk) * 128 + bn];

        __syncthreads();
#pragma unroll
        for (int it = 0; it < 2; it++) {
            int r = ar + it * 64;
            float vv[4] = {av[it].x, av[it].y, av[it].z, av[it].w};
#pragma unroll
            for (int j = 0; j < 4; j++) Ah[r * ASTR + ac4 + j] = f2tf32(vv[j]);
        }
#pragma unroll
        for (int kk = 0; kk < 8; kk++) Bh[bn * ASTR + bk0 + kk] = f2tf32(bv[kk]);
        __syncthreads();
#pragma unroll
        for (int s = 0; s < 2; s++) {
            const int ks = s * 8;
            unsigned bh[4][2];
#pragma unroll
            for (int nf = 0; nf < 4; nf++) {
                int b0 = (wn + nf * 8 + grp) * ASTR + ks + tg;
                bh[nf][0] = Bh[b0]; bh[nf][1] = Bh[b0 + 4];
            }
#pragma unroll
            for (int mf = 0; mf < 4; mf++) {
                unsigned ah[4];
                int a0 = (wm + mf * 16 + grp) * ASTR + ks + tg;
                int a1 = a0 + 8 * ASTR;
                ah[0] = Ah[a0]; ah[1] = Ah[a1]; ah[2] = Ah[a0 + 4]; ah[3] = Ah[a1 + 4];
#pragma unroll
                for (int nf = 0; nf < 4; nf++) MMA_TF32(c[mf][nf], ah, bh[nf]);
            }
        }
    }

#pragma unroll
    for (int mf = 0; mf < 4; mf++) {
        int r0 = row0 + wm + mf * 16 + grp;
        int r1 = r0 + 8;
#pragma unroll
        for (int nf = 0; nf < 4; nf++) {
            int col = wn + nf * 8 + 2 * tg;
            float bia0 = bias[col], bia1 = bias[col + 1];
            if (r0 < N_NODES) {
                float v0 = silu(c[mf][nf][0] + bia0), v1 = silu(c[mf][nf][1] + bia1);
                g_x[(size_t)r0 * 128 + col]      = v0;
                g_x[(size_t)r0 * 128 + col + 1]  = v1;
                g_xh[(size_t)r0 * 128 + col]     = __float2half(v0);
                g_xh[(size_t)r0 * 128 + col + 1] = __float2half(v1);
            }
            if (r1 < N_NODES) {
                float v2 = silu(c[mf][nf][2] + bia0), v3 = silu(c[mf][nf][3] + bia1);
                g_x[(size_t)r1 * 128 + col]      = v2;
                g_x[(size_t)r1 * 128 + col + 1]  = v3;
                g_xh[(size_t)r1 * 128 + col]     = __float2half(v2);
                g_xh[(size_t)r1 * 128 + col + 1] = __float2half(v3);
            }
        }
    }
}

// ================= mega layer kernel (single-pass tf32, fp32 state) =========
__device__ __forceinline__ const float* feat_ptr(int gr, int k) {
    return (k < 128) ? (g_x + (size_t)gr * 128 + k)
                     : (g_hops + (size_t)gr * 384 + (k - 128));
}

__global__ __launch_bounds__(512, 1) void layer_kernel(
    const float* __restrict__ in_w,   const float* __restrict__ in_b,
    const float* __restrict__ skip_w, const float* __restrict__ skip_b,
    const float* __restrict__ mlp_w1, const float* __restrict__ mlp_b1,
    const float* __restrict__ mlp_w2, const float* __restrict__ mlp_b2,
    int l) {
    extern __shared__ unsigned sm[];
    float*    Xf  = (float*)sm;            // 128*XSTR fp32 state (residuals)
    unsigned* Xh  = sm  + 128 * XSTR;      // 128*XSTR tf32 mirror (MMA A-operand)
    unsigned* Ahs = Xh  + 128 * XSTR;      // 128*ASTR streamed A chunks
    unsigned* Bhs = Ahs + 128 * ASTR;      // 256*ASTR streamed B chunks

    const int tid  = threadIdx.x;
    const int lane = tid & 31, wid = tid >> 5;
    const int grp  = lane >> 2, tg = lane & 3;
    const int wm   = (wid >> 3) * 64;
    const int wni  = wid & 7;
    const int row0 = blockIdx.x * 128;

    const float* Win = in_w   + (size_t)l * 512 * 128;
    const float* Wsk = skip_w + (size_t)l * 512 * 128;

    float cA[4][4][4];
#pragma unroll
    for (int i = 0; i < 4; i++)
#pragma unroll
        for (int j = 0; j < 4; j++)
#pragma unroll
            for (int q = 0; q < 4; q++) cA[i][j][q] = 0.f;

    const int ar  = tid >> 2;
    const int ac4 = (tid & 3) * 4;
    const int bn  = tid & 255;
    const int bk0 = (tid >> 8) * 8;
    const float* Wmy = (bn < 128) ? Win : Wsk;
    const int    bcol = bn & 127;

    float4 av; float bv[8];
    {
        int gr = row0 + ar;
        av = (gr < N_NODES) ? *(const float4*)feat_ptr(gr, ac4) : make_float4(0,0,0,0);
#pragma unroll
        for (int kk = 0; kk < 8; kk++) bv[kk] = Wmy[(size_t)(bk0 + kk) * 128 + bcol];
    }

    const int wnA = wni * 32;
    for (int k0 = 0; k0 < 512; k0 += 16) {
        __syncthreads();
        {
            float vv[4] = {av.x, av.y, av.z, av.w};
#pragma unroll
            for (int j = 0; j < 4; j++) Ahs[ar * ASTR + ac4 + j] = f2tf32(vv[j]);
#pragma unroll
            for (int kk = 0; kk < 8; kk++) Bhs[bn * ASTR + bk0 + kk] = f2tf32(bv[kk]);
        }
        __syncthreads();
        if (k0 + 16 < 512) {
            int kn = k0 + 16;
            int gr = row0 + ar;
            av = (gr < N_NODES) ? *(const float4*)feat_ptr(gr, kn + ac4) : make_float4(0,0,0,0);
#pragma unroll
            for (int kk = 0; kk < 8; kk++) bv[kk] = Wmy[(size_t)(kn + bk0 + kk) * 128 + bcol];
        }
#pragma unroll
        for (int s = 0; s < 2; s++) {
            const int ks = s * 8;
            unsigned bh[4][2];
#pragma unroll
            for (int nf = 0; nf < 4; nf++) {
                int b0 = (wnA + nf * 8 + grp) * ASTR + ks + tg;
                bh[nf][0] = Bhs[b0]; bh[nf][1] = Bhs[b0 + 4];
            }
#pragma unroll
            for (int mf = 0; mf < 4; mf++) {
                unsigned ah[4];
                int a0 = (wm + mf * 16 + grp) * ASTR + ks + tg;
                int a1 = a0 + 8 * ASTR;
                ah[0] = Ahs[a0]; ah[1] = Ahs[a1]; ah[2] = Ahs[a0 + 4]; ah[3] = Ahs[a1 + 4];
#pragma unroll
                for (int nf = 0; nf < 4; nf++) MMA_TF32(cA[mf][nf], ah, bh[nf]);
            }
        }
    }
    __syncthreads();

    // phase A epilogue: wni<4 -> h (silu) into Xf/Xh; wni>=4 -> gskip to global
    {
        const float* bias = (wni < 4) ? (in_b + l * 128) : (skip_b + l * 128);
#pragma unroll
        for (int mf = 0; mf < 4; mf++) {
            int r0 = wm + mf * 16 + grp;
#pragma unroll
            for (int nf = 0; nf < 4; nf++) {
                int col = (wni & 3) * 32 + nf * 8 + 2 * tg;
                float b0 = bias[col], b1 = bias[col + 1];
                float v0 = cA[mf][nf][0] + b0, v1 = cA[mf][nf][1] + b1;
                float v2 = cA[mf][nf][2] + b0, v3 = cA[mf][nf][3] + b1;
                if (wni < 4) {
                    v0 = silu(v0); v1 = silu(v1); v2 = silu(v2); v3 = silu(v3);
                    Xf[r0*XSTR + col]       = v0; Xh[r0*XSTR + col]       = f2tf32(v0);
                    Xf[r0*XSTR + col + 1]   = v1; Xh[r0*XSTR + col + 1]   = f2tf32(v1);
                    Xf[(r0+8)*XSTR + col]   = v2; Xh[(r0+8)*XSTR + col]   = f2tf32(v2);
                    Xf[(r0+8)*XSTR + col+1] = v3; Xh[(r0+8)*XSTR + col+1] = f2tf32(v3);
                } else {
                    int gr0 = row0 + r0, gr1 = gr0 + 8;
                    if (gr0 < N_NODES) { g_gskip[(size_t)gr0*128 + col] = v0; g_gskip[(size_t)gr0*128 + col+1] = v1; }
                    if (gr1 < N_NODES) { g_gskip[(size_t)gr1*128 + col] = v2; g_gskip[(size_t)gr1*128 + col+1] = v3; }
                }
            }
        }
    }
    __syncthreads();

    const int wnM  = wni * 16;
    const int bn2  = tid & 127;
    const int kb2  = (tid >> 7) * 4;

    for (int m = 0; m < 2; m++) {
        const float* B1 = mlp_b1 + (l * 2 + m) * 128;
        const float* B2 = mlp_b2 + (l * 2 + m) * 128;

        for (int phase = 0; phase < 2; phase++) {
            const float* W = (phase ? mlp_w2 : mlp_w1) + (size_t)(l * 2 + m) * 16384;
            float cT[4][2][4];
#pragma unroll
            for (int i = 0; i < 4; i++)
#pragma unroll
                for (int j = 0; j < 2; j++)
#pragma unroll
                    for (int q = 0; q < 4; q++) cT[i][j][q] = 0.f;

            float bv2[4];
#pragma unroll
            for (int kk = 0; kk < 4; kk++) bv2[kk] = W[(size_t)(kb2 + kk) * 128 + bn2];

            for (int k0 = 0; k0 < 128; k0 += 16) {
                __syncthreads();
#pragma unroll
                for (int kk = 0; kk < 4; kk++) Bhs[bn2 * ASTR + kb2 + kk] = f2tf32(bv2[kk]);
                __syncthreads();
                if (k0 + 16 < 128) {
                    int kn = k0 + 16;
#pragma unroll
                    for (int kk = 0; kk < 4; kk++) bv2[kk] = W[(size_t)(kn + kb2 + kk) * 128 + bn2];
                }
#pragma unroll
                for (int s = 0; s < 2; s++) {
                    const int ks = s * 8;
                    unsigned bh[2][2];
#pragma unroll
                    for (int nf = 0; nf < 2; nf++) {
                        int b0 = (wnM + nf * 8 + grp) * ASTR + ks + tg;
                        bh[nf][0] = Bhs[b0]; bh[nf][1] = Bhs[b0 + 4];
                    }
#pragma unroll
                    for (int mf = 0; mf < 4; mf++) {
                        unsigned ah[4];
                        int a0 = (wm + mf * 16 + grp) * XSTR + k0 + ks + tg;
                        int a1 = a0 + 8 * XSTR;
                        ah[0] = Xh[a0]; ah[1] = Xh[a1]; ah[2] = Xh[a0 + 4]; ah[3] = Xh[a1 + 4];
#pragma unroll
                        for (int nf = 0; nf < 2; nf++) MMA_TF32(cT[mf][nf], ah, bh[nf]);
                    }
                }
            }

            if (phase == 0) {
                float res[4][2][4];
#pragma unroll
                for (int mf = 0; mf < 4; mf++) {
                    int r0 = wm + mf * 16 + grp;
#pragma unroll
                    for (int nf = 0; nf < 2; nf++) {
                        int col = wnM + nf * 8 + 2 * tg;
                        res[mf][nf][0] = Xf[r0*XSTR + col];
                        res[mf][nf][1] = Xf[r0*XSTR + col + 1];
                        res[mf][nf][2] = Xf[(r0+8)*XSTR + col];
                        res[mf][nf][3] = Xf[(r0+8)*XSTR + col + 1];
                        cT[mf][nf][0] = silu(cT[mf][nf][0] + B1[col]);
                        cT[mf][nf][1] = silu(cT[mf][nf][1] + B1[col + 1]);
                        cT[mf][nf][2] = silu(cT[mf][nf][2] + B1[col]);
                        cT[mf][nf][3] = silu(cT[mf][nf][3] + B1[col + 1]);
                    }
                }
                __syncthreads();
#pragma unroll
                for (int mf = 0; mf < 4; mf++) {
                    int r0 = wm + mf * 16 + grp;
#pragma unroll
                    for (int nf = 0; nf < 2; nf++) {
                        int col = wnM + nf * 8 + 2 * tg;
                        Xf[r0*XSTR+col]       = cT[mf][nf][0]; Xh[r0*XSTR+col]       = f2tf32(cT[mf][nf][0]);
                        Xf[r0*XSTR+col+1]     = cT[mf][nf][1]; Xh[r0*XSTR+col+1]     = f2tf32(cT[mf][nf][1]);
                        Xf[(r0+8)*XSTR+col]   = cT[mf][nf][2]; Xh[(r0+8)*XSTR+col]   = f2tf32(cT[mf][nf][2]);
                        Xf[(r0+8)*XSTR+col+1] = cT[mf][nf][3]; Xh[(r0+8)*XSTR+col+1] = f2tf32(cT[mf][nf][3]);
                        cA[mf][nf][0] = res[mf][nf][0]; cA[mf][nf][1] = res[mf][nf][1];
                        cA[mf][nf][2] = res[mf][nf][2]; cA[mf][nf][3] = res[mf][nf][3];
                    }
                }
                __syncthreads();
            } else {
                if (m == 0) __syncthreads();
#pragma unroll
                for (int mf = 0; mf < 4; mf++) {
                    int r0 = wm + mf * 16 + grp;
#pragma unroll
                    for (int nf = 0; nf < 2; nf++) {
                        int col = wnM + nf * 8 + 2 * tg;
                        float o0 = cT[mf][nf][0] + B2[col]     + cA[mf][nf][0];
                        float o1 = cT[mf][nf][1] + B2[col + 1] + cA[mf][nf][1];
                        float o2 = cT[mf][nf][2] + B2[col]     + cA[mf][nf][2];
                        float o3 = cT[mf][nf][3] + B2[col + 1] + cA[mf][nf][3];
                        if (m == 1) {
                            int gr0 = row0 + r0, gr1 = gr0 + 8;
                            if (gr0 < N_NODES) {
                                float f0 = o0 + g_gskip[(size_t)gr0*128 + col];
                                float f1 = o1 + g_gskip[(size_t)gr0*128 + col+1];
                                g_x[(size_t)gr0*128 + col]    = f0;
                                g_x[(size_t)gr0*128 + col+1]  = f1;
                                g_xh[(size_t)gr0*128 + col]   = __float2half(f0);
                                g_xh[(size_t)gr0*128 + col+1] = __float2half(f1);
                            }
                            if (gr1 < N_NODES) {
                                float f2 = o2 + g_gskip[(size_t)gr1*128 + col];
                                float f3 = o3 + g_gskip[(size_t)gr1*128 + col+1];
                                g_x[(size_t)gr1*128 + col]    = f2;
                                g_x[(size_t)gr1*128 + col+1]  = f3;
                                g_xh[(size_t)gr1*128 + col]   = __float2half(f2);
                                g_xh[(size_t)gr1*128 + col+1] = __float2half(f3);
                            }
                        } else {
                            Xf[r0*XSTR+col]       = o0; Xh[r0*XSTR+col]       = f2tf32(o0);
                            Xf[r0*XSTR+col+1]     = o1; Xh[r0*XSTR+col+1]     = f2tf32(o1);
                            Xf[(r0+8)*XSTR+col]   = o2; Xh[(r0+8)*XSTR+col]   = f2tf32(o2);
                            Xf[(r0+8)*XSTR+col+1] = o3; Xh[(r0+8)*XSTR+col+1] = f2tf32(o3);
                        }
                    }
                }
                if (m == 0) __syncthreads();
            }
        }
    }
}

// ================= fused pooling + FFN: one block per graph =================
__global__ __launch_bounds__(128) void pool_ffn_kernel(
    const int* __restrict__ batch,
    const float* __restrict__ attn_w, const float* __restrict__ attn_b,
    const float* __restrict__ temp,
    const float* __restrict__ w1, const float* __restrict__ b1,
    const float* __restrict__ w2, const float* __restrict__ b2,
    const float* __restrict__ w3, const float* __restrict__ b3,
    float* __restrict__ out) {
    const int g = blockIdx.x, t = threadIdx.x;
    const int lane = t & 31, wrp = t >> 5;
    __shared__ int sbeg, send;
    __shared__ float aw[512];
    __shared__ float P[4][128];
    __shared__ float ex[128][4];
    __shared__ float m[4], s[4], rs[4];
    __shared__ float wred[4][4];
    __shared__ float p[128], h1[128], red[128];

    if (t == 0) {
        int lo = 0, hi = N_NODES;
        while (lo < hi) { int mid = (lo + hi) >> 1; if (batch[mid] < g) lo = mid + 1; else hi = mid; }
        sbeg = lo;
        hi = N_NODES;
        while (lo < hi) { int mid = (lo + hi) >> 1; if (batch[mid] < g + 1) lo = mid + 1; else hi = mid; }
        send = lo;
    }
    aw[t] = attn_w[t]; aw[128 + t] = attn_w[128 + t];
    aw[256 + t] = attn_w[256 + t]; aw[384 + t] = attn_w[384 + t];
    if (t < 4) { m[t] = -1e30f; s[t] = 0.f; }
    P[0][t] = 0.f; P[1][t] = 0.f; P[2][t] = 0.f; P[3][t] = 0.f;
    __syncthreads();
    const int beg = sbeg, end = send;
    const float invT = 1.f / temp[0];

    for (int c0 = beg; c0 < end; c0 += 128) {
        int idx = c0 + t;
        bool active = idx < end;
        float sc[4] = {-1e30f, -1e30f, -1e30f, -1e30f};
        if (active) {
            const float* xr = g_x + (size_t)idx * HID;
            float a0 = 0.f, a1 = 0.f, a2 = 0.f, a3 = 0.f;
#pragma unroll 8
            for (int k = 0; k < 128; k += 4) {
                float4 xv = *(const float4*)(xr + k);
                a0 += xv.x*aw[k]     + xv.y*aw[k+1]     + xv.z*aw[k+2]     + xv.w*aw[k+3];
                a1 += xv.x*aw[128+k] + xv.y*aw[128+k+1] + xv.z*aw[128+k+2] + xv.w*aw[128+k+3];
                a2 += xv.x*aw[256+k] + xv.y*aw[256+k+1] + xv.z*aw[256+k+2] + xv.w*aw[256+k+3];
                a3 += xv.x*aw[384+k] + xv.y*aw[384+k+1] + xv.z*aw[384+k+2] + xv.w*aw[384+k+3];
            }
            sc[0] = (a0 + attn_b[0]) * invT;
            sc[1] = (a1 + attn_b[1]) * invT;
            sc[2] = (a2 + attn_b[2]) * invT;
            sc[3] = (a3 + attn_b[3]) * invT;
        }
        float mx[4] = {sc[0], sc[1], sc[2], sc[3]};
#pragma unroll
        for (int o = 16; o; o >>= 1)
#pragma unroll
            for (int h = 0; h < 4; h++) mx[h] = fmaxf(mx[h], __shfl_xor_sync(0xffffffffu, mx[h], o));
        if (lane == 0)
#pragma unroll
            for (int h = 0; h < 4; h++) wred[wrp][h] = mx[h];
        __syncthreads();
        if (t < 4) {
            float cm = fmaxf(fmaxf(wred[0][t], wred[1][t]), fmaxf(wred[2][t], wred[3][t]));
            float nm = fmaxf(m[t], cm);
            rs[t] = __expf(m[t] - nm);
            m[t] = nm;
            s[t] *= rs[t];
        }
        __syncthreads();
        float e[4];
#pragma unroll
        for (int h = 0; h < 4; h++) {
            e[h] = active ? __expf(sc[h] - m[h]) : 0.f;
            ex[t][h] = e[h];
        }
        float sm2[4] = {e[0], e[1], e[2], e[3]};
#pragma unroll
        for (int o = 16; o; o >>= 1)
#pragma unroll
            for (int h = 0; h < 4; h++) sm2[h] += __shfl_xor_sync(0xffffffffu, sm2[h], o);
        if (lane == 0)
#pragma unroll
            for (int h = 0; h < 4; h++) wred[wrp][h] = sm2[h];
        __syncthreads();
        if (t < 4) s[t] += wred[0][t] + wred[1][t] + wred[2][t] + wred[3][t];

        int cnt = min(128, end - c0);
        float p0 = P[0][t] * rs[0], p1 = P[1][t] * rs[1];
        float p2 = P[2][t] * rs[2], p3 = P[3][t] * rs[3];
        for (int n = 0; n < cnt; n++) {
            float xv = g_x[(size_t)(c0 + n) * HID + t];
            p0 += ex[n][0] * xv;
            p1 += ex[n][1] * xv;
            p2 += ex[n][2] * xv;
            p3 += ex[n][3] * xv;
        }
        P[0][t] = p0; P[1][t] = p1; P[2][t] = p2; P[3][t] = p3;
        __syncthreads();
    }

    float pooled = 0.f;
#pragma unroll
    for (int h = 0; h < 4; h++) if (s[h] > 0.f) pooled += P[h][t] / s[h];
    p[t] = pooled * 0.25f;
    __syncthreads();

    float acc = b1[t];
#pragma unroll 8
    for (int k = 0; k < 128; k++) acc += p[k] * w1[k * 128 + t];
    h1[t] = silu(acc);
    __syncthreads();
    float acc2 = b2[t];
#pragma unroll 8
    for (int k = 0; k < 128; k++) acc2 += h1[k] * w2[k * 128 + t];
    acc2 = silu(acc2);
    red[t] = acc2 * w3[t];
    __syncthreads();
    for (int o = 64; o > 0; o >>= 1) {
        if (t < o) red[t] += red[t + o];
        __syncthreads();
    }
    if (t == 0) out[g] = red[0] + b3[0];
}

// ---------------- host launcher ---------------------------------------------
extern "C" void kernel_launch(void* const* d_in, const int* in_sizes, int n_in,
                              void* d_out, int out_size) {
    const int* atom  = (const int*)d_in[0];
    const int* hyd   = (const int*)d_in[1];
    const int* deg   = (const int*)d_in[2];
    const int* hyb   = (const int*)d_in[3];
    const int* tgt   = (const int*)d_in[4];
    const int* srcv  = (const int*)d_in[5];
    const int* batch = (const int*)d_in[6];
    const float* emb_atom = (const float*)d_in[7];
    const float* emb_h    = (const float*)d_in[8];
    const float* emb_deg  = (const float*)d_in[9];
    const float* emb_hyb  = (const float*)d_in[10];
    const float* proj_w   = (const float*)d_in[11];
    const float* proj_b   = (const float*)d_in[12];
    const float* in_w     = (const float*)d_in[13];
    const float* in_b     = (const float*)d_in[14];
    const float* mlp_w1   = (const float*)d_in[15];
    const float* mlp_b1   = (const float*)d_in[16];
    const float* mlp_w2   = (const float*)d_in[17];
    const float* mlp_b2   = (const float*)d_in[18];
    const float* skip_w   = (const float*)d_in[19];
    const float* skip_b   = (const float*)d_in[20];
    const float* attn_w   = (const float*)d_in[21];
    const float* attn_b   = (const float*)d_in[22];
    const float* temp     = (const float*)d_in[23];
    const float* ffn_w1   = (const float*)d_in[24];
    const float* ffn_b1   = (const float*)d_in[25];
    const float* ffn_w2   = (const float*)d_in[26];
    const float* ffn_b2   = (const float*)d_in[27];
    const float* ffn_w3   = (const float*)d_in[28];
    const float* ffn_b3   = (const float*)d_in[29];
    float* out = (float*)d_out;

    const int LAYER_SMEM = (2 * 128 * XSTR + 128 * ASTR + 256 * ASTR) * 4;  // 165888
    cudaFuncSetAttribute(layer_kernel, cudaFuncAttributeMaxDynamicSharedMemorySize, LAYER_SMEM);

    // 0. CSR build (once; reused by all 3 layers)
    zero_cnt_kernel<<<(NSLOT + 255) / 256, 256>>>();
    count_kernel<<<(N_EDGES + 255) / 256, 256>>>(tgt);
    chunk_sum_kernel<<<NCHUNK, 256>>>();
    scan_chunks_kernel<<<1, 256>>>();
    scan_within_kernel<<<NCHUNK, 1024>>>();
    fill_kernel<<<(N_EDGES + 255) / 256, 256>>>(tgt, srcv);

    // 1. fused embedding + projection (writes fp32 x + fp16 mirror)
    proj_kernel<<<GEMM_BLKS, 256>>>(atom, hyd, deg, hyb, emb_atom, emb_h, emb_deg, emb_hyb,
                                    proj_w, proj_b);

    // 2. shell conv layers
    for (int l = 0; l < 3; l++) {
        gather_hops_kernel<<<(NSLOT * 32 + 255) / 256, 256>>>();
        layer_kernel<<<GEMM_BLKS, 512, LAYER_SMEM>>>(in_w, in_b, skip_w, skip_b,
                                                     mlp_w1, mlp_b1, mlp_w2, mlp_b2, l);
    }

    // 3. fused attention pooling + FFN readout
    pool_ffn_kernel<<<NUM_GRAPHS, 128>>>(batch, attn_w, attn_b, temp,
                                         ffn_w1, ffn_b1, ffn_w2, ffn_b2, ffn_w3, ffn_b3, out);
}

// round 8
// speedup vs baseline: 5.7395x; 1.3240x over previous
#include <cuda_runtime.h>
#include <cuda_fp16.h>

#define N_NODES   50000
#define N_EDGES   2400000
#define NUM_GRAPHS 2048
#define NSLOT     (3 * N_NODES)          // 150000 hop-slots
#define NCHUNK    ((NSLOT + 1023) / 1024) // 147
#define HID       128
#define GEMM_BLKS ((N_NODES + 127) / 128)   // 391
#define ASTR 20    // smem stride for proj streamed tiles (tf32 path)
#define XSTR 132   // smem stride for resident fp32 state
#define HSTR 68    // smem stride (u32) for resident fp16 buffers, 68%32==4
#define CSTR 20    // smem stride (u32) for streamed fp16 chunks,  20%32==20 (conflict-free pattern)

// ---------------- scratch (static device memory; no allocs) ----------------
__device__ __align__(16) float  g_x[N_NODES * HID];
__device__ __align__(16) __half g_xh[N_NODES * HID];             // fp16 mirror of x
__device__ __align__(16) __half g_hops16[(size_t)N_NODES * 384]; // fp16 hop sums
__device__ __align__(16) float  g_gskip[N_NODES * HID];
__device__ int g_cnt[NSLOT];
__device__ int g_csum[NCHUNK];
__device__ int g_coff[NCHUNK];
__device__ int g_rowptr[NSLOT + 1];
__device__ int g_cursor[NSLOT];
__device__ int g_esrc[N_EDGES];

__device__ __forceinline__ float silu(float v) { return v / (1.f + __expf(-v)); }

__device__ __forceinline__ unsigned f2tf32(float v) {
    unsigned r;
    asm("cvt.rna.tf32.f32 %0, %1;" : "=r"(r) : "f"(v));
    return r;
}
__device__ __forceinline__ unsigned pack_half2(float a, float b) {
    __half2 h = __floats2half2_rn(a, b);
    return *(unsigned*)&h;
}

#define MMA_TF32(cc, aa, bb) \
    asm volatile("mma.sync.aligned.m16n8k8.row.col.f32.tf32.tf32.f32 " \
                 "{%0,%1,%2,%3},{%4,%5,%6,%7},{%8,%9},{%0,%1,%2,%3};" \
                 : "+f"(cc[0]), "+f"(cc[1]), "+f"(cc[2]), "+f"(cc[3]) \
                 : "r"(aa[0]), "r"(aa[1]), "r"(aa[2]), "r"(aa[3]), \
                   "r"(bb[0]), "r"(bb[1]))

#define MMA_F16(cc, aa, bb) \
    asm volatile("mma.sync.aligned.m16n8k16.row.col.f32.f16.f16.f32 " \
                 "{%0,%1,%2,%3},{%4,%5,%6,%7},{%8,%9},{%0,%1,%2,%3};" \
                 : "+f"(cc[0]), "+f"(cc[1]), "+f"(cc[2]), "+f"(cc[3]) \
                 : "r"(aa[0]), "r"(aa[1]), "r"(aa[2]), "r"(aa[3]), \
                   "r"(bb[0]), "r"(bb[1]))

// ================= CSR build =================
__global__ void zero_cnt_kernel() {
    int i = blockIdx.x * blockDim.x + threadIdx.x;
    if (i < NSLOT) g_cnt[i] = 0;
}
__global__ void count_kernel(const int* __restrict__ tgt) {
    int e = blockIdx.x * blockDim.x + threadIdx.x;
    if (e < N_EDGES) atomicAdd(&g_cnt[tgt[e]], 1);
}
__global__ void chunk_sum_kernel() {
    __shared__ int red[256];
    int b = blockIdx.x, t = threadIdx.x;
    int s = 0;
#pragma unroll
    for (int j = 0; j < 4; j++) {
        int i = b * 1024 + j * 256 + t;
        if (i < NSLOT) s += g_cnt[i];
    }
    red[t] = s; __syncthreads();
    for (int o = 128; o > 0; o >>= 1) {
        if (t < o) red[t] += red[t + o];
        __syncthreads();
    }
    if (t == 0) g_csum[b] = red[0];
}
__global__ void scan_chunks_kernel() {
    __shared__ int buf[2][256];
    int t = threadIdx.x;
    int v = (t < NCHUNK) ? g_csum[t] : 0;
    buf[0][t] = v;
    __syncthreads();
    int cur = 0;
#pragma unroll
    for (int off = 1; off < 256; off <<= 1) {
        int nv = buf[cur][t] + ((t >= off) ? buf[cur][t - off] : 0);
        buf[cur ^ 1][t] = nv;
        cur ^= 1;
        __syncthreads();
    }
    if (t < NCHUNK) g_coff[t] = buf[cur][t] - v;
    if (t == NCHUNK - 1) g_rowptr[NSLOT] = buf[cur][t];
}
__global__ void scan_within_kernel() {
    __shared__ int buf[2][1024];
    int b = blockIdx.x, t = threadIdx.x;
    int i = b * 1024 + t;
    int v = (i < NSLOT) ? g_cnt[i] : 0;
    buf[0][t] = v;
    __syncthreads();
    int cur = 0;
#pragma unroll
    for (int off = 1; off < 1024; off <<= 1) {
        int nv = buf[cur][t] + ((t >= off) ? buf[cur][t - off] : 0);
        buf[cur ^ 1][t] = nv;
        cur ^= 1;
        __syncthreads();
    }
    if (i < NSLOT) {
        int excl = buf[cur][t] - v;
        int rp = g_coff[b] + excl;
        g_rowptr[i] = rp;
        g_cursor[i] = rp;
    }
}
__global__ void fill_kernel(const int* __restrict__ tgt, const int* __restrict__ srcv) {
    int e = blockIdx.x * blockDim.x + threadIdx.x;
    if (e >= N_EDGES) return;
    int t = tgt[e];
    int pos = atomicAdd(&g_cursor[t], 1);
    g_esrc[pos] = srcv[e] % N_NODES;
}

// ================= hop gather: fp16 rows, fp32 accum, fp16 out ==============
__global__ __launch_bounds__(256) void gather_hops_kernel() {
    int slot = (blockIdx.x * blockDim.x + threadIdx.x) >> 5;
    int lane = threadIdx.x & 31;
    if (slot >= NSLOT) return;
    int beg = g_rowptr[slot], end = g_rowptr[slot + 1];
    float4 a0 = make_float4(0.f,0.f,0.f,0.f), a1 = a0, a2 = a0, a3 = a0;
    const uint2* xh = (const uint2*)g_xh;   // 32 uint2 per 128-half row
    int e = beg;
    for (; e + 3 < end; e += 4) {
        int s0 = g_esrc[e], s1 = g_esrc[e+1], s2 = g_esrc[e+2], s3 = g_esrc[e+3];
        uint2 u0 = xh[(size_t)s0 * 32 + lane];
        uint2 u1 = xh[(size_t)s1 * 32 + lane];
        uint2 u2 = xh[(size_t)s2 * 32 + lane];
        uint2 u3 = xh[(size_t)s3 * 32 + lane];
        float2 f;
        f = __half22float2(*(__half2*)&u0.x); a0.x += f.x; a0.y += f.y;
        f = __half22float2(*(__half2*)&u0.y); a0.z += f.x; a0.w += f.y;
        f = __half22float2(*(__half2*)&u1.x); a1.x += f.x; a1.y += f.y;
        f = __half22float2(*(__half2*)&u1.y); a1.z += f.x; a1.w += f.y;
        f = __half22float2(*(__half2*)&u2.x); a2.x += f.x; a2.y += f.y;
        f = __half22float2(*(__half2*)&u2.y); a2.z += f.x; a2.w += f.y;
        f = __half22float2(*(__half2*)&u3.x); a3.x += f.x; a3.y += f.y;
        f = __half22float2(*(__half2*)&u3.y); a3.z += f.x; a3.w += f.y;
    }
    for (; e < end; e++) {
        int s0 = g_esrc[e];
        uint2 u0 = xh[(size_t)s0 * 32 + lane];
        float2 f;
        f = __half22float2(*(__half2*)&u0.x); a0.x += f.x; a0.y += f.y;
        f = __half22float2(*(__half2*)&u0.y); a0.z += f.x; a0.w += f.y;
    }
    a0.x += a1.x + a2.x + a3.x;
    a0.y += a1.y + a2.y + a3.y;
    a0.z += a1.z + a2.z + a3.z;
    a0.w += a1.w + a2.w + a3.w;
    int node = slot % N_NODES, hop = slot / N_NODES;
    uint2 o;
    o.x = pack_half2(a0.x, a0.y);
    o.y = pack_half2(a0.z, a0.w);
    ((uint2*)g_hops16)[(size_t)node * 96 + hop * 32 + lane] = o;
}

// ================= fused embed+proj GEMM (single-pass tf32) =================
__global__ __launch_bounds__(256) void proj_kernel(
    const int* __restrict__ atom, const int* __restrict__ hyd,
    const int* __restrict__ deg,  const int* __restrict__ hyb,
    const float* __restrict__ ea, const float* __restrict__ eh,
    const float* __restrict__ ed, const float* __restrict__ ey,
    const float* __restrict__ B, const float* __restrict__ bias) {
    __shared__ unsigned Ah[128 * ASTR];
    __shared__ unsigned Bh[128 * ASTR];
    __shared__ int sidx[128][4];

    const int tid  = threadIdx.x;
    const int lane = tid & 31, wid = tid >> 5;
    const int wm = (wid >> 2) * 64;
    const int wn = (wid & 3) * 32;
    const int grp = lane >> 2, tg = lane & 3;
    const int row0 = blockIdx.x * 128;

    if (tid < 128) {
        int gr = row0 + tid;
        int g2 = (gr < N_NODES) ? gr : 0;
        sidx[tid][0] = atom[g2];
        sidx[tid][1] = hyd[g2];
        sidx[tid][2] = deg[g2];
        sidx[tid][3] = hyb[g2];
    }
    __syncthreads();
    const float* tabs[4] = {ea, eh, ed, ey};

    float c[4][4][4];
#pragma unroll
    for (int i = 0; i < 4; i++)
#pragma unroll
        for (int j = 0; j < 4; j++)
#pragma unroll
            for (int q = 0; q < 4; q++) c[i][j][q] = 0.f;

    const int ar  = tid >> 2;
    const int ac4 = (tid & 3) * 4;
    const int bn  = tid & 127;
    const int bk0 = (tid >> 7) * 8;

    for (int k0 = 0; k0 < 256; k0 += 16) {
        float4 av[2]; float bv[8];
        int kt = (k0 + ac4) >> 6, kw = (k0 + ac4) & 63;
#pragma unroll
        for (int it = 0; it < 2; it++) {
            int r = ar + it * 64;
            av[it] = *(const float4*)(tabs[kt] + (size_t)sidx[r][kt] * 64 + kw);
        }
#pragma unroll
        for (int kk = 0; kk < 8; kk++) bv[kk] = B[(size_t)(k0 + bk0 + kk) * 128 + bn];

        __syncthreads();
#pragma unroll
        for (int it = 0; it < 2; it++) {
            int r = ar + it * 64;
            float vv[4] = {av[it].x, av[it].y, av[it].z, av[it].w};
#pragma unroll
            for (int j = 0; j < 4; j++) Ah[r * ASTR + ac4 + j] = f2tf32(vv[j]);
        }
#pragma unroll
        for (int kk = 0; kk < 8; kk++) Bh[bn * ASTR + bk0 + kk] = f2tf32(bv[kk]);
        __syncthreads();
#pragma unroll
        for (int s = 0; s < 2; s++) {
            const int ks = s * 8;
            unsigned bh[4][2];
#pragma unroll
            for (int nf = 0; nf < 4; nf++) {
                int b0 = (wn + nf * 8 + grp) * ASTR + ks + tg;
                bh[nf][0] = Bh[b0]; bh[nf][1] = Bh[b0 + 4];
            }
#pragma unroll
            for (int mf = 0; mf < 4; mf++) {
                unsigned ah[4];
                int a0 = (wm + mf * 16 + grp) * ASTR + ks + tg;
                int a1 = a0 + 8 * ASTR;
                ah[0] = Ah[a0]; ah[1] = Ah[a1]; ah[2] = Ah[a0 + 4]; ah[3] = Ah[a1 + 4];
#pragma unroll
                for (int nf = 0; nf < 4; nf++) MMA_TF32(c[mf][nf], ah, bh[nf]);
            }
        }
    }

#pragma unroll
    for (int mf = 0; mf < 4; mf++) {
        int r0 = row0 + wm + mf * 16 + grp;
        int r1 = r0 + 8;
#pragma unroll
        for (int nf = 0; nf < 4; nf++) {
            int col = wn + nf * 8 + 2 * tg;
            float bia0 = bias[col], bia1 = bias[col + 1];
            if (r0 < N_NODES) {
                float v0 = silu(c[mf][nf][0] + bia0), v1 = silu(c[mf][nf][1] + bia1);
                g_x[(size_t)r0 * 128 + col]     = v0;
                g_x[(size_t)r0 * 128 + col + 1] = v1;
                *(unsigned*)&g_xh[(size_t)r0 * 128 + col] = pack_half2(v0, v1);
            }
            if (r1 < N_NODES) {
                float v2 = silu(c[mf][nf][2] + bia0), v3 = silu(c[mf][nf][3] + bia1);
                g_x[(size_t)r1 * 128 + col]     = v2;
                g_x[(size_t)r1 * 128 + col + 1] = v3;
                *(unsigned*)&g_xh[(size_t)r1 * 128 + col] = pack_half2(v2, v3);
            }
        }
    }
}

// ================= mega layer kernel (fp16 MMA, fp32 state) ==================
// smem (u32 units): Xf 128*XSTR(fp32) | Xh16 128*HSTR | union{ A16 128*CSTR + B16 256*CSTR , W16 128*HSTR }
__device__ __forceinline__ const __half* feat16_ptr(int gr, int k) {
    return (k < 128) ? (g_xh + (size_t)gr * 128 + k)
                     : (g_hops16 + (size_t)gr * 384 + (k - 128));
}

__global__ __launch_bounds__(512, 1) void layer_kernel(
    const float* __restrict__ in_w,   const float* __restrict__ in_b,
    const float* __restrict__ skip_w, const float* __restrict__ skip_b,
    const float* __restrict__ mlp_w1, const float* __restrict__ mlp_b1,
    const float* __restrict__ mlp_w2, const float* __restrict__ mlp_b2,
    int l) {
    extern __shared__ unsigned sm[];
    float*    Xf   = (float*)sm;                 // fp32 state
    unsigned* Xh16 = sm + 128 * XSTR;            // fp16 state mirror (half2 words)
    unsigned* U    = Xh16 + 128 * HSTR;          // union region
    unsigned* A16  = U;                          // phase A: streamed A (128*CSTR)
    unsigned* B16  = U + 128 * CSTR;             // phase A: streamed B (256*CSTR)
    unsigned* W16  = U;                          // MLP: full weight panel (128*HSTR)

    const int tid  = threadIdx.x;
    const int lane = tid & 31, wid = tid >> 5;
    const int grp  = lane >> 2, tg = lane & 3;
    const int wm   = (wid >> 3) * 64;
    const int wni  = wid & 7;
    const int row0 = blockIdx.x * 128;

    const float* Win = in_w   + (size_t)l * 512 * 128;
    const float* Wsk = skip_w + (size_t)l * 512 * 128;

    float cA[4][4][4];
#pragma unroll
    for (int i = 0; i < 4; i++)
#pragma unroll
        for (int j = 0; j < 4; j++)
#pragma unroll
            for (int q = 0; q < 4; q++) cA[i][j][q] = 0.f;

    // ---- phase A: feats[128,512] @ [in_w | skip_w] -> N=256, fp16 MMA ----
    const int ar = tid >> 2;            // A row 0..127
    const int aq = tid & 3;             // uint4 (8 halves) within 32-half chunk
    const int bn = tid & 255;           // B col 0..255
    const int ko = (tid >> 8) * 16;     // B k-half offset (0 or 16)
    const float* Wmy = (bn < 128) ? Win : Wsk;
    const int    bcol = bn & 127;

    uint4 av; float bv[16];
    {
        int gr = row0 + ar;
        av = (gr < N_NODES) ? *(const uint4*)feat16_ptr(gr, aq * 8)
                            : make_uint4(0,0,0,0);
#pragma unroll
        for (int j = 0; j < 16; j++) bv[j] = Wmy[(size_t)(ko + j) * 128 + bcol];
    }

    const int wnA = wni * 32;
    for (int k0 = 0; k0 < 512; k0 += 32) {
        __syncthreads();
        *(uint4*)&A16[ar * CSTR + aq * 4] = av;
#pragma unroll
        for (int j = 0; j < 16; j += 2)
            B16[bn * CSTR + (ko >> 1) + (j >> 1)] = pack_half2(bv[j], bv[j + 1]);
        __syncthreads();
        if (k0 + 32 < 512) {
            int kn = k0 + 32;
            int gr = row0 + ar;
            av = (gr < N_NODES) ? *(const uint4*)feat16_ptr(gr, kn + aq * 8)
                                : make_uint4(0,0,0,0);
#pragma unroll
            for (int j = 0; j < 16; j++) bv[j] = Wmy[(size_t)(kn + ko + j) * 128 + bcol];
        }
#pragma unroll
        for (int s = 0; s < 2; s++) {
            const int sb = s * 8;
            unsigned bh[4][2];
#pragma unroll
            for (int nf = 0; nf < 4; nf++) {
                int b0 = (wnA + nf * 8 + grp) * CSTR + sb + tg;
                bh[nf][0] = B16[b0]; bh[nf][1] = B16[b0 + 4];
            }
#pragma unroll
            for (int mf = 0; mf < 4; mf++) {
                unsigned ah[4];
                int a0 = (wm + mf * 16 + grp) * CSTR + sb + tg;
                int a1 = a0 + 8 * CSTR;
                ah[0] = A16[a0]; ah[1] = A16[a1]; ah[2] = A16[a0 + 4]; ah[3] = A16[a1 + 4];
#pragma unroll
                for (int nf = 0; nf < 4; nf++) MMA_F16(cA[mf][nf], ah, bh[nf]);
            }
        }
    }
    __syncthreads();

    // phase A epilogue: wni<4 -> h (silu) into Xf/Xh16; wni>=4 -> gskip
    {
        const float* bias = (wni < 4) ? (in_b + l * 128) : (skip_b + l * 128);
#pragma unroll
        for (int mf = 0; mf < 4; mf++) {
            int r0 = wm + mf * 16 + grp;
#pragma unroll
            for (int nf = 0; nf < 4; nf++) {
                int col = (wni & 3) * 32 + nf * 8 + 2 * tg;
                float b0 = bias[col], b1 = bias[col + 1];
                float v0 = cA[mf][nf][0] + b0, v1 = cA[mf][nf][1] + b1;
                float v2 = cA[mf][nf][2] + b0, v3 = cA[mf][nf][3] + b1;
                if (wni < 4) {
                    v0 = silu(v0); v1 = silu(v1); v2 = silu(v2); v3 = silu(v3);
                    int h2 = (col >> 1);
                    Xf[r0*XSTR + col]       = v0; Xf[r0*XSTR + col + 1]   = v1;
                    Xf[(r0+8)*XSTR + col]   = v2; Xf[(r0+8)*XSTR + col+1] = v3;
                    Xh16[r0*HSTR + h2]      = pack_half2(v0, v1);
                    Xh16[(r0+8)*HSTR + h2]  = pack_half2(v2, v3);
                } else {
                    int gr0 = row0 + r0, gr1 = gr0 + 8;
                    if (gr0 < N_NODES) { g_gskip[(size_t)gr0*128 + col] = v0; g_gskip[(size_t)gr0*128 + col+1] = v1; }
                    if (gr1 < N_NODES) { g_gskip[(size_t)gr1*128 + col] = v2; g_gskip[(size_t)gr1*128 + col+1] = v3; }
                }
            }
        }
    }
    __syncthreads();

    // ---- MLP chain: 2 blocks x 2 phases, K=128, full W panel in smem ----
    const int wnM  = wni * 16;
    const int colW = tid & 127;          // weight panel load: column
    const int kseg = (tid >> 7) * 32;    // weight panel load: k range (4 segs)

    for (int m = 0; m < 2; m++) {
        const float* B1 = mlp_b1 + (l * 2 + m) * 128;
        const float* B2 = mlp_b2 + (l * 2 + m) * 128;

        for (int phase = 0; phase < 2; phase++) {
            const float* W = (phase ? mlp_w2 : mlp_w1) + (size_t)(l * 2 + m) * 16384;

            // load full W panel as fp16 [n][k/2], stride HSTR
#pragma unroll
            for (int j = 0; j < 32; j += 2) {
                float w0 = W[(size_t)(kseg + j) * 128 + colW];
                float w1 = W[(size_t)(kseg + j + 1) * 128 + colW];
                W16[colW * HSTR + ((kseg + j) >> 1)] = pack_half2(w0, w1);
            }
            __syncthreads();

            float cT[4][2][4];
#pragma unroll
            for (int i = 0; i < 4; i++)
#pragma unroll
                for (int j = 0; j < 2; j++)
#pragma unroll
                    for (int q = 0; q < 4; q++) cT[i][j][q] = 0.f;

#pragma unroll
            for (int c = 0; c < 8; c++) {       // 8 x k16 steps, no barriers
                const int cb = c * 8;
                unsigned bh[2][2];
#pragma unroll
                for (int nf = 0; nf < 2; nf++) {
                    int b0 = (wnM + nf * 8 + grp) * HSTR + cb + tg;
                    bh[nf][0] = W16[b0]; bh[nf][1] = W16[b0 + 4];
                }
#pragma unroll
                for (int mf = 0; mf < 4; mf++) {
                    unsigned ah[4];
                    int a0 = (wm + mf * 16 + grp) * HSTR + cb + tg;
                    int a1 = a0 + 8 * HSTR;
                    ah[0] = Xh16[a0]; ah[1] = Xh16[a1]; ah[2] = Xh16[a0 + 4]; ah[3] = Xh16[a1 + 4];
#pragma unroll
                    for (int nf = 0; nf < 2; nf++) MMA_F16(cT[mf][nf], ah, bh[nf]);
                }
            }

            if (phase == 0) {
                // t = silu(cT + b1); stash residual (fp32 state), overwrite X with t
                float res[4][2][4];
#pragma unroll
                for (int mf = 0; mf < 4; mf++) {
                    int r0 = wm + mf * 16 + grp;
#pragma unroll
                    for (int nf = 0; nf < 2; nf++) {
                        int col = wnM + nf * 8 + 2 * tg;
                        res[mf][nf][0] = Xf[r0*XSTR + col];
                        res[mf][nf][1] = Xf[r0*XSTR + col + 1];
                        res[mf][nf][2] = Xf[(r0+8)*XSTR + col];
                        res[mf][nf][3] = Xf[(r0+8)*XSTR + col + 1];
                        cT[mf][nf][0] = silu(cT[mf][nf][0] + B1[col]);
                        cT[mf][nf][1] = silu(cT[mf][nf][1] + B1[col + 1]);
                        cT[mf][nf][2] = silu(cT[mf][nf][2] + B1[col]);
                        cT[mf][nf][3] = silu(cT[mf][nf][3] + B1[col + 1]);
                    }
                }
                __syncthreads();   // MMA reads of Xh16 done before overwrite
#pragma unroll
                for (int mf = 0; mf < 4; mf++) {
                    int r0 = wm + mf * 16 + grp;
#pragma unroll
                    for (int nf = 0; nf < 2; nf++) {
                        int col = wnM + nf * 8 + 2 * tg;
                        int h2 = col >> 1;
                        Xf[r0*XSTR+col]       = cT[mf][nf][0]; Xf[r0*XSTR+col+1]     = cT[mf][nf][1];
                        Xf[(r0+8)*XSTR+col]   = cT[mf][nf][2]; Xf[(r0+8)*XSTR+col+1] = cT[mf][nf][3];
                        Xh16[r0*HSTR + h2]     = pack_half2(cT[mf][nf][0], cT[mf][nf][1]);
                        Xh16[(r0+8)*HSTR + h2] = pack_half2(cT[mf][nf][2], cT[mf][nf][3]);
                        cA[mf][nf][0] = res[mf][nf][0]; cA[mf][nf][1] = res[mf][nf][1];
                        cA[mf][nf][2] = res[mf][nf][2]; cA[mf][nf][3] = res[mf][nf][3];
                    }
                }
                __syncthreads();
            } else {
                if (m == 0) __syncthreads();   // MMA reads done before state overwrite
#pragma unroll
                for (int mf = 0; mf < 4; mf++) {
                    int r0 = wm + mf * 16 + grp;
#pragma unroll
                    for (int nf = 0; nf < 2; nf++) {
                        int col = wnM + nf * 8 + 2 * tg;
                        float o0 = cT[mf][nf][0] + B2[col]     + cA[mf][nf][0];
                        float o1 = cT[mf][nf][1] + B2[col + 1] + cA[mf][nf][1];
                        float o2 = cT[mf][nf][2] + B2[col]     + cA[mf][nf][2];
                        float o3 = cT[mf][nf][3] + B2[col + 1] + cA[mf][nf][3];
                        if (m == 1) {
                            int gr0 = row0 + r0, gr1 = gr0 + 8;
                            if (gr0 < N_NODES) {
                                float f0 = o0 + g_gskip[(size_t)gr0*128 + col];
                                float f1 = o1 + g_gskip[(size_t)gr0*128 + col+1];
                                g_x[(size_t)gr0*128 + col]   = f0;
                                g_x[(size_t)gr0*128 + col+1] = f1;
                                *(unsigned*)&g_xh[(size_t)gr0*128 + col] = pack_half2(f0, f1);
                            }
                            if (gr1 < N_NODES) {
                                float f2 = o2 + g_gskip[(size_t)gr1*128 + col];
                                float f3 = o3 + g_gskip[(size_t)gr1*128 + col+1];
                                g_x[(size_t)gr1*128 + col]   = f2;
                                g_x[(size_t)gr1*128 + col+1] = f3;
                                *(unsigned*)&g_xh[(size_t)gr1*128 + col] = pack_half2(f2, f3);
                            }
                        } else {
                            int h2 = col >> 1;
                            Xf[r0*XSTR+col]       = o0; Xf[r0*XSTR+col+1]     = o1;
                            Xf[(r0+8)*XSTR+col]   = o2; Xf[(r0+8)*XSTR+col+1] = o3;
                            Xh16[r0*HSTR + h2]     = pack_half2(o0, o1);
                            Xh16[(r0+8)*HSTR + h2] = pack_half2(o2, o3);
                        }
                    }
                }
                if (m == 0) __syncthreads();
            }
        }
    }
}

// ================= fused pooling + FFN: one block per graph =================
__global__ __launch_bounds__(128) void pool_ffn_kernel(
    const int* __restrict__ batch,
    const float* __restrict__ attn_w, const float* __restrict__ attn_b,
    const float* __restrict__ temp,
    const float* __restrict__ w1, const float* __restrict__ b1,
    const float* __restrict__ w2, const float* __restrict__ b2,
    const float* __restrict__ w3, const float* __restrict__ b3,
    float* __restrict__ out) {
    const int g = blockIdx.x, t = threadIdx.x;
    const int lane = t & 31, wrp = t >> 5;
    __shared__ int sbeg, send;
    __shared__ float aw[512];
    __shared__ float P[4][128];
    __shared__ float ex[128][4];
    __shared__ float m[4], s[4], rs[4];
    __shared__ float wred[4][4];
    __shared__ float p[128], h1[128], red[128];

    if (t == 0) {
        int lo = 0, hi = N_NODES;
        while (lo < hi) { int mid = (lo + hi) >> 1; if (batch[mid] < g) lo = mid + 1; else hi = mid; }
        sbeg = lo;
        hi = N_NODES;
        while (lo < hi) { int mid = (lo + hi) >> 1; if (batch[mid] < g + 1) lo = mid + 1; else hi = mid; }
        send = lo;
    }
    aw[t] = attn_w[t]; aw[128 + t] = attn_w[128 + t];
    aw[256 + t] = attn_w[256 + t]; aw[384 + t] = attn_w[384 + t];
    if (t < 4) { m[t] = -1e30f; s[t] = 0.f; }
    P[0][t] = 0.f; P[1][t] = 0.f; P[2][t] = 0.f; P[3][t] = 0.f;
    __syncthreads();
    const int beg = sbeg, end = send;
    const float invT = 1.f / temp[0];

    for (int c0 = beg; c0 < end; c0 += 128) {
        int idx = c0 + t;
        bool active = idx < end;
        float sc[4] = {-1e30f, -1e30f, -1e30f, -1e30f};
        if (active) {
            const float* xr = g_x + (size_t)idx * HID;
            float a0 = 0.f, a1 = 0.f, a2 = 0.f, a3 = 0.f;
#pragma unroll 8
            for (int k = 0; k < 128; k += 4) {
                float4 xv = *(const float4*)(xr + k);
                a0 += xv.x*aw[k]     + xv.y*aw[k+1]     + xv.z*aw[k+2]     + xv.w*aw[k+3];
                a1 += xv.x*aw[128+k] + xv.y*aw[128+k+1] + xv.z*aw[128+k+2] + xv.w*aw[128+k+3];
                a2 += xv.x*aw[256+k] + xv.y*aw[256+k+1] + xv.z*aw[256+k+2] + xv.w*aw[256+k+3];
                a3 += xv.x*aw[384+k] + xv.y*aw[384+k+1] + xv.z*aw[384+k+2] + xv.w*aw[384+k+3];
            }
            sc[0] = (a0 + attn_b[0]) * invT;
            sc[1] = (a1 + attn_b[1]) * invT;
            sc[2] = (a2 + attn_b[2]) * invT;
            sc[3] = (a3 + attn_b[3]) * invT;
        }
        float mx[4] = {sc[0], sc[1], sc[2], sc[3]};
#pragma unroll
        for (int o = 16; o; o >>= 1)
#pragma unroll
            for (int h = 0; h < 4; h++) mx[h] = fmaxf(mx[h], __shfl_xor_sync(0xffffffffu, mx[h], o));
        if (lane == 0)
#pragma unroll
            for (int h = 0; h < 4; h++) wred[wrp][h] = mx[h];
        __syncthreads();
        if (t < 4) {
            float cm = fmaxf(fmaxf(wred[0][t], wred[1][t]), fmaxf(wred[2][t], wred[3][t]));
            float nm = fmaxf(m[t], cm);
            rs[t] = __expf(m[t] - nm);
            m[t] = nm;
            s[t] *= rs[t];
        }
        __syncthreads();
        float e[4];
#pragma unroll
        for (int h = 0; h < 4; h++) {
            e[h] = active ? __expf(sc[h] - m[h]) : 0.f;
            ex[t][h] = e[h];
        }
        float sm2[4] = {e[0], e[1], e[2], e[3]};
#pragma unroll
        for (int o = 16; o; o >>= 1)
#pragma unroll
            for (int h = 0; h < 4; h++) sm2[h] += __shfl_xor_sync(0xffffffffu, sm2[h], o);
        if (lane == 0)
#pragma unroll
            for (int h = 0; h < 4; h++) wred[wrp][h] = sm2[h];
        __syncthreads();
        if (t < 4) s[t] += wred[0][t] + wred[1][t] + wred[2][t] + wred[3][t];

        int cnt = min(128, end - c0);
        float p0 = P[0][t] * rs[0], p1 = P[1][t] * rs[1];
        float p2 = P[2][t] * rs[2], p3 = P[3][t] * rs[3];
        for (int n = 0; n < cnt; n++) {
            float xv = g_x[(size_t)(c0 + n) * HID + t];
            p0 += ex[n][0] * xv;
            p1 += ex[n][1] * xv;
            p2 += ex[n][2] * xv;
            p3 += ex[n][3] * xv;
        }
        P[0][t] = p0; P[1][t] = p1; P[2][t] = p2; P[3][t] = p3;
        __syncthreads();
    }

    float pooled = 0.f;
#pragma unroll
    for (int h = 0; h < 4; h++) if (s[h] > 0.f) pooled += P[h][t] / s[h];
    p[t] = pooled * 0.25f;
    __syncthreads();

    float acc = b1[t];
#pragma unroll 8
    for (int k = 0; k < 128; k++) acc += p[k] * w1[k * 128 + t];
    h1[t] = silu(acc);
    __syncthreads();
    float acc2 = b2[t];
#pragma unroll 8
    for (int k = 0; k < 128; k++) acc2 += h1[k] * w2[k * 128 + t];
    acc2 = silu(acc2);
    red[t] = acc2 * w3[t];
    __syncthreads();
    for (int o = 64; o > 0; o >>= 1) {
        if (t < o) red[t] += red[t + o];
        __syncthreads();
    }
    if (t == 0) out[g] = red[0] + b3[0];
}

// ---------------- host launcher ---------------------------------------------
extern "C" void kernel_launch(void* const* d_in, const int* in_sizes, int n_in,
                              void* d_out, int out_size) {
    const int* atom  = (const int*)d_in[0];
    const int* hyd   = (const int*)d_in[1];
    const int* deg   = (const int*)d_in[2];
    const int* hyb   = (const int*)d_in[3];
    const int* tgt   = (const int*)d_in[4];
    const int* srcv  = (const int*)d_in[5];
    const int* batch = (const int*)d_in[6];
    const float* emb_atom = (const float*)d_in[7];
    const float* emb_h    = (const float*)d_in[8];
    const float* emb_deg  = (const float*)d_in[9];
    const float* emb_hyb  = (const float*)d_in[10];
    const float* proj_w   = (const float*)d_in[11];
    const float* proj_b   = (const float*)d_in[12];
    const float* in_w     = (const float*)d_in[13];
    const float* in_b     = (const float*)d_in[14];
    const float* mlp_w1   = (const float*)d_in[15];
    const float* mlp_b1   = (const float*)d_in[16];
    const float* mlp_w2   = (const float*)d_in[17];
    const float* mlp_b2   = (const float*)d_in[18];
    const float* skip_w   = (const float*)d_in[19];
    const float* skip_b   = (const float*)d_in[20];
    const float* attn_w   = (const float*)d_in[21];
    const float* attn_b   = (const float*)d_in[22];
    const float* temp     = (const float*)d_in[23];
    const float* ffn_w1   = (const float*)d_in[24];
    const float* ffn_b1   = (const float*)d_in[25];
    const float* ffn_w2   = (const float*)d_in[26];
    const float* ffn_b2   = (const float*)d_in[27];
    const float* ffn_w3   = (const float*)d_in[28];
    const float* ffn_b3   = (const float*)d_in[29];
    float* out = (float*)d_out;

    // Xf + Xh16 + max(A16+B16, W16)
    const int UNION_U32 = (128 * CSTR + 256 * CSTR) > (128 * HSTR)
                        ? (128 * CSTR + 256 * CSTR) : (128 * HSTR);
    const int LAYER_SMEM = (128 * XSTR + 128 * HSTR + UNION_U32) * 4;
    cudaFuncSetAttribute(layer_kernel, cudaFuncAttributeMaxDynamicSharedMemorySize, LAYER_SMEM);

    // 0. CSR build (once; reused by all 3 layers)
    zero_cnt_kernel<<<(NSLOT + 255) / 256, 256>>>();
    count_kernel<<<(N_EDGES + 255) / 256, 256>>>(tgt);
    chunk_sum_kernel<<<NCHUNK, 256>>>();
    scan_chunks_kernel<<<1, 256>>>();
    scan_within_kernel<<<NCHUNK, 1024>>>();
    fill_kernel<<<(N_EDGES + 255) / 256, 256>>>(tgt, srcv);

    // 1. fused embedding + projection (writes fp32 x + fp16 mirror)
    proj_kernel<<<GEMM_BLKS, 256>>>(atom, hyd, deg, hyb, emb_atom, emb_h, emb_deg, emb_hyb,
                                    proj_w, proj_b);

    // 2. shell conv layers
    for (int l = 0; l < 3; l++) {
        gather_hops_kernel<<<(NSLOT * 32 + 255) / 256, 256>>>();
        layer_kernel<<<GEMM_BLKS, 512, LAYER_SMEM>>>(in_w, in_b, skip_w, skip_b,
                                                     mlp_w1, mlp_b1, mlp_w2, mlp_b2, l);
    }

    // 3. fused attention pooling + FFN readout
    pool_ffn_kernel<<<NUM_GRAPHS, 128>>>(batch, attn_w, attn_b, temp,
                                         ffn_w1, ffn_b1, ffn_w2, ffn_b2, ffn_w3, ffn_b3, out);
}